// round 11
// baseline (speedup 1.0000x reference)
#include <cuda_runtime.h>
#include <cuda_fp16.h>
#include <math.h>

#define BB 4
#define CC 192
#define C2 384
#define HWN 16384
#define HIMG 128
#define CHD 48
#define HIDC 510
#define HID2 1020
#define GGPAD 512
#define EPSLN 1e-5f

__device__ __forceinline__ unsigned smem_u32(const void* p) {
    unsigned a;
    asm("{ .reg .u64 t; cvta.to.shared.u64 t, %1; cvt.u32.u64 %0, t; }"
        : "=r"(a) : "l"(p));
    return a;
}
#define CP_ASYNC16(dst, src) \
    asm volatile("cp.async.cg.shared.global [%0], [%1], 16;" :: "r"(dst), "l"(src))
#define CP_COMMIT() asm volatile("cp.async.commit_group;" ::: "memory")
#define CP_WAIT(n)  asm volatile("cp.async.wait_group %0;" :: "n"(n) : "memory")

__device__ __forceinline__ void ldm_x4(unsigned& r0, unsigned& r1, unsigned& r2, unsigned& r3,
                                       unsigned addr) {
    asm volatile("ldmatrix.sync.aligned.m8n8.x4.shared.b16 {%0,%1,%2,%3}, [%4];"
        : "=r"(r0), "=r"(r1), "=r"(r2), "=r"(r3) : "r"(addr));
}
__device__ __forceinline__ void ldm_x4_t(unsigned& r0, unsigned& r1, unsigned& r2, unsigned& r3,
                                         unsigned addr) {
    asm volatile("ldmatrix.sync.aligned.m8n8.x4.trans.shared.b16 {%0,%1,%2,%3}, [%4];"
        : "=r"(r0), "=r"(r1), "=r"(r2), "=r"(r3) : "r"(addr));
}
__device__ __forceinline__ void mma_f16(float* d, const unsigned* a, unsigned b0, unsigned b1) {
    asm volatile("mma.sync.aligned.m16n8k16.row.col.f32.f16.f16.f32 "
        "{%0,%1,%2,%3}, {%4,%5,%6,%7}, {%8,%9}, {%0,%1,%2,%3};"
        : "+f"(d[0]), "+f"(d[1]), "+f"(d[2]), "+f"(d[3])
        : "r"(a[0]), "r"(a[1]), "r"(a[2]), "r"(a[3]), "r"(b0), "r"(b1));
}

// ---------------- scratch ----------------
__device__ __align__(16) __half g_qpre [BB*C2*HWN];
__device__ __align__(16) __half g_kv1pre[BB*C2*HWN];
__device__ __align__(16) __half g_kv2pre[BB*C2*HWN];
__device__ __align__(16) __half g_q   [BB*C2*HWN];
__device__ __align__(16) __half g_kv1 [BB*C2*HWN];
__device__ __align__(16) __half g_kv2 [BB*C2*HWN];
__device__ __align__(16) __half g_h   [BB*HID2*HWN];
__device__ float g_x2  [BB*CC*HWN];
__device__ float g_S   [32*CHD*CHD];
__device__ float g_nrm [32*2*CHD];

// fp16 activations, natural layout: [b][channel][pixel]
__device__ __align__(16) __half xt_a [BB*CC*HWN];
__device__ __align__(16) __half xt_k1[BB*CC*HWN];
__device__ __align__(16) __half xt_k2[BB*CC*HWN];
__device__ __align__(16) __half xt_ao[BB*C2*HWN];
__device__ __align__(16) __half xt_gg[BB*GGPAD*HWN];
// converted weights (row-major [O][Cpad]), fp16
#define OFF_Q   0
#define OFF_K1  (384*192)
#define OFF_K2  (2*384*192)
#define OFF_P   (3*384*192)
#define OFF_PIN (3*384*192 + 192*384)
#define OFF_PO  (3*384*192 + 192*384 + 1020*192)
#define WTOT    (3*384*192 + 192*384 + 1020*192 + 192*512)
#define WPAD    (64*512)
__device__ __align__(16) __half g_wh[WTOT + WPAD];

// ---------------- fp32 -> fp16 helpers ----------------
__device__ __forceinline__ void st_half4(__half* dst, float a0, float a1, float a2, float a3) {
    __half2 h01 = __floats2half2_rn(a0, a1);
    __half2 h23 = __floats2half2_rn(a2, a3);
    uint2 u; u.x = *(unsigned*)&h01; u.y = *(unsigned*)&h23;
    *(uint2*)dst = u;
}

// ---------------- merged weight conversion (1 launch) ----------------
__global__ void wconv_all(const float* __restrict__ q_w, const float* __restrict__ kv1_w,
                          const float* __restrict__ kv2_w, const float* __restrict__ proj_w,
                          const float* __restrict__ pin_w, const float* __restrict__ pout_w) {
    int r = blockIdx.x;
    const float* W; int o, Cin, Cpad, off;
    if (r < 384)        { W = q_w;    o = r;        Cin = 192; Cpad = 192; off = OFF_Q; }
    else if (r < 768)   { W = kv1_w;  o = r - 384;  Cin = 192; Cpad = 192; off = OFF_K1; }
    else if (r < 1152)  { W = kv2_w;  o = r - 768;  Cin = 192; Cpad = 192; off = OFF_K2; }
    else if (r < 1344)  { W = proj_w; o = r - 1152; Cin = 384; Cpad = 384; off = OFF_P; }
    else if (r < 2364)  { W = pin_w;  o = r - 1344; Cin = 192; Cpad = 192; off = OFF_PIN; }
    else                { W = pout_w; o = r - 2364; Cin = 510; Cpad = 512; off = OFF_PO; }
    int c0 = threadIdx.x * 8;
    if (c0 >= Cpad) return;
    float v[8];
    #pragma unroll
    for (int j = 0; j < 8; j++) {
        int c = c0 + j;
        v[j] = (c < Cin) ? W[(size_t)o * Cin + c] : 0.f;
    }
    __half* dst = g_wh + (size_t)off + (size_t)o * Cpad + c0;
    st_half4(dst,     v[0], v[1], v[2], v[3]);
    st_half4(dst + 4, v[4], v[5], v[6], v[7]);
}

// ======================= HMMA GEMM body =====================================
// Y[b][o][p] = sum_c W[o][c] * X[b][c][p] (+ residual). Single fp16 HMMA.
// BM=128 (o), BN=128 (p), BK=32. 8 warps 4m x 2n, warp tile 32x64.
#define BK 32
#define ASTRIDE 40
#define PSTR 136
#define A_BYTES (128 * ASTRIDE * 2)          // 10240
#define B_BYTES (BK * PSTR * 2)              // 8704
#define BUF_BYTES (A_BYTES + B_BYTES)        // 18944
#define YSTRIDE 132
#define GEMM_SMEM (128 * YSTRIDE * 4)        // 67584 > 2*BUF_BYTES

template<bool RESID, bool HALF_OUT>
__device__ __forceinline__
void gemm_body(const __half* __restrict__ W, const __half* __restrict__ XB,
               const float* __restrict__ R, void* __restrict__ Yv, int O, int Cpad,
               int b, int p0, int o0, char* dsm) {
    unsigned sbase = smem_u32(dsm);
    int t = threadIdx.x, lane = t & 31, wid = t >> 5;
    int warpM = (wid >> 1) * 32;
    int warpN = (wid & 1) * 64;

    const __half* WB = W + (size_t)o0 * Cpad;

    int nk = Cpad / BK;

    auto fill = [&](int kt) {
        int buf = kt & 1;
        unsigned bb = sbase + buf * BUF_BYTES;
        int k0 = kt * BK;
        #pragma unroll
        for (int j = 0; j < 4; j++) {
            int ci = j * 256 + t;
            if (ci < 512) {
                int row = ci >> 2, g = ci & 3;
                const __half* src = WB + (size_t)row * Cpad + k0 + g * 8;
                unsigned dst = bb + (unsigned)(row * ASTRIDE + g * 8) * 2;
                CP_ASYNC16(dst, src);
            } else {
                int m = ci - 512;
                int row = m >> 4, g = m & 15;
                const __half* src = XB + (size_t)(k0 + row) * HWN + g * 8;
                unsigned dst = bb + A_BYTES + (unsigned)(row * PSTR + g * 8) * 2;
                CP_ASYNC16(dst, src);
            }
        }
        CP_COMMIT();
    };

    float acc[2][8][4];
    #pragma unroll
    for (int i = 0; i < 2; i++)
        #pragma unroll
        for (int j = 0; j < 8; j++)
            #pragma unroll
            for (int k = 0; k < 4; k++) acc[i][j][k] = 0.f;

    fill(0);

    int rsel = lane & 15, csel = (lane >> 4) * 8;
    int bkr = (lane & 7) + ((lane >> 4) & 1) * 8;
    int bpc = ((lane >> 3) & 1) * 8;

    for (int kt = 0; kt < nk; kt++) {
        if (kt + 1 < nk) { fill(kt + 1); CP_WAIT(1); }
        else             { CP_WAIT(0); }
        __syncthreads();

        unsigned bb = sbase + (kt & 1) * BUF_BYTES;
        unsigned Aa = bb, Ba = bb + A_BYTES;

        #pragma unroll
        for (int kk = 0; kk < 2; kk++) {
            int kc = csel + kk * 16;
            unsigned af[2][4], bf[4][4];
            #pragma unroll
            for (int mt = 0; mt < 2; mt++) {
                unsigned off = (unsigned)((warpM + mt * 16 + rsel) * ASTRIDE + kc) * 2;
                ldm_x4(af[mt][0], af[mt][1], af[mt][2], af[mt][3], Aa + off);
            }
            #pragma unroll
            for (int np = 0; np < 4; np++) {
                unsigned off = (unsigned)((kk * 16 + bkr) * PSTR + warpN + np * 16 + bpc) * 2;
                ldm_x4_t(bf[np][0], bf[np][1], bf[np][2], bf[np][3], Ba + off);
            }
            #pragma unroll
            for (int mt = 0; mt < 2; mt++)
                #pragma unroll
                for (int nt = 0; nt < 8; nt++) {
                    int np = nt >> 1, hf = nt & 1;
                    mma_f16(acc[mt][nt], af[mt], bf[np][hf], bf[np][hf + 2]);
                }
        }
        __syncthreads();
    }

    float* Ysm = (float*)dsm;
    #pragma unroll
    for (int mt = 0; mt < 2; mt++)
        #pragma unroll
        for (int nt = 0; nt < 8; nt++) {
            int r0 = warpM + mt * 16 + (lane >> 2);
            int cc = warpN + nt * 8 + (lane & 3) * 2;
            Ysm[r0 * YSTRIDE + cc]           = acc[mt][nt][0];
            Ysm[r0 * YSTRIDE + cc + 1]       = acc[mt][nt][1];
            Ysm[(r0 + 8) * YSTRIDE + cc]     = acc[mt][nt][2];
            Ysm[(r0 + 8) * YSTRIDE + cc + 1] = acc[mt][nt][3];
        }
    __syncthreads();
    #pragma unroll
    for (int i = 0; i < 16; i++) {
        int idx = i * 256 + t;
        int row = idx >> 5, c4 = (idx & 31) * 4;
        int o = o0 + row;
        if (o < O) {
            float4 v = *(float4*)(Ysm + row * YSTRIDE + c4);
            size_t goff = ((size_t)b * O + o) * HWN + p0 + c4;
            if (HALF_OUT) {
                st_half4((__half*)Yv + goff, v.x, v.y, v.z, v.w);
            } else {
                if (RESID) {
                    float4 q = *(const float4*)(R + goff);
                    v.x += q.x; v.y += q.y; v.z += q.z; v.w += q.w;
                }
                *(float4*)((float*)Yv + goff) = v;
            }
        }
    }
}

template<bool RESID, bool HALF_OUT>
__global__ __launch_bounds__(256)
void gemm_mma(const __half* __restrict__ W, const __half* __restrict__ X,
              const float* __restrict__ R, void* __restrict__ Y, int O, int Cpad) {
    extern __shared__ char dsm[];
    int b = blockIdx.z;
    gemm_body<RESID, HALF_OUT>(W,
                     X + (size_t)b * Cpad * HWN + blockIdx.x * 128,
                     R, Y, O, Cpad, b, blockIdx.x * 128, blockIdx.y * 128, dsm);
}

// merged q/kv1/kv2 GEMM: grid (128, 3, 12); z: which = z>>2, b = z&3
__global__ __launch_bounds__(256)
void gemm3(void) {
    extern __shared__ char dsm[];
    int z = blockIdx.z, which = z >> 2, b = z & 3;
    const __half *W, *X;
    __half* Y;
    if (which == 0)      { W = g_wh + OFF_Q;  X = xt_a;  Y = g_qpre; }
    else if (which == 1) { W = g_wh + OFF_K1; X = xt_k1; Y = g_kv1pre; }
    else                 { W = g_wh + OFF_K2; X = xt_k2; Y = g_kv2pre; }
    gemm_body<false, true>(W,
                     X + (size_t)b * CC * HWN + blockIdx.x * 128,
                     nullptr, Y, C2, CC, b, blockIdx.x * 128, blockIdx.y * 128, dsm);
}

// ---------------- LayerNorm -> fp16 [c][p] ----------------------------------
__device__ __forceinline__
void ln_body(const float* __restrict__ X, const float* __restrict__ w,
             const float* __restrict__ bia, __half* __restrict__ Hx,
             int b, int pblk) {
    __shared__ float2 red[256];
    int px = threadIdx.x & 63, cg = threadIdx.x >> 6;
    int p = pblk * 64 + px;
    const float* xp = X + ((size_t)b * CC + (size_t)cg * 48) * HWN + p;
    float v[48];
    float s = 0.f, q = 0.f;
    #pragma unroll
    for (int i = 0; i < 48; i++) {
        float t = xp[(size_t)i * HWN];
        v[i] = t; s += t; q += t * t;
    }
    red[threadIdx.x] = make_float2(s, q);
    __syncthreads();
    float2 r0 = red[px], r1 = red[64 + px], r2 = red[128 + px], r3 = red[192 + px];
    float st = r0.x + r1.x + r2.x + r3.x;
    float qt = r0.y + r1.y + r2.y + r3.y;
    const float invc = 1.f / CC;
    float mu = st * invc;
    float iv = rsqrtf(fmaxf(qt * invc - mu * mu, 0.f) + EPSLN);
    size_t base = ((size_t)b * CC + (size_t)cg * 48) * HWN + p;
    #pragma unroll
    for (int i = 0; i < 48; i++) {
        int c = cg * 48 + i;
        float o = (v[i] - mu) * iv * w[c] + bia[c];
        Hx[base + (size_t)i * HWN] = __float2half_rn(o);
    }
}

__global__ __launch_bounds__(256)
void ln3(const float* __restrict__ X0, const float* __restrict__ X1, const float* __restrict__ X2,
         const float* __restrict__ w0, const float* __restrict__ b0,
         const float* __restrict__ w1, const float* __restrict__ b1,
         const float* __restrict__ w2, const float* __restrict__ b2) {
    int which = blockIdx.z;
    const float *X, *w, *bia;
    __half* Hx;
    if (which == 0)      { X = X0; w = w0; bia = b0; Hx = xt_a; }
    else if (which == 1) { X = X1; w = w1; bia = b1; Hx = xt_k1; }
    else                 { X = X2; w = w2; bia = b2; Hx = xt_k2; }
    ln_body(X, w, bia, Hx, blockIdx.y, blockIdx.x);
}

__global__ __launch_bounds__(256)
void ln_cp(const float* __restrict__ X, const float* __restrict__ w,
           const float* __restrict__ bia, __half* __restrict__ Hx) {
    ln_body(X, w, bia, Hx, blockIdx.y, blockIdx.x);
}

// ---------------- depthwise 3x3 core over fp16 input ----------------
__device__ __forceinline__ void dw_core_h(const __half* __restrict__ xp, const float* kv,
                                          int h, int wcol, float& a0, float& a1,
                                          float& a2, float& a3) {
    #pragma unroll
    for (int dy = -1; dy <= 1; dy++) {
        int hh = h + dy;
        if (hh < 0 || hh >= HIMG) continue;
        const __half* r = xp + hh * HIMG + wcol;
        __half2 p01 = *(const __half2*)r;
        __half2 p23 = *(const __half2*)(r + 2);
        float m0 = __low2float(p01), m1 = __high2float(p01);
        float m2 = __low2float(p23), m3 = __high2float(p23);
        float lf = (wcol > 0) ? __half2float(r[-1]) : 0.f;
        float rt = (wcol < 124) ? __half2float(r[4]) : 0.f;
        const float* k = kv + (dy + 1) * 3;
        a0 += k[0]*lf + k[1]*m0 + k[2]*m1;
        a1 += k[0]*m0 + k[1]*m1 + k[2]*m2;
        a2 += k[0]*m1 + k[1]*m2 + k[2]*m3;
        a3 += k[0]*m2 + k[1]*m3 + k[2]*rt;
    }
}

// merged q-grouped + kv1 + kv2 depthwise (grid.y = 3*C2)
__global__ void dwconv_all(const float* __restrict__ Wq, const float* __restrict__ Wt1,
                           const float* __restrict__ Wt2) {
    int b = blockIdx.z, cc = blockIdx.y;
    int p = (blockIdx.x * 256 + threadIdx.x) * 4;
    int h = p >> 7, wcol = p & 127;
    float a0 = 0, a1 = 0, a2 = 0, a3 = 0;
    if (cc < C2) {
        // grouped conv: 2 in / 2 out per group
        int o = cc;
        int i0 = (o >> 1) << 1;
        const __half* x0 = g_qpre + ((size_t)b * C2 + i0) * HWN;
        float kv[18];
        #pragma unroll
        for (int i = 0; i < 18; i++) kv[i] = Wq[(size_t)o * 18 + i];
        dw_core_h(x0, kv, h, wcol, a0, a1, a2, a3);
        dw_core_h(x0 + HWN, kv + 9, h, wcol, a0, a1, a2, a3);
        st_half4(g_q + ((size_t)b * C2 + o) * HWN + p, a0, a1, a2, a3);
    } else {
        const __half* X; const float* Wt; __half* Y; int c;
        if (cc < 2 * C2) { X = g_kv1pre; Wt = Wt1; Y = g_kv1; c = cc - C2; }
        else             { X = g_kv2pre; Wt = Wt2; Y = g_kv2; c = cc - 2 * C2; }
        const __half* xp = X + ((size_t)b * C2 + c) * HWN;
        float kv[9];
        #pragma unroll
        for (int i = 0; i < 9; i++) kv[i] = Wt[(size_t)c * 9 + i];
        dw_core_h(xp, kv, h, wcol, a0, a1, a2, a3);
        st_half4(Y + ((size_t)b * C2 + c) * HWN + p, a0, a1, a2, a3);
    }
}

// ---------------- fused FFN dwconv + gated gelu -> fp16 [c][p] --------------
__global__ void dwgelu(const float* __restrict__ Wt, __half* __restrict__ Hx) {
    int b = blockIdx.z, c = blockIdx.y;
    int p = (blockIdx.x * 256 + threadIdx.x) * 4;
    size_t oidx = ((size_t)b * GGPAD + c) * HWN + p;
    if (c >= HIDC) {
        *(uint2*)(Hx + oidx) = make_uint2(0, 0);
        return;
    }
    int h = p >> 7, wcol = p & 127;
    float va[8];
    #pragma unroll
    for (int half = 0; half < 2; half++) {
        int ch = c + half * HIDC;
        const __half* xp = g_h + ((size_t)b * HID2 + ch) * HWN;
        float kv[9];
        #pragma unroll
        for (int i = 0; i < 9; i++) kv[i] = Wt[(size_t)ch * 9 + i];
        float a0 = 0, a1 = 0, a2 = 0, a3 = 0;
        dw_core_h(xp, kv, h, wcol, a0, a1, a2, a3);
        va[half*4+0] = a0; va[half*4+1] = a1; va[half*4+2] = a2; va[half*4+3] = a3;
    }
    float o[4];
    #pragma unroll
    for (int j = 0; j < 4; j++) {
        float a = va[j];
        float ge = 0.5f * a * (1.f + erff(a * 0.70710678118654752f));
        o[j] = ge * va[4+j];
    }
    st_half4(Hx + oidx, o[0], o[1], o[2], o[3]);
}

// ---------------- attention ----------------
__global__ void zero_attn() {
    int i = blockIdx.x * 256 + threadIdx.x;
    if (i < 32 * CHD * CHD) g_S[i] = 0.f;
    if (i < 32 * 96) g_nrm[i] = 0.f;
}

__global__ void skernel() {
    int m = blockIdx.x, ns = blockIdx.y;
    int b = m >> 3, br = (m >> 2) & 1, hh = m & 3;
    const __half* qb = g_q + ((size_t)b * C2 + br * CC + hh * CHD) * HWN;
    const __half* kb = (br ? g_kv2 : g_kv1) + ((size_t)b * C2 + hh * CHD) * HWN;
    __shared__ float Qs[CHD][65];
    __shared__ float Ks[CHD][65];
    int t = threadIdx.x;
    int tx = t & 15, ty = t >> 4;
    float acc[3][3];
    #pragma unroll
    for (int i = 0; i < 3; i++)
        #pragma unroll
        for (int j = 0; j < 3; j++) acc[i][j] = 0.f;
    const float* nrow = (t < CHD) ? &Qs[t][0] : ((t < 96) ? &Ks[t - CHD][0] : (const float*)0);
    float nacc = 0.f;
    int nbeg = ns * 1024;
    for (int n0 = nbeg; n0 < nbeg + 1024; n0 += 64) {
        #pragma unroll
        for (int i = t; i < CHD * 32; i += 256) {
            int rr = i >> 5, cc = (i & 31) * 2;
            __half2 qv2 = *(const __half2*)(qb + (size_t)rr * HWN + n0 + cc);
            __half2 kv2 = *(const __half2*)(kb + (size_t)rr * HWN + n0 + cc);
            Qs[rr][cc] = __low2float(qv2); Qs[rr][cc+1] = __high2float(qv2);
            Ks[rr][cc] = __low2float(kv2); Ks[rr][cc+1] = __high2float(kv2);
        }
        __syncthreads();
        if (nrow) {
            #pragma unroll 8
            for (int cc = 0; cc < 64; cc++) { float v = nrow[cc]; nacc += v * v; }
        }
        #pragma unroll 8
        for (int kk = 0; kk < 64; kk++) {
            float qv[3], kvv[3];
            #pragma unroll
            for (int i = 0; i < 3; i++) qv[i] = Qs[ty + 16 * i][kk];
            #pragma unroll
            for (int j = 0; j < 3; j++) kvv[j] = Ks[tx + 16 * j][kk];
            #pragma unroll
            for (int i = 0; i < 3; i++)
                #pragma unroll
                for (int j = 0; j < 3; j++) acc[i][j] += qv[i] * kvv[j];
        }
        __syncthreads();
    }
    #pragma unroll
    for (int i = 0; i < 3; i++)
        #pragma unroll
        for (int j = 0; j < 3; j++)
            atomicAdd(&g_S[m * CHD * CHD + (ty + 16 * i) * CHD + (tx + 16 * j)], acc[i][j]);
    if (t < 96) atomicAdd(&g_nrm[m * 96 + t], nacc);
}

__global__ void softmax_kernel(const float* __restrict__ t1, const float* __restrict__ t2) {
    int m = blockIdx.x;
    int c = threadIdx.x;
    __shared__ float nk[CHD];
    if (c < CHD) nk[c] = fmaxf(sqrtf(g_nrm[m * 96 + CHD + c]), 1e-12f);
    __syncthreads();
    if (c >= CHD) return;
    int br = (m >> 2) & 1, hh = m & 3;
    float tmp = (br ? t2 : t1)[hh];
    float nq = fmaxf(sqrtf(g_nrm[m * 96 + c]), 1e-12f);
    float* row = g_S + (size_t)m * CHD * CHD + c * CHD;
    float vals[CHD];
    float mx = -1e30f;
    #pragma unroll
    for (int d = 0; d < CHD; d++) {
        float v = row[d] / (nq * nk[d]) * tmp;
        vals[d] = v;
        mx = fmaxf(mx, v);
    }
    float sum = 0.f;
    #pragma unroll
    for (int d = 0; d < CHD; d++) { vals[d] = __expf(vals[d] - mx); sum += vals[d]; }
    float inv = 1.f / sum;
    #pragma unroll
    for (int d = 0; d < CHD; d++) row[d] = vals[d] * inv;
}

__global__ void av_cp() {
    int m = blockIdx.x;
    int b = m >> 3, br = (m >> 2) & 1, hh = m & 3;
    __shared__ float As[CHD * CHD];
    for (int i = threadIdx.x; i < CHD * CHD; i += 128) As[i] = g_S[(size_t)m * CHD * CHD + i];
    __syncthreads();
    const __half* vb = (br ? g_kv2 : g_kv1) + ((size_t)b * C2 + CC + hh * CHD) * HWN;
    int p = blockIdx.y * 256 + threadIdx.x * 2;
    float acc0[CHD], acc1[CHD];
    #pragma unroll
    for (int c = 0; c < CHD; c++) { acc0[c] = 0.f; acc1[c] = 0.f; }
    for (int d = 0; d < CHD; d++) {
        __half2 v2 = *(const __half2*)(vb + (size_t)d * HWN + p);
        float vx = __low2float(v2), vy = __high2float(v2);
        #pragma unroll
        for (int c = 0; c < CHD; c++) {
            float a = As[c * CHD + d];
            acc0[c] += a * vx;
            acc1[c] += a * vy;
        }
    }
    int off = br * CC + hh * CHD;
    size_t base = ((size_t)b * C2 + off) * HWN + p;
    #pragma unroll
    for (int c = 0; c < CHD; c++) {
        __half2 h2 = __floats2half2_rn(acc0[c], acc1[c]);
        *(__half2*)(xt_ao + base + (size_t)c * HWN) = h2;
    }
}

// ---------------- launch ----------------
extern "C" void kernel_launch(void* const* d_in, const int* in_sizes, int n_in,
                              void* d_out, int out_size) {
    const float* x       = (const float*)d_in[0];
    const float* kv1in   = (const float*)d_in[1];
    const float* kv2in   = (const float*)d_in[2];
    const float* n1w = (const float*)d_in[3];  const float* n1b = (const float*)d_in[4];
    const float* nk1w = (const float*)d_in[5]; const float* nk1b = (const float*)d_in[6];
    const float* nk2w = (const float*)d_in[7]; const float* nk2b = (const float*)d_in[8];
    const float* n2w = (const float*)d_in[9];  const float* n2b = (const float*)d_in[10];
    const float* q_w   = (const float*)d_in[11];
    const float* kv1_w = (const float*)d_in[12];
    const float* kv2_w = (const float*)d_in[13];
    const float* q_dw  = (const float*)d_in[14];
    const float* kv1_dw= (const float*)d_in[15];
    const float* kv2_dw= (const float*)d_in[16];
    const float* proj_w= (const float*)d_in[17];
    const float* temp1 = (const float*)d_in[18];
    const float* temp2 = (const float*)d_in[19];
    const float* pin_w = (const float*)d_in[20];
    const float* dw_w  = (const float*)d_in[21];
    const float* pout_w= (const float*)d_in[22];
    float* out = (float*)d_out;

    cudaFuncSetAttribute((const void*)gemm_mma<false, true>,  cudaFuncAttributeMaxDynamicSharedMemorySize, GEMM_SMEM);
    cudaFuncSetAttribute((const void*)gemm_mma<true, false>,  cudaFuncAttributeMaxDynamicSharedMemorySize, GEMM_SMEM);
    cudaFuncSetAttribute((const void*)gemm3, cudaFuncAttributeMaxDynamicSharedMemorySize, GEMM_SMEM);

    float *p_x2;
    cudaGetSymbolAddress((void**)&p_x2, g_x2);
    __half *p_h, *wh, *pa, *pao, *pgg;
    cudaGetSymbolAddress((void**)&p_h, g_h);
    cudaGetSymbolAddress((void**)&wh, g_wh);
    cudaGetSymbolAddress((void**)&pa, xt_a);
    cudaGetSymbolAddress((void**)&pao, xt_ao);
    cudaGetSymbolAddress((void**)&pgg, xt_gg);

    // 1: weights
    wconv_all<<<2556, 64>>>(q_w, kv1_w, kv2_w, proj_w, pin_w, pout_w);
    // 2: merged LNs
    ln3<<<dim3(HWN / 64, BB, 3), 256>>>(x, kv1in, kv2in, n1w, n1b, nk1w, nk1b, nk2w, nk2b);
    // 3: zero attn accumulators
    zero_attn<<<300, 256>>>();
    // 4: merged q/kv1/kv2 GEMM (profiled slot)
    gemm3<<<dim3(HWN / 128, 3, 12), 256, GEMM_SMEM>>>();
    // 5: merged dwconvs
    dim3 dAll(HWN / 1024, 3 * C2, BB);
    dwconv_all<<<dAll, 256>>>(q_dw, kv1_dw, kv2_dw);
    // 6-8: attention
    skernel<<<dim3(32, 16), 256>>>();
    softmax_kernel<<<32, 64>>>(temp1, temp2);
    av_cp<<<dim3(32, HWN / 256), 128>>>();
    // 9: proj + residual x -> g_x2 (fp32)
    dim3 gP(HWN / 128, 2, BB);
    gemm_mma<true, false><<<gP, 256, GEMM_SMEM>>>(wh + OFF_P, pao, x, p_x2, 192, 384);
    // 10: FFN LN
    dim3 lnG(HWN / 64, BB);
    ln_cp<<<lnG, 256>>>(p_x2, n2w, n2b, pa);
    // 11: pin GEMM -> g_h (fp16)
    dim3 gIn(HWN / 128, 8, BB);
    gemm_mma<false, true><<<gIn, 256, GEMM_SMEM>>>(wh + OFF_PIN, pa, nullptr, p_h, 1020, 192);
    // 12: fused dwconv+gelu
    dim3 dGG(HWN / 1024, GGPAD, BB);
    dwgelu<<<dGG, 256>>>(dw_w, pgg);
    // 13: pout GEMM + residual
    gemm_mma<true, false><<<gP, 256, GEMM_SMEM>>>(wh + OFF_PO, pgg, p_x2, out, 192, 512);
}

// round 12
// speedup vs baseline: 1.1878x; 1.1878x over previous
#include <cuda_runtime.h>
#include <cuda_fp16.h>
#include <math.h>

#define BB 4
#define CC 192
#define C2 384
#define HWN 16384
#define HIMG 128
#define CHD 48
#define HIDC 510
#define HID2 1020
#define GGPAD 512
#define EPSLN 1e-5f

__device__ __forceinline__ unsigned smem_u32(const void* p) {
    unsigned a;
    asm("{ .reg .u64 t; cvta.to.shared.u64 t, %1; cvt.u32.u64 %0, t; }"
        : "=r"(a) : "l"(p));
    return a;
}
#define CP_ASYNC16(dst, src) \
    asm volatile("cp.async.cg.shared.global [%0], [%1], 16;" :: "r"(dst), "l"(src))
#define CP_COMMIT() asm volatile("cp.async.commit_group;" ::: "memory")
#define CP_WAIT(n)  asm volatile("cp.async.wait_group %0;" :: "n"(n) : "memory")

__device__ __forceinline__ void ldm_x4(unsigned& r0, unsigned& r1, unsigned& r2, unsigned& r3,
                                       unsigned addr) {
    asm volatile("ldmatrix.sync.aligned.m8n8.x4.shared.b16 {%0,%1,%2,%3}, [%4];"
        : "=r"(r0), "=r"(r1), "=r"(r2), "=r"(r3) : "r"(addr));
}
__device__ __forceinline__ void ldm_x4_t(unsigned& r0, unsigned& r1, unsigned& r2, unsigned& r3,
                                         unsigned addr) {
    asm volatile("ldmatrix.sync.aligned.m8n8.x4.trans.shared.b16 {%0,%1,%2,%3}, [%4];"
        : "=r"(r0), "=r"(r1), "=r"(r2), "=r"(r3) : "r"(addr));
}
__device__ __forceinline__ void mma_f16(float* d, const unsigned* a, unsigned b0, unsigned b1) {
    asm volatile("mma.sync.aligned.m16n8k16.row.col.f32.f16.f16.f32 "
        "{%0,%1,%2,%3}, {%4,%5,%6,%7}, {%8,%9}, {%0,%1,%2,%3};"
        : "+f"(d[0]), "+f"(d[1]), "+f"(d[2]), "+f"(d[3])
        : "r"(a[0]), "r"(a[1]), "r"(a[2]), "r"(a[3]), "r"(b0), "r"(b1));
}

// ---------------- scratch ----------------
__device__ __align__(16) __half g_qpre [BB*C2*HWN];
__device__ __align__(16) __half g_kv1pre[BB*C2*HWN];
__device__ __align__(16) __half g_kv2pre[BB*C2*HWN];
__device__ __align__(16) __half g_q   [BB*C2*HWN];
__device__ __align__(16) __half g_kv1 [BB*C2*HWN];
__device__ __align__(16) __half g_kv2 [BB*C2*HWN];
__device__ __align__(16) __half g_h   [BB*HID2*HWN];
__device__ float g_x2  [BB*CC*HWN];
__device__ float g_S   [32*CHD*CHD];
__device__ float g_nrm [32*2*CHD];

// fp16 activations, natural layout: [b][channel][pixel]
__device__ __align__(16) __half xt_a [BB*CC*HWN];
__device__ __align__(16) __half xt_k1[BB*CC*HWN];
__device__ __align__(16) __half xt_k2[BB*CC*HWN];
__device__ __align__(16) __half xt_ao[BB*C2*HWN];
__device__ __align__(16) __half xt_gg[BB*GGPAD*HWN];
// converted weights (row-major [O][Cpad]), fp16
#define OFF_Q   0
#define OFF_K1  (384*192)
#define OFF_K2  (2*384*192)
#define OFF_P   (3*384*192)
#define OFF_PIN (3*384*192 + 192*384)
#define OFF_PO  (3*384*192 + 192*384 + 1020*192)
#define WTOT    (3*384*192 + 192*384 + 1020*192 + 192*512)
#define WPAD    (64*512)
__device__ __align__(16) __half g_wh[WTOT + WPAD];

// ---------------- fp32 -> fp16 helpers ----------------
__device__ __forceinline__ void st_half4(__half* dst, float a0, float a1, float a2, float a3) {
    __half2 h01 = __floats2half2_rn(a0, a1);
    __half2 h23 = __floats2half2_rn(a2, a3);
    uint2 u; u.x = *(unsigned*)&h01; u.y = *(unsigned*)&h23;
    *(uint2*)dst = u;
}

// ---------------- merged weight conversion ----------------
__global__ void wconv_all(const float* __restrict__ q_w, const float* __restrict__ kv1_w,
                          const float* __restrict__ kv2_w, const float* __restrict__ proj_w,
                          const float* __restrict__ pin_w, const float* __restrict__ pout_w) {
    int r = blockIdx.x;
    const float* W; int o, Cin, Cpad, off;
    if (r < 384)        { W = q_w;    o = r;        Cin = 192; Cpad = 192; off = OFF_Q; }
    else if (r < 768)   { W = kv1_w;  o = r - 384;  Cin = 192; Cpad = 192; off = OFF_K1; }
    else if (r < 1152)  { W = kv2_w;  o = r - 768;  Cin = 192; Cpad = 192; off = OFF_K2; }
    else if (r < 1344)  { W = proj_w; o = r - 1152; Cin = 384; Cpad = 384; off = OFF_P; }
    else if (r < 2364)  { W = pin_w;  o = r - 1344; Cin = 192; Cpad = 192; off = OFF_PIN; }
    else                { W = pout_w; o = r - 2364; Cin = 510; Cpad = 512; off = OFF_PO; }
    int c0 = threadIdx.x * 8;
    if (c0 >= Cpad) return;
    float v[8];
    #pragma unroll
    for (int j = 0; j < 8; j++) {
        int c = c0 + j;
        v[j] = (c < Cin) ? W[(size_t)o * Cin + c] : 0.f;
    }
    __half* dst = g_wh + (size_t)off + (size_t)o * Cpad + c0;
    st_half4(dst,     v[0], v[1], v[2], v[3]);
    st_half4(dst + 4, v[4], v[5], v[6], v[7]);
}

// ======================= HMMA GEMM body (unchanged from R11) =================
#define BK 32
#define ASTRIDE 40
#define PSTR 136
#define A_BYTES (128 * ASTRIDE * 2)
#define B_BYTES (BK * PSTR * 2)
#define BUF_BYTES (A_BYTES + B_BYTES)
#define YSTRIDE 132
#define GEMM_SMEM (128 * YSTRIDE * 4)

template<bool RESID, bool HALF_OUT>
__device__ __forceinline__
void gemm_body(const __half* __restrict__ W, const __half* __restrict__ XB,
               const float* __restrict__ R, void* __restrict__ Yv, int O, int Cpad,
               int b, int p0, int o0, char* dsm) {
    unsigned sbase = smem_u32(dsm);
    int t = threadIdx.x, lane = t & 31, wid = t >> 5;
    int warpM = (wid >> 1) * 32;
    int warpN = (wid & 1) * 64;
    const __half* WB = W + (size_t)o0 * Cpad;
    int nk = Cpad / BK;

    auto fill = [&](int kt) {
        int buf = kt & 1;
        unsigned bb = sbase + buf * BUF_BYTES;
        int k0 = kt * BK;
        #pragma unroll
        for (int j = 0; j < 4; j++) {
            int ci = j * 256 + t;
            if (ci < 512) {
                int row = ci >> 2, g = ci & 3;
                const __half* src = WB + (size_t)row * Cpad + k0 + g * 8;
                unsigned dst = bb + (unsigned)(row * ASTRIDE + g * 8) * 2;
                CP_ASYNC16(dst, src);
            } else {
                int m = ci - 512;
                int row = m >> 4, g = m & 15;
                const __half* src = XB + (size_t)(k0 + row) * HWN + g * 8;
                unsigned dst = bb + A_BYTES + (unsigned)(row * PSTR + g * 8) * 2;
                CP_ASYNC16(dst, src);
            }
        }
        CP_COMMIT();
    };

    float acc[2][8][4];
    #pragma unroll
    for (int i = 0; i < 2; i++)
        #pragma unroll
        for (int j = 0; j < 8; j++)
            #pragma unroll
            for (int k = 0; k < 4; k++) acc[i][j][k] = 0.f;

    fill(0);
    int rsel = lane & 15, csel = (lane >> 4) * 8;
    int bkr = (lane & 7) + ((lane >> 4) & 1) * 8;
    int bpc = ((lane >> 3) & 1) * 8;

    for (int kt = 0; kt < nk; kt++) {
        if (kt + 1 < nk) { fill(kt + 1); CP_WAIT(1); }
        else             { CP_WAIT(0); }
        __syncthreads();
        unsigned bb = sbase + (kt & 1) * BUF_BYTES;
        unsigned Aa = bb, Ba = bb + A_BYTES;
        #pragma unroll
        for (int kk = 0; kk < 2; kk++) {
            int kc = csel + kk * 16;
            unsigned af[2][4], bf[4][4];
            #pragma unroll
            for (int mt = 0; mt < 2; mt++) {
                unsigned off = (unsigned)((warpM + mt * 16 + rsel) * ASTRIDE + kc) * 2;
                ldm_x4(af[mt][0], af[mt][1], af[mt][2], af[mt][3], Aa + off);
            }
            #pragma unroll
            for (int np = 0; np < 4; np++) {
                unsigned off = (unsigned)((kk * 16 + bkr) * PSTR + warpN + np * 16 + bpc) * 2;
                ldm_x4_t(bf[np][0], bf[np][1], bf[np][2], bf[np][3], Ba + off);
            }
            #pragma unroll
            for (int mt = 0; mt < 2; mt++)
                #pragma unroll
                for (int nt = 0; nt < 8; nt++) {
                    int np = nt >> 1, hf = nt & 1;
                    mma_f16(acc[mt][nt], af[mt], bf[np][hf], bf[np][hf + 2]);
                }
        }
        __syncthreads();
    }

    float* Ysm = (float*)dsm;
    #pragma unroll
    for (int mt = 0; mt < 2; mt++)
        #pragma unroll
        for (int nt = 0; nt < 8; nt++) {
            int r0 = warpM + mt * 16 + (lane >> 2);
            int cc = warpN + nt * 8 + (lane & 3) * 2;
            Ysm[r0 * YSTRIDE + cc]           = acc[mt][nt][0];
            Ysm[r0 * YSTRIDE + cc + 1]       = acc[mt][nt][1];
            Ysm[(r0 + 8) * YSTRIDE + cc]     = acc[mt][nt][2];
            Ysm[(r0 + 8) * YSTRIDE + cc + 1] = acc[mt][nt][3];
        }
    __syncthreads();
    #pragma unroll
    for (int i = 0; i < 16; i++) {
        int idx = i * 256 + t;
        int row = idx >> 5, c4 = (idx & 31) * 4;
        int o = o0 + row;
        if (o < O) {
            float4 v = *(float4*)(Ysm + row * YSTRIDE + c4);
            size_t goff = ((size_t)b * O + o) * HWN + p0 + c4;
            if (HALF_OUT) {
                st_half4((__half*)Yv + goff, v.x, v.y, v.z, v.w);
            } else {
                if (RESID) {
                    float4 q = *(const float4*)(R + goff);
                    v.x += q.x; v.y += q.y; v.z += q.z; v.w += q.w;
                }
                *(float4*)((float*)Yv + goff) = v;
            }
        }
    }
}

template<bool RESID, bool HALF_OUT>
__global__ __launch_bounds__(256)
void gemm_mma(const __half* __restrict__ W, const __half* __restrict__ X,
              const float* __restrict__ R, void* __restrict__ Y, int O, int Cpad) {
    extern __shared__ char dsm[];
    int b = blockIdx.z;
    gemm_body<RESID, HALF_OUT>(W,
                     X + (size_t)b * Cpad * HWN + blockIdx.x * 128,
                     R, Y, O, Cpad, b, blockIdx.x * 128, blockIdx.y * 128, dsm);
}

__global__ __launch_bounds__(256)
void gemm3(void) {
    extern __shared__ char dsm[];
    int z = blockIdx.z, which = z >> 2, b = z & 3;
    const __half *W, *X;
    __half* Y;
    if (which == 0)      { W = g_wh + OFF_Q;  X = xt_a;  Y = g_qpre; }
    else if (which == 1) { W = g_wh + OFF_K1; X = xt_k1; Y = g_kv1pre; }
    else                 { W = g_wh + OFF_K2; X = xt_k2; Y = g_kv2pre; }
    gemm_body<false, true>(W,
                     X + (size_t)b * CC * HWN + blockIdx.x * 128,
                     nullptr, Y, C2, CC, b, blockIdx.x * 128, blockIdx.y * 128, dsm);
}

// ---------------- LayerNorm -> fp16 [c][p] ----------------------------------
__device__ __forceinline__
void ln_body(const float* __restrict__ X, const float* __restrict__ w,
             const float* __restrict__ bia, __half* __restrict__ Hx,
             int b, int pblk) {
    __shared__ float2 red[256];
    int px = threadIdx.x & 63, cg = threadIdx.x >> 6;
    int p = pblk * 64 + px;
    const float* xp = X + ((size_t)b * CC + (size_t)cg * 48) * HWN + p;
    float v[48];
    float s = 0.f, q = 0.f;
    #pragma unroll
    for (int i = 0; i < 48; i++) {
        float t = xp[(size_t)i * HWN];
        v[i] = t; s += t; q += t * t;
    }
    red[threadIdx.x] = make_float2(s, q);
    __syncthreads();
    float2 r0 = red[px], r1 = red[64 + px], r2 = red[128 + px], r3 = red[192 + px];
    float st = r0.x + r1.x + r2.x + r3.x;
    float qt = r0.y + r1.y + r2.y + r3.y;
    const float invc = 1.f / CC;
    float mu = st * invc;
    float iv = rsqrtf(fmaxf(qt * invc - mu * mu, 0.f) + EPSLN);
    size_t base = ((size_t)b * CC + (size_t)cg * 48) * HWN + p;
    #pragma unroll
    for (int i = 0; i < 48; i++) {
        int c = cg * 48 + i;
        float o = (v[i] - mu) * iv * w[c] + bia[c];
        Hx[base + (size_t)i * HWN] = __float2half_rn(o);
    }
}

__global__ __launch_bounds__(256)
void ln3(const float* __restrict__ X0, const float* __restrict__ X1, const float* __restrict__ X2,
         const float* __restrict__ w0, const float* __restrict__ b0,
         const float* __restrict__ w1, const float* __restrict__ b1,
         const float* __restrict__ w2, const float* __restrict__ b2) {
    int which = blockIdx.z;
    const float *X, *w, *bia;
    __half* Hx;
    if (which == 0)      { X = X0; w = w0; bia = b0; Hx = xt_a; }
    else if (which == 1) { X = X1; w = w1; bia = b1; Hx = xt_k1; }
    else                 { X = X2; w = w2; bia = b2; Hx = xt_k2; }
    ln_body(X, w, bia, Hx, blockIdx.y, blockIdx.x);
}

__global__ __launch_bounds__(256)
void ln_cp(const float* __restrict__ X, const float* __restrict__ w,
           const float* __restrict__ bia, __half* __restrict__ Hx) {
    ln_body(X, w, bia, Hx, blockIdx.y, blockIdx.x);
}

// ---------------- depthwise 3x3 core over fp16 input ----------------
__device__ __forceinline__ void dw_core_h(const __half* __restrict__ xp, const float* kv,
                                          int h, int wcol, float& a0, float& a1,
                                          float& a2, float& a3) {
    #pragma unroll
    for (int dy = -1; dy <= 1; dy++) {
        int hh = h + dy;
        if (hh < 0 || hh >= HIMG) continue;
        const __half* r = xp + hh * HIMG + wcol;
        __half2 p01 = *(const __half2*)r;
        __half2 p23 = *(const __half2*)(r + 2);
        float m0 = __low2float(p01), m1 = __high2float(p01);
        float m2 = __low2float(p23), m3 = __high2float(p23);
        float lf = (wcol > 0) ? __half2float(r[-1]) : 0.f;
        float rt = (wcol < 124) ? __half2float(r[4]) : 0.f;
        const float* k = kv + (dy + 1) * 3;
        a0 += k[0]*lf + k[1]*m0 + k[2]*m1;
        a1 += k[0]*m0 + k[1]*m1 + k[2]*m2;
        a2 += k[0]*m1 + k[1]*m2 + k[2]*m3;
        a3 += k[0]*m2 + k[1]*m3 + k[2]*rt;
    }
}

// merged q-grouped + kv1 + kv2 depthwise, with fused attention-norm sumsq
__global__ void dwconv_all(const float* __restrict__ Wq, const float* __restrict__ Wt1,
                           const float* __restrict__ Wt2) {
    __shared__ float red[256];
    int b = blockIdx.z, cc = blockIdx.y;
    int t = threadIdx.x;
    int p = (blockIdx.x * 256 + t) * 4;
    int h = p >> 7, wcol = p & 127;
    float a0 = 0, a1 = 0, a2 = 0, a3 = 0;
    bool want = false; int nm = 0, slot = 0;
    if (cc < C2) {
        int o = cc;
        int i0 = (o >> 1) << 1;
        const __half* x0 = g_qpre + ((size_t)b * C2 + i0) * HWN;
        float kv[18];
        #pragma unroll
        for (int i = 0; i < 18; i++) kv[i] = Wq[(size_t)o * 18 + i];
        dw_core_h(x0, kv, h, wcol, a0, a1, a2, a3);
        dw_core_h(x0 + HWN, kv + 9, h, wcol, a0, a1, a2, a3);
        st_half4(g_q + ((size_t)b * C2 + o) * HWN + p, a0, a1, a2, a3);
        int br = o / CC, rem = o % CC;
        want = true; nm = b * 8 + br * 4 + rem / CHD; slot = rem % CHD;
    } else {
        const __half* X; const float* Wt; __half* Y; int c, br;
        if (cc < 2 * C2) { X = g_kv1pre; Wt = Wt1; Y = g_kv1; c = cc - C2;     br = 0; }
        else             { X = g_kv2pre; Wt = Wt2; Y = g_kv2; c = cc - 2 * C2; br = 1; }
        const __half* xp = X + ((size_t)b * C2 + c) * HWN;
        float kv[9];
        #pragma unroll
        for (int i = 0; i < 9; i++) kv[i] = Wt[(size_t)c * 9 + i];
        dw_core_h(xp, kv, h, wcol, a0, a1, a2, a3);
        st_half4(Y + ((size_t)b * C2 + c) * HWN + p, a0, a1, a2, a3);
        if (c < CC) { want = true; nm = b * 8 + br * 4 + c / CHD; slot = CHD + c % CHD; }
    }
    // block-level sum of squares -> g_nrm
    red[t] = want ? (a0*a0 + a1*a1 + a2*a2 + a3*a3) : 0.f;
    __syncthreads();
    for (int st = 128; st > 0; st >>= 1) {
        if (t < st) red[t] += red[t + st];
        __syncthreads();
    }
    if (t == 0 && want) atomicAdd(&g_nrm[nm * 96 + slot], red[0]);
}

// ---------------- fused FFN dwconv + gated gelu -> fp16 [c][p] --------------
__global__ void dwgelu(const float* __restrict__ Wt, __half* __restrict__ Hx) {
    int b = blockIdx.z, c = blockIdx.y;
    int p = (blockIdx.x * 256 + threadIdx.x) * 4;
    size_t oidx = ((size_t)b * GGPAD + c) * HWN + p;
    if (c >= HIDC) {
        *(uint2*)(Hx + oidx) = make_uint2(0, 0);
        return;
    }
    int h = p >> 7, wcol = p & 127;
    float va[8];
    #pragma unroll
    for (int half = 0; half < 2; half++) {
        int ch = c + half * HIDC;
        const __half* xp = g_h + ((size_t)b * HID2 + ch) * HWN;
        float kv[9];
        #pragma unroll
        for (int i = 0; i < 9; i++) kv[i] = Wt[(size_t)ch * 9 + i];
        float a0 = 0, a1 = 0, a2 = 0, a3 = 0;
        dw_core_h(xp, kv, h, wcol, a0, a1, a2, a3);
        va[half*4+0] = a0; va[half*4+1] = a1; va[half*4+2] = a2; va[half*4+3] = a3;
    }
    float o[4];
    #pragma unroll
    for (int j = 0; j < 4; j++) {
        float a = va[j];
        float ge = 0.5f * a * (1.f + erff(a * 0.70710678118654752f));
        o[j] = ge * va[4+j];
    }
    st_half4(Hx + oidx, o[0], o[1], o[2], o[3]);
}

// ---------------- attention ----------------
__global__ void zero_attn() {
    int i = blockIdx.x * 256 + threadIdx.x;
    if (i < 32 * CHD * CHD) g_S[i] = 0.f;
    if (i < 32 * 96) g_nrm[i] = 0.f;
}

// QK^T on HMMA. grid (32, 8): matrix m, k-split (2048 px each). 8 warps,
// each warp owns a 16-px slice of the 128-px staged chunk.
#define QKS 136
__global__ __launch_bounds__(256)
void skernel() {
    __shared__ __half Qs[CHD * QKS];
    __shared__ __half Ks[CHD * QKS];
    __shared__ float Ssm[CHD * 49];
    int m = blockIdx.x, ns = blockIdx.y;
    int b = m >> 3, br = (m >> 2) & 1, hh = m & 3;
    const __half* qb = g_q + ((size_t)b * C2 + br * CC + hh * CHD) * HWN;
    const __half* kb = (br ? g_kv2 : g_kv1) + ((size_t)b * C2 + hh * CHD) * HWN;
    int t = threadIdx.x, lane = t & 31, wid = t >> 5;
    for (int i = t; i < CHD * 49; i += 256) Ssm[i] = 0.f;
    unsigned qsb = smem_u32(Qs), ksb = smem_u32(Ks);

    float acc[3][6][4];
    #pragma unroll
    for (int i = 0; i < 3; i++)
        #pragma unroll
        for (int j = 0; j < 6; j++)
            #pragma unroll
            for (int k = 0; k < 4; k++) acc[i][j][k] = 0.f;

    int rsel = lane & 15, csel = (lane >> 4) * 8;
    int bnr = (lane & 7) + ((lane >> 4) & 1) * 8;   // n row (K channel) within 16
    int bkc = ((lane >> 3) & 1) * 8;                // k col within 16
    int kc = wid * 16;
    int nbeg = ns * 2048;

    for (int ch = 0; ch < 16; ch++) {
        int n0 = nbeg + ch * 128;
        __syncthreads();
        #pragma unroll
        for (int j = 0; j < 6; j++) {
            int ci = j * 256 + t;                   // 0..1535
            int mtx = (ci >= 768);
            int loc = ci - mtx * 768;
            int row = loc >> 4, g = loc & 15;
            const __half* src = (mtx ? kb : qb) + (size_t)row * HWN + n0 + g * 8;
            unsigned dst = (mtx ? ksb : qsb) + (unsigned)(row * QKS + g * 8) * 2;
            CP_ASYNC16(dst, src);
        }
        CP_COMMIT(); CP_WAIT(0);
        __syncthreads();
        unsigned af[3][4], bf[3][4];
        #pragma unroll
        for (int mt = 0; mt < 3; mt++) {
            unsigned off = (unsigned)((mt * 16 + rsel) * QKS + kc + csel) * 2;
            ldm_x4(af[mt][0], af[mt][1], af[mt][2], af[mt][3], qsb + off);
        }
        #pragma unroll
        for (int nf = 0; nf < 3; nf++) {
            unsigned off = (unsigned)((nf * 16 + bnr) * QKS + kc + bkc) * 2;
            ldm_x4(bf[nf][0], bf[nf][1], bf[nf][2], bf[nf][3], ksb + off);
        }
        #pragma unroll
        for (int mt = 0; mt < 3; mt++)
            #pragma unroll
            for (int nf = 0; nf < 3; nf++)
                #pragma unroll
                for (int hf = 0; hf < 2; hf++)
                    mma_f16(acc[mt][nf * 2 + hf], af[mt], bf[nf][2 * hf], bf[nf][2 * hf + 1]);
    }
    __syncthreads();
    #pragma unroll
    for (int mt = 0; mt < 3; mt++)
        #pragma unroll
        for (int nt = 0; nt < 6; nt++) {
            int r0 = mt * 16 + (lane >> 2);
            int cl = nt * 8 + (lane & 3) * 2;
            atomicAdd(&Ssm[r0 * 49 + cl],           acc[mt][nt][0]);
            atomicAdd(&Ssm[r0 * 49 + cl + 1],       acc[mt][nt][1]);
            atomicAdd(&Ssm[(r0 + 8) * 49 + cl],     acc[mt][nt][2]);
            atomicAdd(&Ssm[(r0 + 8) * 49 + cl + 1], acc[mt][nt][3]);
        }
    __syncthreads();
    for (int i = t; i < CHD * CHD; i += 256) {
        int r = i / CHD, c = i % CHD;
        atomicAdd(&g_S[(size_t)m * CHD * CHD + i], Ssm[r * 49 + c]);
    }
}

__global__ void softmax_kernel(const float* __restrict__ t1, const float* __restrict__ t2) {
    int m = blockIdx.x;
    int c = threadIdx.x;
    __shared__ float nk[CHD];
    if (c < CHD) nk[c] = fmaxf(sqrtf(g_nrm[m * 96 + CHD + c]), 1e-12f);
    __syncthreads();
    if (c >= CHD) return;
    int br = (m >> 2) & 1, hh = m & 3;
    float tmp = (br ? t2 : t1)[hh];
    float nq = fmaxf(sqrtf(g_nrm[m * 96 + c]), 1e-12f);
    float* row = g_S + (size_t)m * CHD * CHD + c * CHD;
    float vals[CHD];
    float mx = -1e30f;
    #pragma unroll
    for (int d = 0; d < CHD; d++) {
        float v = row[d] / (nq * nk[d]) * tmp;
        vals[d] = v;
        mx = fmaxf(mx, v);
    }
    float sum = 0.f;
    #pragma unroll
    for (int d = 0; d < CHD; d++) { vals[d] = __expf(vals[d] - mx); sum += vals[d]; }
    float inv = 1.f / sum;
    #pragma unroll
    for (int d = 0; d < CHD; d++) row[d] = vals[d] * inv;
}

// A·V on HMMA. grid (32, 64): matrix m, 256-px chunk. A fp16 [m][k], V trans.
#define AVS 56
#define VVS 264
__global__ __launch_bounds__(256)
void av_mma() {
    __shared__ __half As[CHD * AVS];
    __shared__ __half Vs[CHD * VVS];
    int m = blockIdx.x;
    int b = m >> 3, br = (m >> 2) & 1, hh = m & 3;
    int t = threadIdx.x, lane = t & 31, wid = t >> 5;
    for (int i = t; i < CHD * CHD; i += 256) {
        int r = i / CHD, c = i % CHD;
        As[r * AVS + c] = __float2half_rn(g_S[(size_t)m * CHD * CHD + i]);
    }
    const __half* vb = (br ? g_kv2 : g_kv1) + ((size_t)b * C2 + CC + hh * CHD) * HWN;
    int p0 = blockIdx.y * 256;
    unsigned asb = smem_u32(As), vsb = smem_u32(Vs);
    #pragma unroll
    for (int j = 0; j < 6; j++) {
        int ci = j * 256 + t;              // 0..1535: 48 rows x 32 groups
        int row = ci >> 5, g = ci & 31;
        CP_ASYNC16(vsb + (unsigned)(row * VVS + g * 8) * 2,
                   vb + (size_t)row * HWN + p0 + g * 8);
    }
    CP_COMMIT(); CP_WAIT(0);
    __syncthreads();

    int rsel = lane & 15, csel = (lane >> 4) * 8;
    int bkr = (lane & 7) + ((lane >> 4) & 1) * 8;
    int bpc = ((lane >> 3) & 1) * 8;
    int warpN = wid * 32;

    float acc[3][4][4];
    #pragma unroll
    for (int i = 0; i < 3; i++)
        #pragma unroll
        for (int j = 0; j < 4; j++)
            #pragma unroll
            for (int k = 0; k < 4; k++) acc[i][j][k] = 0.f;

    #pragma unroll
    for (int kt = 0; kt < 3; kt++) {
        unsigned af[3][4], bf[2][4];
        #pragma unroll
        for (int mt = 0; mt < 3; mt++) {
            unsigned off = (unsigned)((mt * 16 + rsel) * AVS + kt * 16 + csel) * 2;
            ldm_x4(af[mt][0], af[mt][1], af[mt][2], af[mt][3], asb + off);
        }
        #pragma unroll
        for (int np = 0; np < 2; np++) {
            unsigned off = (unsigned)((kt * 16 + bkr) * VVS + warpN + np * 16 + bpc) * 2;
            ldm_x4_t(bf[np][0], bf[np][1], bf[np][2], bf[np][3], vsb + off);
        }
        #pragma unroll
        for (int mt = 0; mt < 3; mt++)
            #pragma unroll
            for (int nt = 0; nt < 4; nt++) {
                int np = nt >> 1, hf = nt & 1;
                mma_f16(acc[mt][nt], af[mt], bf[np][hf], bf[np][hf + 2]);
            }
    }
    int off = br * CC + hh * CHD;
    #pragma unroll
    for (int mt = 0; mt < 3; mt++)
        #pragma unroll
        for (int nt = 0; nt < 4; nt++) {
            int r0 = off + mt * 16 + (lane >> 2);
            int pc = p0 + warpN + nt * 8 + (lane & 3) * 2;
            __half2 h0 = __floats2half2_rn(acc[mt][nt][0], acc[mt][nt][1]);
            __half2 h1 = __floats2half2_rn(acc[mt][nt][2], acc[mt][nt][3]);
            *(__half2*)(xt_ao + ((size_t)b * C2 + r0) * HWN + pc) = h0;
            *(__half2*)(xt_ao + ((size_t)b * C2 + r0 + 8) * HWN + pc) = h1;
        }
}

// ---------------- launch ----------------
extern "C" void kernel_launch(void* const* d_in, const int* in_sizes, int n_in,
                              void* d_out, int out_size) {
    const float* x       = (const float*)d_in[0];
    const float* kv1in   = (const float*)d_in[1];
    const float* kv2in   = (const float*)d_in[2];
    const float* n1w = (const float*)d_in[3];  const float* n1b = (const float*)d_in[4];
    const float* nk1w = (const float*)d_in[5]; const float* nk1b = (const float*)d_in[6];
    const float* nk2w = (const float*)d_in[7]; const float* nk2b = (const float*)d_in[8];
    const float* n2w = (const float*)d_in[9];  const float* n2b = (const float*)d_in[10];
    const float* q_w   = (const float*)d_in[11];
    const float* kv1_w = (const float*)d_in[12];
    const float* kv2_w = (const float*)d_in[13];
    const float* q_dw  = (const float*)d_in[14];
    const float* kv1_dw= (const float*)d_in[15];
    const float* kv2_dw= (const float*)d_in[16];
    const float* proj_w= (const float*)d_in[17];
    const float* temp1 = (const float*)d_in[18];
    const float* temp2 = (const float*)d_in[19];
    const float* pin_w = (const float*)d_in[20];
    const float* dw_w  = (const float*)d_in[21];
    const float* pout_w= (const float*)d_in[22];
    float* out = (float*)d_out;

    cudaFuncSetAttribute((const void*)gemm_mma<false, true>,  cudaFuncAttributeMaxDynamicSharedMemorySize, GEMM_SMEM);
    cudaFuncSetAttribute((const void*)gemm_mma<true, false>,  cudaFuncAttributeMaxDynamicSharedMemorySize, GEMM_SMEM);
    cudaFuncSetAttribute((const void*)gemm3, cudaFuncAttributeMaxDynamicSharedMemorySize, GEMM_SMEM);

    float *p_x2;
    cudaGetSymbolAddress((void**)&p_x2, g_x2);
    __half *p_h, *wh, *pa, *pao, *pgg;
    cudaGetSymbolAddress((void**)&p_h, g_h);
    cudaGetSymbolAddress((void**)&wh, g_wh);
    cudaGetSymbolAddress((void**)&pa, xt_a);
    cudaGetSymbolAddress((void**)&pao, xt_ao);
    cudaGetSymbolAddress((void**)&pgg, xt_gg);

    // 1: weights
    wconv_all<<<2556, 64>>>(q_w, kv1_w, kv2_w, proj_w, pin_w, pout_w);
    // 2: merged LNs
    ln3<<<dim3(HWN / 64, BB, 3), 256>>>(x, kv1in, kv2in, n1w, n1b, nk1w, nk1b, nk2w, nk2b);
    // 3: zero attn accumulators
    zero_attn<<<300, 256>>>();
    // 4: merged q/kv1/kv2 GEMM
    gemm3<<<dim3(HWN / 128, 3, 12), 256, GEMM_SMEM>>>();
    // 5: merged dwconvs (+ fused attention norms)
    dim3 dAll(HWN / 1024, 3 * C2, BB);
    dwconv_all<<<dAll, 256>>>(q_dw, kv1_dw, kv2_dw);
    // 6-8: attention on HMMA
    skernel<<<dim3(32, 8), 256>>>();
    softmax_kernel<<<32, 64>>>(temp1, temp2);
    av_mma<<<dim3(32, HWN / 256), 256>>>();
    // 9: proj + residual x -> g_x2 (fp32)
    dim3 gP(HWN / 128, 2, BB);
    gemm_mma<true, false><<<gP, 256, GEMM_SMEM>>>(wh + OFF_P, pao, x, p_x2, 192, 384);
    // 10: FFN LN
    dim3 lnG(HWN / 64, BB);
    ln_cp<<<lnG, 256>>>(p_x2, n2w, n2b, pa);
    // 11: pin GEMM -> g_h (fp16)
    dim3 gIn(HWN / 128, 8, BB);
    gemm_mma<false, true><<<gIn, 256, GEMM_SMEM>>>(wh + OFF_PIN, pa, nullptr, p_h, 1020, 192);
    // 12: fused dwconv+gelu
    dim3 dGG(HWN / 1024, GGPAD, BB);
    dwgelu<<<dGG, 256>>>(dw_w, pgg);
    // 13: pout GEMM + residual
    gemm_mma<true, false><<<gP, 256, GEMM_SMEM>>>(wh + OFF_PO, pgg, p_x2, out, 192, 512);
}

// round 13
// speedup vs baseline: 1.3750x; 1.1577x over previous
#include <cuda_runtime.h>
#include <cuda_fp16.h>
#include <math.h>

#define BB 4
#define CC 192
#define C2 384
#define HWN 16384
#define HIMG 128
#define CHD 48
#define HIDC 510
#define HID2 1020
#define GGPAD 512
#define EPSLN 1e-5f

__device__ __forceinline__ unsigned smem_u32(const void* p) {
    unsigned a;
    asm("{ .reg .u64 t; cvta.to.shared.u64 t, %1; cvt.u32.u64 %0, t; }"
        : "=r"(a) : "l"(p));
    return a;
}
#define CP_ASYNC16(dst, src) \
    asm volatile("cp.async.cg.shared.global [%0], [%1], 16;" :: "r"(dst), "l"(src))
#define CP_COMMIT() asm volatile("cp.async.commit_group;" ::: "memory")
#define CP_WAIT(n)  asm volatile("cp.async.wait_group %0;" :: "n"(n) : "memory")

__device__ __forceinline__ void ldm_x4(unsigned& r0, unsigned& r1, unsigned& r2, unsigned& r3,
                                       unsigned addr) {
    asm volatile("ldmatrix.sync.aligned.m8n8.x4.shared.b16 {%0,%1,%2,%3}, [%4];"
        : "=r"(r0), "=r"(r1), "=r"(r2), "=r"(r3) : "r"(addr));
}
__device__ __forceinline__ void ldm_x4_t(unsigned& r0, unsigned& r1, unsigned& r2, unsigned& r3,
                                         unsigned addr) {
    asm volatile("ldmatrix.sync.aligned.m8n8.x4.trans.shared.b16 {%0,%1,%2,%3}, [%4];"
        : "=r"(r0), "=r"(r1), "=r"(r2), "=r"(r3) : "r"(addr));
}
__device__ __forceinline__ void mma_f16(float* d, const unsigned* a, unsigned b0, unsigned b1) {
    asm volatile("mma.sync.aligned.m16n8k16.row.col.f32.f16.f16.f32 "
        "{%0,%1,%2,%3}, {%4,%5,%6,%7}, {%8,%9}, {%0,%1,%2,%3};"
        : "+f"(d[0]), "+f"(d[1]), "+f"(d[2]), "+f"(d[3])
        : "r"(a[0]), "r"(a[1]), "r"(a[2]), "r"(a[3]), "r"(b0), "r"(b1));
}

// ---------------- scratch ----------------
__device__ __align__(16) __half g_qpre [BB*C2*HWN];
__device__ __align__(16) __half g_kv1pre[BB*C2*HWN];
__device__ __align__(16) __half g_kv2pre[BB*C2*HWN];
__device__ __align__(16) __half g_q   [BB*C2*HWN];
__device__ __align__(16) __half g_kv1 [BB*C2*HWN];
__device__ __align__(16) __half g_kv2 [BB*C2*HWN];
__device__ __align__(16) __half g_h   [BB*HID2*HWN];
__device__ float g_x2  [BB*CC*HWN];
__device__ float g_S   [32*CHD*CHD];
__device__ float g_nrm [32*2*CHD];

// fp16 activations, natural layout: [b][channel][pixel]
__device__ __align__(16) __half xt_a [BB*CC*HWN];
__device__ __align__(16) __half xt_k1[BB*CC*HWN];
__device__ __align__(16) __half xt_k2[BB*CC*HWN];
__device__ __align__(16) __half xt_ao[BB*C2*HWN];
__device__ __align__(16) __half xt_gg[BB*GGPAD*HWN];
// converted weights (row-major [O][Cpad]), fp16
#define OFF_Q   0
#define OFF_K1  (384*192)
#define OFF_K2  (2*384*192)
#define OFF_P   (3*384*192)
#define OFF_PIN (3*384*192 + 192*384)
#define OFF_PO  (3*384*192 + 192*384 + 1020*192)
#define WTOT    (3*384*192 + 192*384 + 1020*192 + 192*512)
#define WPAD    (64*512)
__device__ __align__(16) __half g_wh[WTOT + WPAD];

// ---------------- fp32 -> fp16 helpers ----------------
__device__ __forceinline__ void st_half4(__half* dst, float a0, float a1, float a2, float a3) {
    __half2 h01 = __floats2half2_rn(a0, a1);
    __half2 h23 = __floats2half2_rn(a2, a3);
    uint2 u; u.x = *(unsigned*)&h01; u.y = *(unsigned*)&h23;
    *(uint2*)dst = u;
}
__device__ __forceinline__ void st_half8(__half* dst, const float* a) {
    __half2 h0 = __floats2half2_rn(a[0], a[1]);
    __half2 h1 = __floats2half2_rn(a[2], a[3]);
    __half2 h2 = __floats2half2_rn(a[4], a[5]);
    __half2 h3 = __floats2half2_rn(a[6], a[7]);
    uint4 u;
    u.x = *(unsigned*)&h0; u.y = *(unsigned*)&h1;
    u.z = *(unsigned*)&h2; u.w = *(unsigned*)&h3;
    *(uint4*)dst = u;
}

// ---------------- merged weight conversion ----------------
__global__ void wconv_all(const float* __restrict__ q_w, const float* __restrict__ kv1_w,
                          const float* __restrict__ kv2_w, const float* __restrict__ proj_w,
                          const float* __restrict__ pin_w, const float* __restrict__ pout_w) {
    int r = blockIdx.x;
    const float* W; int o, Cin, Cpad, off;
    if (r < 384)        { W = q_w;    o = r;        Cin = 192; Cpad = 192; off = OFF_Q; }
    else if (r < 768)   { W = kv1_w;  o = r - 384;  Cin = 192; Cpad = 192; off = OFF_K1; }
    else if (r < 1152)  { W = kv2_w;  o = r - 768;  Cin = 192; Cpad = 192; off = OFF_K2; }
    else if (r < 1344)  { W = proj_w; o = r - 1152; Cin = 384; Cpad = 384; off = OFF_P; }
    else if (r < 2364)  { W = pin_w;  o = r - 1344; Cin = 192; Cpad = 192; off = OFF_PIN; }
    else                { W = pout_w; o = r - 2364; Cin = 510; Cpad = 512; off = OFF_PO; }
    int c0 = threadIdx.x * 8;
    if (c0 >= Cpad) return;
    float v[8];
    #pragma unroll
    for (int j = 0; j < 8; j++) {
        int c = c0 + j;
        v[j] = (c < Cin) ? W[(size_t)o * Cin + c] : 0.f;
    }
    st_half8(g_wh + (size_t)off + (size_t)o * Cpad + c0, v);
}

// ======================= HMMA GEMM body =====================================
#define BK 32
#define ASTRIDE 40
#define PSTR 136
#define A_BYTES (128 * ASTRIDE * 2)
#define B_BYTES (BK * PSTR * 2)
#define BUF_BYTES (A_BYTES + B_BYTES)
#define YSTRIDE 132
#define GEMM_SMEM (128 * YSTRIDE * 4)
#define GEMM_SMEM_H (2 * BUF_BYTES)

template<bool RESID, bool HALF_OUT>
__device__ __forceinline__
void gemm_body(const __half* __restrict__ W, const __half* __restrict__ XB,
               const float* __restrict__ R, void* __restrict__ Yv, int O, int Cpad,
               int b, int p0, int o0, char* dsm) {
    unsigned sbase = smem_u32(dsm);
    int t = threadIdx.x, lane = t & 31, wid = t >> 5;
    int warpM = (wid >> 1) * 32;
    int warpN = (wid & 1) * 64;
    const __half* WB = W + (size_t)o0 * Cpad;
    int nk = Cpad / BK;

    auto fill = [&](int kt) {
        int buf = kt & 1;
        unsigned bb = sbase + buf * BUF_BYTES;
        int k0 = kt * BK;
        #pragma unroll
        for (int j = 0; j < 4; j++) {
            int ci = j * 256 + t;
            if (ci < 512) {
                int row = ci >> 2, g = ci & 3;
                const __half* src = WB + (size_t)row * Cpad + k0 + g * 8;
                unsigned dst = bb + (unsigned)(row * ASTRIDE + g * 8) * 2;
                CP_ASYNC16(dst, src);
            } else {
                int m = ci - 512;
                int row = m >> 4, g = m & 15;
                const __half* src = XB + (size_t)(k0 + row) * HWN + g * 8;
                unsigned dst = bb + A_BYTES + (unsigned)(row * PSTR + g * 8) * 2;
                CP_ASYNC16(dst, src);
            }
        }
        CP_COMMIT();
    };

    float acc[2][8][4];
    #pragma unroll
    for (int i = 0; i < 2; i++)
        #pragma unroll
        for (int j = 0; j < 8; j++)
            #pragma unroll
            for (int k = 0; k < 4; k++) acc[i][j][k] = 0.f;

    fill(0);
    int rsel = lane & 15, csel = (lane >> 4) * 8;
    int bkr = (lane & 7) + ((lane >> 4) & 1) * 8;
    int bpc = ((lane >> 3) & 1) * 8;

    for (int kt = 0; kt < nk; kt++) {
        if (kt + 1 < nk) { fill(kt + 1); CP_WAIT(1); }
        else             { CP_WAIT(0); }
        __syncthreads();
        unsigned bb = sbase + (kt & 1) * BUF_BYTES;
        unsigned Aa = bb, Ba = bb + A_BYTES;
        #pragma unroll
        for (int kk = 0; kk < 2; kk++) {
            int kc = csel + kk * 16;
            unsigned af[2][4], bf[4][4];
            #pragma unroll
            for (int mt = 0; mt < 2; mt++) {
                unsigned off = (unsigned)((warpM + mt * 16 + rsel) * ASTRIDE + kc) * 2;
                ldm_x4(af[mt][0], af[mt][1], af[mt][2], af[mt][3], Aa + off);
            }
            #pragma unroll
            for (int np = 0; np < 4; np++) {
                unsigned off = (unsigned)((kk * 16 + bkr) * PSTR + warpN + np * 16 + bpc) * 2;
                ldm_x4_t(bf[np][0], bf[np][1], bf[np][2], bf[np][3], Ba + off);
            }
            #pragma unroll
            for (int mt = 0; mt < 2; mt++)
                #pragma unroll
                for (int nt = 0; nt < 8; nt++) {
                    int np = nt >> 1, hf = nt & 1;
                    mma_f16(acc[mt][nt], af[mt], bf[np][hf], bf[np][hf + 2]);
                }
        }
        __syncthreads();
    }

    if (HALF_OUT) {
        // direct fragment -> global half2 stores (no smem staging)
        __half* Y = (__half*)Yv;
        #pragma unroll
        for (int mt = 0; mt < 2; mt++)
            #pragma unroll
            for (int nt = 0; nt < 8; nt++) {
                int r0 = o0 + warpM + mt * 16 + (lane >> 2);
                int pc = p0 + warpN + nt * 8 + (lane & 3) * 2;
                __half2 h0 = __floats2half2_rn(acc[mt][nt][0], acc[mt][nt][1]);
                __half2 h1 = __floats2half2_rn(acc[mt][nt][2], acc[mt][nt][3]);
                if (r0 < O)     *(__half2*)(Y + ((size_t)b * O + r0) * HWN + pc) = h0;
                if (r0 + 8 < O) *(__half2*)(Y + ((size_t)b * O + r0 + 8) * HWN + pc) = h1;
            }
        return;
    }

    float* Ysm = (float*)dsm;
    #pragma unroll
    for (int mt = 0; mt < 2; mt++)
        #pragma unroll
        for (int nt = 0; nt < 8; nt++) {
            int r0 = warpM + mt * 16 + (lane >> 2);
            int cc = warpN + nt * 8 + (lane & 3) * 2;
            Ysm[r0 * YSTRIDE + cc]           = acc[mt][nt][0];
            Ysm[r0 * YSTRIDE + cc + 1]       = acc[mt][nt][1];
            Ysm[(r0 + 8) * YSTRIDE + cc]     = acc[mt][nt][2];
            Ysm[(r0 + 8) * YSTRIDE + cc + 1] = acc[mt][nt][3];
        }
    __syncthreads();
    #pragma unroll
    for (int i = 0; i < 16; i++) {
        int idx = i * 256 + t;
        int row = idx >> 5, c4 = (idx & 31) * 4;
        int o = o0 + row;
        if (o < O) {
            float4 v = *(float4*)(Ysm + row * YSTRIDE + c4);
            size_t goff = ((size_t)b * O + o) * HWN + p0 + c4;
            if (RESID) {
                float4 q = *(const float4*)(R + goff);
                v.x += q.x; v.y += q.y; v.z += q.z; v.w += q.w;
            }
            *(float4*)((float*)Yv + goff) = v;
        }
    }
}

template<bool RESID, bool HALF_OUT>
__global__ __launch_bounds__(256)
void gemm_mma(const __half* __restrict__ W, const __half* __restrict__ X,
              const float* __restrict__ R, void* __restrict__ Y, int O, int Cpad) {
    extern __shared__ char dsm[];
    int b = blockIdx.z;
    gemm_body<RESID, HALF_OUT>(W,
                     X + (size_t)b * Cpad * HWN + blockIdx.x * 128,
                     R, Y, O, Cpad, b, blockIdx.x * 128, blockIdx.y * 128, dsm);
}

__global__ __launch_bounds__(256)
void gemm3(void) {
    extern __shared__ char dsm[];
    int z = blockIdx.z, which = z >> 2, b = z & 3;
    const __half *W, *X;
    __half* Y;
    if (which == 0)      { W = g_wh + OFF_Q;  X = xt_a;  Y = g_qpre; }
    else if (which == 1) { W = g_wh + OFF_K1; X = xt_k1; Y = g_kv1pre; }
    else                 { W = g_wh + OFF_K2; X = xt_k2; Y = g_kv2pre; }
    gemm_body<false, true>(W,
                     X + (size_t)b * CC * HWN + blockIdx.x * 128,
                     nullptr, Y, C2, CC, b, blockIdx.x * 128, blockIdx.y * 128, dsm);
}

// ---------------- LayerNorm -> fp16 [c][p] ----------------------------------
__device__ __forceinline__
void ln_body(const float* __restrict__ X, const float* __restrict__ w,
             const float* __restrict__ bia, __half* __restrict__ Hx,
             int b, int pblk) {
    __shared__ float2 red[256];
    int px = threadIdx.x & 63, cg = threadIdx.x >> 6;
    int p = pblk * 64 + px;
    const float* xp = X + ((size_t)b * CC + (size_t)cg * 48) * HWN + p;
    float v[48];
    float s = 0.f, q = 0.f;
    #pragma unroll
    for (int i = 0; i < 48; i++) {
        float t = xp[(size_t)i * HWN];
        v[i] = t; s += t; q += t * t;
    }
    red[threadIdx.x] = make_float2(s, q);
    __syncthreads();
    float2 r0 = red[px], r1 = red[64 + px], r2 = red[128 + px], r3 = red[192 + px];
    float st = r0.x + r1.x + r2.x + r3.x;
    float qt = r0.y + r1.y + r2.y + r3.y;
    const float invc = 1.f / CC;
    float mu = st * invc;
    float iv = rsqrtf(fmaxf(qt * invc - mu * mu, 0.f) + EPSLN);
    size_t base = ((size_t)b * CC + (size_t)cg * 48) * HWN + p;
    #pragma unroll
    for (int i = 0; i < 48; i++) {
        int c = cg * 48 + i;
        float o = (v[i] - mu) * iv * w[c] + bia[c];
        Hx[base + (size_t)i * HWN] = __float2half_rn(o);
    }
}

__global__ __launch_bounds__(256)
void ln3(const float* __restrict__ X0, const float* __restrict__ X1, const float* __restrict__ X2,
         const float* __restrict__ w0, const float* __restrict__ b0,
         const float* __restrict__ w1, const float* __restrict__ b1,
         const float* __restrict__ w2, const float* __restrict__ b2) {
    int which = blockIdx.z;
    const float *X, *w, *bia;
    __half* Hx;
    if (which == 0)      { X = X0; w = w0; bia = b0; Hx = xt_a; }
    else if (which == 1) { X = X1; w = w1; bia = b1; Hx = xt_k1; }
    else                 { X = X2; w = w2; bia = b2; Hx = xt_k2; }
    ln_body(X, w, bia, Hx, blockIdx.y, blockIdx.x);
}

__global__ __launch_bounds__(256)
void ln_cp(const float* __restrict__ X, const float* __restrict__ w,
           const float* __restrict__ bia, __half* __restrict__ Hx) {
    ln_body(X, w, bia, Hx, blockIdx.y, blockIdx.x);
}

// ---------------- depthwise 3x3 core, 8 px/thread ----------------
__device__ __forceinline__ void dw_core_h8(const __half* __restrict__ xp, const float* kv,
                                           int h, int wcol, float* a) {
    #pragma unroll
    for (int dy = -1; dy <= 1; dy++) {
        int hh = h + dy;
        if (hh < 0 || hh >= HIMG) continue;
        const __half* r = xp + hh * HIMG + wcol;
        uint4 u = *(const uint4*)r;
        __half2 h0 = *(__half2*)&u.x, h1 = *(__half2*)&u.y;
        __half2 h2 = *(__half2*)&u.z, h3 = *(__half2*)&u.w;
        float m[8];
        m[0] = __low2float(h0); m[1] = __high2float(h0);
        m[2] = __low2float(h1); m[3] = __high2float(h1);
        m[4] = __low2float(h2); m[5] = __high2float(h2);
        m[6] = __low2float(h3); m[7] = __high2float(h3);
        float lf = (wcol > 0)   ? __half2float(r[-1]) : 0.f;
        float rt = (wcol < 120) ? __half2float(r[8])  : 0.f;
        const float* k = kv + (dy + 1) * 3;
        a[0] += k[0]*lf + k[1]*m[0] + k[2]*m[1];
        #pragma unroll
        for (int j = 1; j < 7; j++)
            a[j] += k[0]*m[j-1] + k[1]*m[j] + k[2]*m[j+1];
        a[7] += k[0]*m[6] + k[1]*m[7] + k[2]*rt;
    }
}

// merged q-grouped + kv1 + kv2 depthwise, fused norm sumsq (8 px/thread)
__global__ __launch_bounds__(256)
void dwconv_all(const float* __restrict__ Wq, const float* __restrict__ Wt1,
                const float* __restrict__ Wt2) {
    __shared__ float red[8];
    int b = blockIdx.z, cc = blockIdx.y;
    int t = threadIdx.x, lane = t & 31, wid = t >> 5;
    int p = (blockIdx.x * 256 + t) * 8;
    int h = p >> 7, wcol = p & 127;
    float a[8];
    #pragma unroll
    for (int i = 0; i < 8; i++) a[i] = 0.f;
    bool want = false; int nm = 0, slot = 0;
    if (cc < C2) {
        int o = cc;
        int i0 = (o >> 1) << 1;
        const __half* x0 = g_qpre + ((size_t)b * C2 + i0) * HWN;
        float kv[18];
        #pragma unroll
        for (int i = 0; i < 18; i++) kv[i] = Wq[(size_t)o * 18 + i];
        dw_core_h8(x0, kv, h, wcol, a);
        dw_core_h8(x0 + HWN, kv + 9, h, wcol, a);
        st_half8(g_q + ((size_t)b * C2 + o) * HWN + p, a);
        int br = o / CC, rem = o % CC;
        want = true; nm = b * 8 + br * 4 + rem / CHD; slot = rem % CHD;
    } else {
        const __half* X; const float* Wt; __half* Y; int c, br;
        if (cc < 2 * C2) { X = g_kv1pre; Wt = Wt1; Y = g_kv1; c = cc - C2;     br = 0; }
        else             { X = g_kv2pre; Wt = Wt2; Y = g_kv2; c = cc - 2 * C2; br = 1; }
        const __half* xp = X + ((size_t)b * C2 + c) * HWN;
        float kv[9];
        #pragma unroll
        for (int i = 0; i < 9; i++) kv[i] = Wt[(size_t)c * 9 + i];
        dw_core_h8(xp, kv, h, wcol, a);
        st_half8(Y + ((size_t)b * C2 + c) * HWN + p, a);
        if (c < CC) { want = true; nm = b * 8 + br * 4 + c / CHD; slot = CHD + c % CHD; }
    }
    if (want) {
        float ss = 0.f;
        #pragma unroll
        for (int i = 0; i < 8; i++) ss += a[i] * a[i];
        #pragma unroll
        for (int st = 16; st > 0; st >>= 1)
            ss += __shfl_xor_sync(0xffffffffu, ss, st);
        if (lane == 0) red[wid] = ss;
        __syncthreads();
        if (t == 0) {
            float tot = 0.f;
            #pragma unroll
            for (int i = 0; i < 8; i++) tot += red[i];
            atomicAdd(&g_nrm[nm * 96 + slot], tot);
        }
    }
}

// ---------------- fused FFN dwconv + gated gelu -> fp16, 8 px/thread --------
__global__ __launch_bounds__(256)
void dwgelu(const float* __restrict__ Wt, __half* __restrict__ Hx) {
    int b = blockIdx.z, c = blockIdx.y;
    int p = (blockIdx.x * 256 + threadIdx.x) * 8;
    size_t oidx = ((size_t)b * GGPAD + c) * HWN + p;
    if (c >= HIDC) {
        uint4 z = make_uint4(0, 0, 0, 0);
        *(uint4*)(Hx + oidx) = z;
        return;
    }
    int h = p >> 7, wcol = p & 127;
    float va[8], vg[8];
    #pragma unroll
    for (int i = 0; i < 8; i++) { va[i] = 0.f; vg[i] = 0.f; }
    {
        const __half* xp = g_h + ((size_t)b * HID2 + c) * HWN;
        float kv[9];
        #pragma unroll
        for (int i = 0; i < 9; i++) kv[i] = Wt[(size_t)c * 9 + i];
        dw_core_h8(xp, kv, h, wcol, va);
    }
    {
        int ch = c + HIDC;
        const __half* xp = g_h + ((size_t)b * HID2 + ch) * HWN;
        float kv[9];
        #pragma unroll
        for (int i = 0; i < 9; i++) kv[i] = Wt[(size_t)ch * 9 + i];
        dw_core_h8(xp, kv, h, wcol, vg);
    }
    float o[8];
    #pragma unroll
    for (int j = 0; j < 8; j++) {
        float aa = va[j];
        float ge = 0.5f * aa * (1.f + erff(aa * 0.70710678118654752f));
        o[j] = ge * vg[j];
    }
    st_half8(Hx + oidx, o);
}

// ---------------- attention ----------------
__global__ void zero_attn() {
    int i = blockIdx.x * 256 + threadIdx.x;
    if (i < 32 * CHD * CHD) g_S[i] = 0.f;
    if (i < 32 * 96) g_nrm[i] = 0.f;
}

#define QKS 136
__global__ __launch_bounds__(256)
void skernel() {
    __shared__ __half Qs[CHD * QKS];
    __shared__ __half Ks[CHD * QKS];
    __shared__ float Ssm[CHD * 49];
    int m = blockIdx.x, ns = blockIdx.y;
    int b = m >> 3, br = (m >> 2) & 1, hh = m & 3;
    const __half* qb = g_q + ((size_t)b * C2 + br * CC + hh * CHD) * HWN;
    const __half* kb = (br ? g_kv2 : g_kv1) + ((size_t)b * C2 + hh * CHD) * HWN;
    int t = threadIdx.x, lane = t & 31, wid = t >> 5;
    for (int i = t; i < CHD * 49; i += 256) Ssm[i] = 0.f;
    unsigned qsb = smem_u32(Qs), ksb = smem_u32(Ks);

    float acc[3][6][4];
    #pragma unroll
    for (int i = 0; i < 3; i++)
        #pragma unroll
        for (int j = 0; j < 6; j++)
            #pragma unroll
            for (int k = 0; k < 4; k++) acc[i][j][k] = 0.f;

    int rsel = lane & 15, csel = (lane >> 4) * 8;
    int bnr = (lane & 7) + ((lane >> 4) & 1) * 8;
    int bkc = ((lane >> 3) & 1) * 8;
    int kc = wid * 16;
    int nbeg = ns * 2048;

    for (int ch = 0; ch < 16; ch++) {
        int n0 = nbeg + ch * 128;
        __syncthreads();
        #pragma unroll
        for (int j = 0; j < 6; j++) {
            int ci = j * 256 + t;
            int mtx = (ci >= 768);
            int loc = ci - mtx * 768;
            int row = loc >> 4, g = loc & 15;
            const __half* src = (mtx ? kb : qb) + (size_t)row * HWN + n0 + g * 8;
            unsigned dst = (mtx ? ksb : qsb) + (unsigned)(row * QKS + g * 8) * 2;
            CP_ASYNC16(dst, src);
        }
        CP_COMMIT(); CP_WAIT(0);
        __syncthreads();
        unsigned af[3][4], bf[3][4];
        #pragma unroll
        for (int mt = 0; mt < 3; mt++) {
            unsigned off = (unsigned)((mt * 16 + rsel) * QKS + kc + csel) * 2;
            ldm_x4(af[mt][0], af[mt][1], af[mt][2], af[mt][3], qsb + off);
        }
        #pragma unroll
        for (int nf = 0; nf < 3; nf++) {
            unsigned off = (unsigned)((nf * 16 + bnr) * QKS + kc + bkc) * 2;
            ldm_x4(bf[nf][0], bf[nf][1], bf[nf][2], bf[nf][3], ksb + off);
        }
        #pragma unroll
        for (int mt = 0; mt < 3; mt++)
            #pragma unroll
            for (int nf = 0; nf < 3; nf++)
                #pragma unroll
                for (int hf = 0; hf < 2; hf++)
                    mma_f16(acc[mt][nf * 2 + hf], af[mt], bf[nf][2 * hf], bf[nf][2 * hf + 1]);
    }
    __syncthreads();
    #pragma unroll
    for (int mt = 0; mt < 3; mt++)
        #pragma unroll
        for (int nt = 0; nt < 6; nt++) {
            int r0 = mt * 16 + (lane >> 2);
            int cl = nt * 8 + (lane & 3) * 2;
            atomicAdd(&Ssm[r0 * 49 + cl],           acc[mt][nt][0]);
            atomicAdd(&Ssm[r0 * 49 + cl + 1],       acc[mt][nt][1]);
            atomicAdd(&Ssm[(r0 + 8) * 49 + cl],     acc[mt][nt][2]);
            atomicAdd(&Ssm[(r0 + 8) * 49 + cl + 1], acc[mt][nt][3]);
        }
    __syncthreads();
    for (int i = t; i < CHD * CHD; i += 256) {
        int r = i / CHD, c = i % CHD;
        atomicAdd(&g_S[(size_t)m * CHD * CHD + i], Ssm[r * 49 + c]);
    }
}

__global__ void softmax_kernel(const float* __restrict__ t1, const float* __restrict__ t2) {
    int m = blockIdx.x;
    int c = threadIdx.x;
    __shared__ float nk[CHD];
    if (c < CHD) nk[c] = fmaxf(sqrtf(g_nrm[m * 96 + CHD + c]), 1e-12f);
    __syncthreads();
    if (c >= CHD) return;
    int br = (m >> 2) & 1, hh = m & 3;
    float tmp = (br ? t2 : t1)[hh];
    float nq = fmaxf(sqrtf(g_nrm[m * 96 + c]), 1e-12f);
    float* row = g_S + (size_t)m * CHD * CHD + c * CHD;
    float vals[CHD];
    float mx = -1e30f;
    #pragma unroll
    for (int d = 0; d < CHD; d++) {
        float v = row[d] / (nq * nk[d]) * tmp;
        vals[d] = v;
        mx = fmaxf(mx, v);
    }
    float sum = 0.f;
    #pragma unroll
    for (int d = 0; d < CHD; d++) { vals[d] = __expf(vals[d] - mx); sum += vals[d]; }
    float inv = 1.f / sum;
    #pragma unroll
    for (int d = 0; d < CHD; d++) row[d] = vals[d] * inv;
}

#define AVS 56
#define VVS 264
__global__ __launch_bounds__(256)
void av_mma() {
    __shared__ __half As[CHD * AVS];
    __shared__ __half Vs[CHD * VVS];
    int m = blockIdx.x;
    int b = m >> 3, br = (m >> 2) & 1, hh = m & 3;
    int t = threadIdx.x, lane = t & 31, wid = t >> 5;
    for (int i = t; i < CHD * CHD; i += 256) {
        int r = i / CHD, c = i % CHD;
        As[r * AVS + c] = __float2half_rn(g_S[(size_t)m * CHD * CHD + i]);
    }
    const __half* vb = (br ? g_kv2 : g_kv1) + ((size_t)b * C2 + CC + hh * CHD) * HWN;
    int p0 = blockIdx.y * 256;
    unsigned asb = smem_u32(As), vsb = smem_u32(Vs);
    #pragma unroll
    for (int j = 0; j < 6; j++) {
        int ci = j * 256 + t;
        int row = ci >> 5, g = ci & 31;
        CP_ASYNC16(vsb + (unsigned)(row * VVS + g * 8) * 2,
                   vb + (size_t)row * HWN + p0 + g * 8);
    }
    CP_COMMIT(); CP_WAIT(0);
    __syncthreads();

    int rsel = lane & 15, csel = (lane >> 4) * 8;
    int bkr = (lane & 7) + ((lane >> 4) & 1) * 8;
    int bpc = ((lane >> 3) & 1) * 8;
    int warpN = wid * 32;

    float acc[3][4][4];
    #pragma unroll
    for (int i = 0; i < 3; i++)
        #pragma unroll
        for (int j = 0; j < 4; j++)
            #pragma unroll
            for (int k = 0; k < 4; k++) acc[i][j][k] = 0.f;

    #pragma unroll
    for (int kt = 0; kt < 3; kt++) {
        unsigned af[3][4], bf[2][4];
        #pragma unroll
        for (int mt = 0; mt < 3; mt++) {
            unsigned off = (unsigned)((mt * 16 + rsel) * AVS + kt * 16 + csel) * 2;
            ldm_x4(af[mt][0], af[mt][1], af[mt][2], af[mt][3], asb + off);
        }
        #pragma unroll
        for (int np = 0; np < 2; np++) {
            unsigned off = (unsigned)((kt * 16 + bkr) * VVS + warpN + np * 16 + bpc) * 2;
            ldm_x4_t(bf[np][0], bf[np][1], bf[np][2], bf[np][3], vsb + off);
        }
        #pragma unroll
        for (int mt = 0; mt < 3; mt++)
            #pragma unroll
            for (int nt = 0; nt < 4; nt++) {
                int np = nt >> 1, hf = nt & 1;
                mma_f16(acc[mt][nt], af[mt], bf[np][hf], bf[np][hf + 2]);
            }
    }
    int off = br * CC + hh * CHD;
    #pragma unroll
    for (int mt = 0; mt < 3; mt++)
        #pragma unroll
        for (int nt = 0; nt < 4; nt++) {
            int r0 = off + mt * 16 + (lane >> 2);
            int pc = p0 + warpN + nt * 8 + (lane & 3) * 2;
            __half2 h0 = __floats2half2_rn(acc[mt][nt][0], acc[mt][nt][1]);
            __half2 h1 = __floats2half2_rn(acc[mt][nt][2], acc[mt][nt][3]);
            *(__half2*)(xt_ao + ((size_t)b * C2 + r0) * HWN + pc) = h0;
            *(__half2*)(xt_ao + ((size_t)b * C2 + r0 + 8) * HWN + pc) = h1;
        }
}

// ---------------- launch ----------------
extern "C" void kernel_launch(void* const* d_in, const int* in_sizes, int n_in,
                              void* d_out, int out_size) {
    const float* x       = (const float*)d_in[0];
    const float* kv1in   = (const float*)d_in[1];
    const float* kv2in   = (const float*)d_in[2];
    const float* n1w = (const float*)d_in[3];  const float* n1b = (const float*)d_in[4];
    const float* nk1w = (const float*)d_in[5]; const float* nk1b = (const float*)d_in[6];
    const float* nk2w = (const float*)d_in[7]; const float* nk2b = (const float*)d_in[8];
    const float* n2w = (const float*)d_in[9];  const float* n2b = (const float*)d_in[10];
    const float* q_w   = (const float*)d_in[11];
    const float* kv1_w = (const float*)d_in[12];
    const float* kv2_w = (const float*)d_in[13];
    const float* q_dw  = (const float*)d_in[14];
    const float* kv1_dw= (const float*)d_in[15];
    const float* kv2_dw= (const float*)d_in[16];
    const float* proj_w= (const float*)d_in[17];
    const float* temp1 = (const float*)d_in[18];
    const float* temp2 = (const float*)d_in[19];
    const float* pin_w = (const float*)d_in[20];
    const float* dw_w  = (const float*)d_in[21];
    const float* pout_w= (const float*)d_in[22];
    float* out = (float*)d_out;

    cudaFuncSetAttribute((const void*)gemm_mma<false, true>,  cudaFuncAttributeMaxDynamicSharedMemorySize, GEMM_SMEM);
    cudaFuncSetAttribute((const void*)gemm_mma<true, false>,  cudaFuncAttributeMaxDynamicSharedMemorySize, GEMM_SMEM);
    cudaFuncSetAttribute((const void*)gemm3, cudaFuncAttributeMaxDynamicSharedMemorySize, GEMM_SMEM);

    float *p_x2;
    cudaGetSymbolAddress((void**)&p_x2, g_x2);
    __half *p_h, *wh, *pa, *pao, *pgg;
    cudaGetSymbolAddress((void**)&p_h, g_h);
    cudaGetSymbolAddress((void**)&wh, g_wh);
    cudaGetSymbolAddress((void**)&pa, xt_a);
    cudaGetSymbolAddress((void**)&pao, xt_ao);
    cudaGetSymbolAddress((void**)&pgg, xt_gg);

    // 1: weights
    wconv_all<<<2556, 64>>>(q_w, kv1_w, kv2_w, proj_w, pin_w, pout_w);
    // 2: merged LNs
    ln3<<<dim3(HWN / 64, BB, 3), 256>>>(x, kv1in, kv2in, n1w, n1b, nk1w, nk1b, nk2w, nk2b);
    // 3: zero attn accumulators
    zero_attn<<<300, 256>>>();
    // 4: merged q/kv1/kv2 GEMM
    gemm3<<<dim3(HWN / 128, 3, 12), 256, GEMM_SMEM_H>>>();
    // 5: merged dwconvs (+ fused attention norms), 8 px/thread
    dim3 dAll(HWN / 2048, 3 * C2, BB);
    dwconv_all<<<dAll, 256>>>(q_dw, kv1_dw, kv2_dw);
    // 6-8: attention on HMMA
    skernel<<<dim3(32, 8), 256>>>();
    softmax_kernel<<<32, 64>>>(temp1, temp2);
    av_mma<<<dim3(32, HWN / 256), 256>>>();
    // 9: proj + residual x -> g_x2 (fp32)
    dim3 gP(HWN / 128, 2, BB);
    gemm_mma<true, false><<<gP, 256, GEMM_SMEM>>>(wh + OFF_P, pao, x, p_x2, 192, 384);
    // 10: FFN LN
    dim3 lnG(HWN / 64, BB);
    ln_cp<<<lnG, 256>>>(p_x2, n2w, n2b, pa);
    // 11: pin GEMM -> g_h (fp16)
    dim3 gIn(HWN / 128, 8, BB);
    gemm_mma<false, true><<<gIn, 256, GEMM_SMEM_H>>>(wh + OFF_PIN, pa, nullptr, p_h, 1020, 192);
    // 12: fused dwconv+gelu, 8 px/thread
    dim3 dGG(HWN / 2048, GGPAD, BB);
    dwgelu<<<dGG, 256>>>(dw_w, pgg);
    // 13: pout GEMM + residual
    gemm_mma<true, false><<<gP, 256, GEMM_SMEM>>>(wh + OFF_PO, pgg, p_x2, out, 192, 512);
}

// round 14
// speedup vs baseline: 1.4046x; 1.0215x over previous
#include <cuda_runtime.h>
#include <cuda_fp16.h>
#include <math.h>

#define BB 4
#define CC 192
#define C2 384
#define HWN 16384
#define HIMG 128
#define CHD 48
#define HIDC 510
#define HID2 1020
#define GGPAD 512
#define EPSLN 1e-5f

__device__ __forceinline__ unsigned smem_u32(const void* p) {
    unsigned a;
    asm("{ .reg .u64 t; cvta.to.shared.u64 t, %1; cvt.u32.u64 %0, t; }"
        : "=r"(a) : "l"(p));
    return a;
}
#define CP_ASYNC16(dst, src) \
    asm volatile("cp.async.cg.shared.global [%0], [%1], 16;" :: "r"(dst), "l"(src))
#define CP_COMMIT() asm volatile("cp.async.commit_group;" ::: "memory")
#define CP_WAIT(n)  asm volatile("cp.async.wait_group %0;" :: "n"(n) : "memory")

__device__ __forceinline__ void ldm_x4(unsigned& r0, unsigned& r1, unsigned& r2, unsigned& r3,
                                       unsigned addr) {
    asm volatile("ldmatrix.sync.aligned.m8n8.x4.shared.b16 {%0,%1,%2,%3}, [%4];"
        : "=r"(r0), "=r"(r1), "=r"(r2), "=r"(r3) : "r"(addr));
}
__device__ __forceinline__ void ldm_x4_t(unsigned& r0, unsigned& r1, unsigned& r2, unsigned& r3,
                                         unsigned addr) {
    asm volatile("ldmatrix.sync.aligned.m8n8.x4.trans.shared.b16 {%0,%1,%2,%3}, [%4];"
        : "=r"(r0), "=r"(r1), "=r"(r2), "=r"(r3) : "r"(addr));
}
__device__ __forceinline__ void mma_f16(float* d, const unsigned* a, unsigned b0, unsigned b1) {
    asm volatile("mma.sync.aligned.m16n8k16.row.col.f32.f16.f16.f32 "
        "{%0,%1,%2,%3}, {%4,%5,%6,%7}, {%8,%9}, {%0,%1,%2,%3};"
        : "+f"(d[0]), "+f"(d[1]), "+f"(d[2]), "+f"(d[3])
        : "r"(a[0]), "r"(a[1]), "r"(a[2]), "r"(a[3]), "r"(b0), "r"(b1));
}

// ---------------- scratch ----------------
__device__ __align__(16) __half g_qpre [BB*C2*HWN];
__device__ __align__(16) __half g_kv1pre[BB*C2*HWN];
__device__ __align__(16) __half g_kv2pre[BB*C2*HWN];
__device__ __align__(16) __half g_q   [BB*C2*HWN];
__device__ __align__(16) __half g_kv1 [BB*C2*HWN];
__device__ __align__(16) __half g_kv2 [BB*C2*HWN];
__device__ __align__(16) __half g_h   [BB*HID2*HWN];
__device__ __align__(16) __half g_x2h [BB*CC*HWN];
__device__ float g_S   [32*CHD*CHD];
__device__ float g_nrm [32*2*CHD];

// fp16 activations, natural layout: [b][channel][pixel]
__device__ __align__(16) __half xt_a [BB*CC*HWN];
__device__ __align__(16) __half xt_k1[BB*CC*HWN];
__device__ __align__(16) __half xt_k2[BB*CC*HWN];
__device__ __align__(16) __half xt_ao[BB*C2*HWN];
__device__ __align__(16) __half xt_gg[BB*GGPAD*HWN];
// converted weights (row-major [O][Cpad]), fp16
#define OFF_Q   0
#define OFF_K1  (384*192)
#define OFF_K2  (2*384*192)
#define OFF_P   (3*384*192)
#define OFF_PIN (3*384*192 + 192*384)
#define OFF_PO  (3*384*192 + 192*384 + 1020*192)
#define WTOT    (3*384*192 + 192*384 + 1020*192 + 192*512)
#define WPAD    (64*512)
__device__ __align__(16) __half g_wh[WTOT + WPAD];

// ---------------- fp32 -> fp16 helpers ----------------
__device__ __forceinline__ void st_half8(__half* dst, const float* a) {
    __half2 h0 = __floats2half2_rn(a[0], a[1]);
    __half2 h1 = __floats2half2_rn(a[2], a[3]);
    __half2 h2 = __floats2half2_rn(a[4], a[5]);
    __half2 h3 = __floats2half2_rn(a[6], a[7]);
    uint4 u;
    u.x = *(unsigned*)&h0; u.y = *(unsigned*)&h1;
    u.z = *(unsigned*)&h2; u.w = *(unsigned*)&h3;
    *(uint4*)dst = u;
}

// ---------------- merged weight conversion + attn-accumulator zero ----------
#define WCONV_BLKS 2556
#define ZERO_BLKS 1152
__global__ void wconv_all(const float* __restrict__ q_w, const float* __restrict__ kv1_w,
                          const float* __restrict__ kv2_w, const float* __restrict__ proj_w,
                          const float* __restrict__ pin_w, const float* __restrict__ pout_w) {
    int r = blockIdx.x;
    if (r >= WCONV_BLKS) {
        int i = (r - WCONV_BLKS) * 64 + threadIdx.x;
        if (i < 32 * CHD * CHD) g_S[i] = 0.f;
        if (i < 32 * 96) g_nrm[i] = 0.f;
        return;
    }
    const float* W; int o, Cin, Cpad, off;
    if (r < 384)        { W = q_w;    o = r;        Cin = 192; Cpad = 192; off = OFF_Q; }
    else if (r < 768)   { W = kv1_w;  o = r - 384;  Cin = 192; Cpad = 192; off = OFF_K1; }
    else if (r < 1152)  { W = kv2_w;  o = r - 768;  Cin = 192; Cpad = 192; off = OFF_K2; }
    else if (r < 1344)  { W = proj_w; o = r - 1152; Cin = 384; Cpad = 384; off = OFF_P; }
    else if (r < 2364)  { W = pin_w;  o = r - 1344; Cin = 192; Cpad = 192; off = OFF_PIN; }
    else                { W = pout_w; o = r - 2364; Cin = 510; Cpad = 512; off = OFF_PO; }
    int c0 = threadIdx.x * 8;
    if (c0 >= Cpad) return;
    float v[8];
    #pragma unroll
    for (int j = 0; j < 8; j++) {
        int c = c0 + j;
        v[j] = (c < Cin) ? W[(size_t)o * Cin + c] : 0.f;
    }
    st_half8(g_wh + (size_t)off + (size_t)o * Cpad + c0, v);
}

// ======================= HMMA GEMM body =====================================
// RMODE: 0 = no residual, 1 = fp32 residual, 2 = fp16 residual
#define BK 32
#define ASTRIDE 40
#define PSTR 136
#define A_BYTES (128 * ASTRIDE * 2)
#define B_BYTES (BK * PSTR * 2)
#define BUF_BYTES (A_BYTES + B_BYTES)
#define YSTRIDE 132
#define GEMM_SMEM (128 * YSTRIDE * 4)
#define GEMM_SMEM_H (2 * BUF_BYTES)

template<int RMODE, bool HALF_OUT>
__device__ __forceinline__
void gemm_body(const __half* __restrict__ W, const __half* __restrict__ XB,
               const void* __restrict__ Rv, void* __restrict__ Yv, int O, int Cpad,
               int b, int p0, int o0, char* dsm) {
    unsigned sbase = smem_u32(dsm);
    int t = threadIdx.x, lane = t & 31, wid = t >> 5;
    int warpM = (wid >> 1) * 32;
    int warpN = (wid & 1) * 64;
    const __half* WB = W + (size_t)o0 * Cpad;
    int nk = Cpad / BK;

    auto fill = [&](int kt) {
        int buf = kt & 1;
        unsigned bb = sbase + buf * BUF_BYTES;
        int k0 = kt * BK;
        #pragma unroll
        for (int j = 0; j < 4; j++) {
            int ci = j * 256 + t;
            if (ci < 512) {
                int row = ci >> 2, g = ci & 3;
                const __half* src = WB + (size_t)row * Cpad + k0 + g * 8;
                unsigned dst = bb + (unsigned)(row * ASTRIDE + g * 8) * 2;
                CP_ASYNC16(dst, src);
            } else {
                int m = ci - 512;
                int row = m >> 4, g = m & 15;
                const __half* src = XB + (size_t)(k0 + row) * HWN + g * 8;
                unsigned dst = bb + A_BYTES + (unsigned)(row * PSTR + g * 8) * 2;
                CP_ASYNC16(dst, src);
            }
        }
        CP_COMMIT();
    };

    float acc[2][8][4];
    #pragma unroll
    for (int i = 0; i < 2; i++)
        #pragma unroll
        for (int j = 0; j < 8; j++)
            #pragma unroll
            for (int k = 0; k < 4; k++) acc[i][j][k] = 0.f;

    fill(0);
    int rsel = lane & 15, csel = (lane >> 4) * 8;
    int bkr = (lane & 7) + ((lane >> 4) & 1) * 8;
    int bpc = ((lane >> 3) & 1) * 8;

    for (int kt = 0; kt < nk; kt++) {
        if (kt + 1 < nk) { fill(kt + 1); CP_WAIT(1); }
        else             { CP_WAIT(0); }
        __syncthreads();
        unsigned bb = sbase + (kt & 1) * BUF_BYTES;
        unsigned Aa = bb, Ba = bb + A_BYTES;
        #pragma unroll
        for (int kk = 0; kk < 2; kk++) {
            int kc = csel + kk * 16;
            unsigned af[2][4], bf[4][4];
            #pragma unroll
            for (int mt = 0; mt < 2; mt++) {
                unsigned off = (unsigned)((warpM + mt * 16 + rsel) * ASTRIDE + kc) * 2;
                ldm_x4(af[mt][0], af[mt][1], af[mt][2], af[mt][3], Aa + off);
            }
            #pragma unroll
            for (int np = 0; np < 4; np++) {
                unsigned off = (unsigned)((kk * 16 + bkr) * PSTR + warpN + np * 16 + bpc) * 2;
                ldm_x4_t(bf[np][0], bf[np][1], bf[np][2], bf[np][3], Ba + off);
            }
            #pragma unroll
            for (int mt = 0; mt < 2; mt++)
                #pragma unroll
                for (int nt = 0; nt < 8; nt++) {
                    int np = nt >> 1, hf = nt & 1;
                    mma_f16(acc[mt][nt], af[mt], bf[np][hf], bf[np][hf + 2]);
                }
        }
        __syncthreads();
    }

    if (HALF_OUT) {
        __half* Y = (__half*)Yv;
        const float* Rf = (const float*)Rv;
        #pragma unroll
        for (int mt = 0; mt < 2; mt++)
            #pragma unroll
            for (int nt = 0; nt < 8; nt++) {
                int r0 = o0 + warpM + mt * 16 + (lane >> 2);
                int pc = p0 + warpN + nt * 8 + (lane & 3) * 2;
                float v0 = acc[mt][nt][0], v1 = acc[mt][nt][1];
                float v2 = acc[mt][nt][2], v3 = acc[mt][nt][3];
                if (RMODE == 1) {
                    if (r0 < O) {
                        float2 q = *(const float2*)(Rf + ((size_t)b * O + r0) * HWN + pc);
                        v0 += q.x; v1 += q.y;
                    }
                    if (r0 + 8 < O) {
                        float2 q = *(const float2*)(Rf + ((size_t)b * O + r0 + 8) * HWN + pc);
                        v2 += q.x; v3 += q.y;
                    }
                }
                __half2 h0 = __floats2half2_rn(v0, v1);
                __half2 h1 = __floats2half2_rn(v2, v3);
                if (r0 < O)     *(__half2*)(Y + ((size_t)b * O + r0) * HWN + pc) = h0;
                if (r0 + 8 < O) *(__half2*)(Y + ((size_t)b * O + r0 + 8) * HWN + pc) = h1;
            }
        return;
    }

    float* Ysm = (float*)dsm;
    #pragma unroll
    for (int mt = 0; mt < 2; mt++)
        #pragma unroll
        for (int nt = 0; nt < 8; nt++) {
            int r0 = warpM + mt * 16 + (lane >> 2);
            int cc = warpN + nt * 8 + (lane & 3) * 2;
            Ysm[r0 * YSTRIDE + cc]           = acc[mt][nt][0];
            Ysm[r0 * YSTRIDE + cc + 1]       = acc[mt][nt][1];
            Ysm[(r0 + 8) * YSTRIDE + cc]     = acc[mt][nt][2];
            Ysm[(r0 + 8) * YSTRIDE + cc + 1] = acc[mt][nt][3];
        }
    __syncthreads();
    #pragma unroll
    for (int i = 0; i < 16; i++) {
        int idx = i * 256 + t;
        int row = idx >> 5, c4 = (idx & 31) * 4;
        int o = o0 + row;
        if (o < O) {
            float4 v = *(float4*)(Ysm + row * YSTRIDE + c4);
            size_t goff = ((size_t)b * O + o) * HWN + p0 + c4;
            if (RMODE == 1) {
                float4 q = *(const float4*)((const float*)Rv + goff);
                v.x += q.x; v.y += q.y; v.z += q.z; v.w += q.w;
            } else if (RMODE == 2) {
                const __half* Rh = (const __half*)Rv;
                __half2 q0 = *(const __half2*)(Rh + goff);
                __half2 q1 = *(const __half2*)(Rh + goff + 2);
                v.x += __low2float(q0); v.y += __high2float(q0);
                v.z += __low2float(q1); v.w += __high2float(q1);
            }
            *(float4*)((float*)Yv + goff) = v;
        }
    }
}

template<int RMODE, bool HALF_OUT>
__global__ __launch_bounds__(256)
void gemm_mma(const __half* __restrict__ W, const __half* __restrict__ X,
              const void* __restrict__ R, void* __restrict__ Y, int O, int Cpad) {
    extern __shared__ char dsm[];
    int b = blockIdx.z;
    gemm_body<RMODE, HALF_OUT>(W,
                     X + (size_t)b * Cpad * HWN + blockIdx.x * 128,
                     R, Y, O, Cpad, b, blockIdx.x * 128, blockIdx.y * 128, dsm);
}

__global__ __launch_bounds__(256)
void gemm3(void) {
    extern __shared__ char dsm[];
    int z = blockIdx.z, which = z >> 2, b = z & 3;
    const __half *W, *X;
    __half* Y;
    if (which == 0)      { W = g_wh + OFF_Q;  X = xt_a;  Y = g_qpre; }
    else if (which == 1) { W = g_wh + OFF_K1; X = xt_k1; Y = g_kv1pre; }
    else                 { W = g_wh + OFF_K2; X = xt_k2; Y = g_kv2pre; }
    gemm_body<0, true>(W,
                     X + (size_t)b * CC * HWN + blockIdx.x * 128,
                     nullptr, Y, C2, CC, b, blockIdx.x * 128, blockIdx.y * 128, dsm);
}

// ---------------- LayerNorm -> fp16 [c][p] (fp32 input) ---------------------
__device__ __forceinline__
void ln_body(const float* __restrict__ X, const float* __restrict__ w,
             const float* __restrict__ bia, __half* __restrict__ Hx,
             int b, int pblk) {
    __shared__ float2 red[256];
    int px = threadIdx.x & 63, cg = threadIdx.x >> 6;
    int p = pblk * 64 + px;
    const float* xp = X + ((size_t)b * CC + (size_t)cg * 48) * HWN + p;
    float v[48];
    float s = 0.f, q = 0.f;
    #pragma unroll
    for (int i = 0; i < 48; i++) {
        float t = xp[(size_t)i * HWN];
        v[i] = t; s += t; q += t * t;
    }
    red[threadIdx.x] = make_float2(s, q);
    __syncthreads();
    float2 r0 = red[px], r1 = red[64 + px], r2 = red[128 + px], r3 = red[192 + px];
    float st = r0.x + r1.x + r2.x + r3.x;
    float qt = r0.y + r1.y + r2.y + r3.y;
    const float invc = 1.f / CC;
    float mu = st * invc;
    float iv = rsqrtf(fmaxf(qt * invc - mu * mu, 0.f) + EPSLN);
    size_t base = ((size_t)b * CC + (size_t)cg * 48) * HWN + p;
    #pragma unroll
    for (int i = 0; i < 48; i++) {
        int c = cg * 48 + i;
        float o = (v[i] - mu) * iv * w[c] + bia[c];
        Hx[base + (size_t)i * HWN] = __float2half_rn(o);
    }
}

__global__ __launch_bounds__(256)
void ln3(const float* __restrict__ X0, const float* __restrict__ X1, const float* __restrict__ X2,
         const float* __restrict__ w0, const float* __restrict__ b0,
         const float* __restrict__ w1, const float* __restrict__ b1,
         const float* __restrict__ w2, const float* __restrict__ b2) {
    int which = blockIdx.z;
    const float *X, *w, *bia;
    __half* Hx;
    if (which == 0)      { X = X0; w = w0; bia = b0; Hx = xt_a; }
    else if (which == 1) { X = X1; w = w1; bia = b1; Hx = xt_k1; }
    else                 { X = X2; w = w2; bia = b2; Hx = xt_k2; }
    ln_body(X, w, bia, Hx, blockIdx.y, blockIdx.x);
}

// fp16-input LN (for x2)
__global__ __launch_bounds__(256)
void ln_h(const __half* __restrict__ X, const float* __restrict__ w,
          const float* __restrict__ bia, __half* __restrict__ Hx) {
    __shared__ float2 red[256];
    int b = blockIdx.y, pblk = blockIdx.x;
    int px = threadIdx.x & 63, cg = threadIdx.x >> 6;
    int p = pblk * 64 + px;
    const __half* xp = X + ((size_t)b * CC + (size_t)cg * 48) * HWN + p;
    float v[48];
    float s = 0.f, q = 0.f;
    #pragma unroll
    for (int i = 0; i < 48; i++) {
        float t = __half2float(xp[(size_t)i * HWN]);
        v[i] = t; s += t; q += t * t;
    }
    red[threadIdx.x] = make_float2(s, q);
    __syncthreads();
    float2 r0 = red[px], r1 = red[64 + px], r2 = red[128 + px], r3 = red[192 + px];
    float st = r0.x + r1.x + r2.x + r3.x;
    float qt = r0.y + r1.y + r2.y + r3.y;
    const float invc = 1.f / CC;
    float mu = st * invc;
    float iv = rsqrtf(fmaxf(qt * invc - mu * mu, 0.f) + EPSLN);
    size_t base = ((size_t)b * CC + (size_t)cg * 48) * HWN + p;
    #pragma unroll
    for (int i = 0; i < 48; i++) {
        int c = cg * 48 + i;
        float o = (v[i] - mu) * iv * w[c] + bia[c];
        Hx[base + (size_t)i * HWN] = __float2half_rn(o);
    }
}

// ---------------- depthwise 3x3 core, 8 px/thread ----------------
__device__ __forceinline__ void dw_core_h8(const __half* __restrict__ xp, const float* kv,
                                           int h, int wcol, float* a) {
    #pragma unroll
    for (int dy = -1; dy <= 1; dy++) {
        int hh = h + dy;
        if (hh < 0 || hh >= HIMG) continue;
        const __half* r = xp + hh * HIMG + wcol;
        uint4 u = *(const uint4*)r;
        __half2 h0 = *(__half2*)&u.x, h1 = *(__half2*)&u.y;
        __half2 h2 = *(__half2*)&u.z, h3 = *(__half2*)&u.w;
        float m[8];
        m[0] = __low2float(h0); m[1] = __high2float(h0);
        m[2] = __low2float(h1); m[3] = __high2float(h1);
        m[4] = __low2float(h2); m[5] = __high2float(h2);
        m[6] = __low2float(h3); m[7] = __high2float(h3);
        float lf = (wcol > 0)   ? __half2float(r[-1]) : 0.f;
        float rt = (wcol < 120) ? __half2float(r[8])  : 0.f;
        const float* k = kv + (dy + 1) * 3;
        a[0] += k[0]*lf + k[1]*m[0] + k[2]*m[1];
        #pragma unroll
        for (int j = 1; j < 7; j++)
            a[j] += k[0]*m[j-1] + k[1]*m[j] + k[2]*m[j+1];
        a[7] += k[0]*m[6] + k[1]*m[7] + k[2]*rt;
    }
}

// merged q-grouped + kv1 + kv2 depthwise, fused norm sumsq (8 px/thread)
__global__ __launch_bounds__(256)
void dwconv_all(const float* __restrict__ Wq, const float* __restrict__ Wt1,
                const float* __restrict__ Wt2) {
    __shared__ float red[8];
    int b = blockIdx.z, cc = blockIdx.y;
    int t = threadIdx.x, lane = t & 31, wid = t >> 5;
    int p = (blockIdx.x * 256 + t) * 8;
    int h = p >> 7, wcol = p & 127;
    float a[8];
    #pragma unroll
    for (int i = 0; i < 8; i++) a[i] = 0.f;
    bool want = false; int nm = 0, slot = 0;
    if (cc < C2) {
        int o = cc;
        int i0 = (o >> 1) << 1;
        const __half* x0 = g_qpre + ((size_t)b * C2 + i0) * HWN;
        float kv[18];
        #pragma unroll
        for (int i = 0; i < 18; i++) kv[i] = Wq[(size_t)o * 18 + i];
        dw_core_h8(x0, kv, h, wcol, a);
        dw_core_h8(x0 + HWN, kv + 9, h, wcol, a);
        st_half8(g_q + ((size_t)b * C2 + o) * HWN + p, a);
        int br = o / CC, rem = o % CC;
        want = true; nm = b * 8 + br * 4 + rem / CHD; slot = rem % CHD;
    } else {
        const __half* X; const float* Wt; __half* Y; int c, br;
        if (cc < 2 * C2) { X = g_kv1pre; Wt = Wt1; Y = g_kv1; c = cc - C2;     br = 0; }
        else             { X = g_kv2pre; Wt = Wt2; Y = g_kv2; c = cc - 2 * C2; br = 1; }
        const __half* xp = X + ((size_t)b * C2 + c) * HWN;
        float kv[9];
        #pragma unroll
        for (int i = 0; i < 9; i++) kv[i] = Wt[(size_t)c * 9 + i];
        dw_core_h8(xp, kv, h, wcol, a);
        st_half8(Y + ((size_t)b * C2 + c) * HWN + p, a);
        if (c < CC) { want = true; nm = b * 8 + br * 4 + c / CHD; slot = CHD + c % CHD; }
    }
    if (want) {
        float ss = 0.f;
        #pragma unroll
        for (int i = 0; i < 8; i++) ss += a[i] * a[i];
        #pragma unroll
        for (int st = 16; st > 0; st >>= 1)
            ss += __shfl_xor_sync(0xffffffffu, ss, st);
        if (lane == 0) red[wid] = ss;
        __syncthreads();
        if (t == 0) {
            float tot = 0.f;
            #pragma unroll
            for (int i = 0; i < 8; i++) tot += red[i];
            atomicAdd(&g_nrm[nm * 96 + slot], tot);
        }
    }
}

// ---------------- fused FFN dwconv + gated gelu -> fp16, 8 px/thread --------
__global__ __launch_bounds__(256)
void dwgelu(const float* __restrict__ Wt, __half* __restrict__ Hx) {
    int b = blockIdx.z, c = blockIdx.y;
    int p = (blockIdx.x * 256 + threadIdx.x) * 8;
    size_t oidx = ((size_t)b * GGPAD + c) * HWN + p;
    if (c >= HIDC) {
        uint4 z = make_uint4(0, 0, 0, 0);
        *(uint4*)(Hx + oidx) = z;
        return;
    }
    int h = p >> 7, wcol = p & 127;
    float va[8], vg[8];
    #pragma unroll
    for (int i = 0; i < 8; i++) { va[i] = 0.f; vg[i] = 0.f; }
    {
        const __half* xp = g_h + ((size_t)b * HID2 + c) * HWN;
        float kv[9];
        #pragma unroll
        for (int i = 0; i < 9; i++) kv[i] = Wt[(size_t)c * 9 + i];
        dw_core_h8(xp, kv, h, wcol, va);
    }
    {
        int ch = c + HIDC;
        const __half* xp = g_h + ((size_t)b * HID2 + ch) * HWN;
        float kv[9];
        #pragma unroll
        for (int i = 0; i < 9; i++) kv[i] = Wt[(size_t)ch * 9 + i];
        dw_core_h8(xp, kv, h, wcol, vg);
    }
    float o[8];
    #pragma unroll
    for (int j = 0; j < 8; j++) {
        float aa = va[j];
        float ge = 0.5f * aa * (1.f + erff(aa * 0.70710678118654752f));
        o[j] = ge * vg[j];
    }
    st_half8(Hx + oidx, o);
}

// ---------------- attention ----------------
#define QKS 136
__global__ __launch_bounds__(256)
void skernel() {
    __shared__ __half Qs[CHD * QKS];
    __shared__ __half Ks[CHD * QKS];
    __shared__ float Ssm[CHD * 49];
    int m = blockIdx.x, ns = blockIdx.y;
    int b = m >> 3, br = (m >> 2) & 1, hh = m & 3;
    const __half* qb = g_q + ((size_t)b * C2 + br * CC + hh * CHD) * HWN;
    const __half* kb = (br ? g_kv2 : g_kv1) + ((size_t)b * C2 + hh * CHD) * HWN;
    int t = threadIdx.x, lane = t & 31, wid = t >> 5;
    for (int i = t; i < CHD * 49; i += 256) Ssm[i] = 0.f;
    unsigned qsb = smem_u32(Qs), ksb = smem_u32(Ks);

    float acc[3][6][4];
    #pragma unroll
    for (int i = 0; i < 3; i++)
        #pragma unroll
        for (int j = 0; j < 6; j++)
            #pragma unroll
            for (int k = 0; k < 4; k++) acc[i][j][k] = 0.f;

    int rsel = lane & 15, csel = (lane >> 4) * 8;
    int bnr = (lane & 7) + ((lane >> 4) & 1) * 8;
    int bkc = ((lane >> 3) & 1) * 8;
    int kc = wid * 16;
    int nbeg = ns * 2048;

    for (int ch = 0; ch < 16; ch++) {
        int n0 = nbeg + ch * 128;
        __syncthreads();
        #pragma unroll
        for (int j = 0; j < 6; j++) {
            int ci = j * 256 + t;
            int mtx = (ci >= 768);
            int loc = ci - mtx * 768;
            int row = loc >> 4, g = loc & 15;
            const __half* src = (mtx ? kb : qb) + (size_t)row * HWN + n0 + g * 8;
            unsigned dst = (mtx ? ksb : qsb) + (unsigned)(row * QKS + g * 8) * 2;
            CP_ASYNC16(dst, src);
        }
        CP_COMMIT(); CP_WAIT(0);
        __syncthreads();
        unsigned af[3][4], bf[3][4];
        #pragma unroll
        for (int mt = 0; mt < 3; mt++) {
            unsigned off = (unsigned)((mt * 16 + rsel) * QKS + kc + csel) * 2;
            ldm_x4(af[mt][0], af[mt][1], af[mt][2], af[mt][3], qsb + off);
        }
        #pragma unroll
        for (int nf = 0; nf < 3; nf++) {
            unsigned off = (unsigned)((nf * 16 + bnr) * QKS + kc + bkc) * 2;
            ldm_x4(bf[nf][0], bf[nf][1], bf[nf][2], bf[nf][3], ksb + off);
        }
        #pragma unroll
        for (int mt = 0; mt < 3; mt++)
            #pragma unroll
            for (int nf = 0; nf < 3; nf++)
                #pragma unroll
                for (int hf = 0; hf < 2; hf++)
                    mma_f16(acc[mt][nf * 2 + hf], af[mt], bf[nf][2 * hf], bf[nf][2 * hf + 1]);
    }
    __syncthreads();
    #pragma unroll
    for (int mt = 0; mt < 3; mt++)
        #pragma unroll
        for (int nt = 0; nt < 6; nt++) {
            int r0 = mt * 16 + (lane >> 2);
            int cl = nt * 8 + (lane & 3) * 2;
            atomicAdd(&Ssm[r0 * 49 + cl],           acc[mt][nt][0]);
            atomicAdd(&Ssm[r0 * 49 + cl + 1],       acc[mt][nt][1]);
            atomicAdd(&Ssm[(r0 + 8) * 49 + cl],     acc[mt][nt][2]);
            atomicAdd(&Ssm[(r0 + 8) * 49 + cl + 1], acc[mt][nt][3]);
        }
    __syncthreads();
    for (int i = t; i < CHD * CHD; i += 256) {
        int r = i / CHD, c = i % CHD;
        atomicAdd(&g_S[(size_t)m * CHD * CHD + i], Ssm[r * 49 + c]);
    }
}

__global__ void softmax_kernel(const float* __restrict__ t1, const float* __restrict__ t2) {
    int m = blockIdx.x;
    int c = threadIdx.x;
    __shared__ float nk[CHD];
    if (c < CHD) nk[c] = fmaxf(sqrtf(g_nrm[m * 96 + CHD + c]), 1e-12f);
    __syncthreads();
    if (c >= CHD) return;
    int br = (m >> 2) & 1, hh = m & 3;
    float tmp = (br ? t2 : t1)[hh];
    float nq = fmaxf(sqrtf(g_nrm[m * 96 + c]), 1e-12f);
    float* row = g_S + (size_t)m * CHD * CHD + c * CHD;
    float vals[CHD];
    float mx = -1e30f;
    #pragma unroll
    for (int d = 0; d < CHD; d++) {
        float v = row[d] / (nq * nk[d]) * tmp;
        vals[d] = v;
        mx = fmaxf(mx, v);
    }
    float sum = 0.f;
    #pragma unroll
    for (int d = 0; d < CHD; d++) { vals[d] = __expf(vals[d] - mx); sum += vals[d]; }
    float inv = 1.f / sum;
    #pragma unroll
    for (int d = 0; d < CHD; d++) row[d] = vals[d] * inv;
}

#define AVS 56
#define VVS 264
__global__ __launch_bounds__(256)
void av_mma() {
    __shared__ __half As[CHD * AVS];
    __shared__ __half Vs[CHD * VVS];
    int m = blockIdx.x;
    int b = m >> 3, br = (m >> 2) & 1, hh = m & 3;
    int t = threadIdx.x, lane = t & 31, wid = t >> 5;
    for (int i = t; i < CHD * CHD; i += 256) {
        int r = i / CHD, c = i % CHD;
        As[r * AVS + c] = __float2half_rn(g_S[(size_t)m * CHD * CHD + i]);
    }
    const __half* vb = (br ? g_kv2 : g_kv1) + ((size_t)b * C2 + CC + hh * CHD) * HWN;
    int p0 = blockIdx.y * 256;
    unsigned asb = smem_u32(As), vsb = smem_u32(Vs);
    #pragma unroll
    for (int j = 0; j < 6; j++) {
        int ci = j * 256 + t;
        int row = ci >> 5, g = ci & 31;
        CP_ASYNC16(vsb + (unsigned)(row * VVS + g * 8) * 2,
                   vb + (size_t)row * HWN + p0 + g * 8);
    }
    CP_COMMIT(); CP_WAIT(0);
    __syncthreads();

    int rsel = lane & 15, csel = (lane >> 4) * 8;
    int bkr = (lane & 7) + ((lane >> 4) & 1) * 8;
    int bpc = ((lane >> 3) & 1) * 8;
    int warpN = wid * 32;

    float acc[3][4][4];
    #pragma unroll
    for (int i = 0; i < 3; i++)
        #pragma unroll
        for (int j = 0; j < 4; j++)
            #pragma unroll
            for (int k = 0; k < 4; k++) acc[i][j][k] = 0.f;

    #pragma unroll
    for (int kt = 0; kt < 3; kt++) {
        unsigned af[3][4], bf[2][4];
        #pragma unroll
        for (int mt = 0; mt < 3; mt++) {
            unsigned off = (unsigned)((mt * 16 + rsel) * AVS + kt * 16 + csel) * 2;
            ldm_x4(af[mt][0], af[mt][1], af[mt][2], af[mt][3], asb + off);
        }
        #pragma unroll
        for (int np = 0; np < 2; np++) {
            unsigned off = (unsigned)((kt * 16 + bkr) * VVS + warpN + np * 16 + bpc) * 2;
            ldm_x4_t(bf[np][0], bf[np][1], bf[np][2], bf[np][3], vsb + off);
        }
        #pragma unroll
        for (int mt = 0; mt < 3; mt++)
            #pragma unroll
            for (int nt = 0; nt < 4; nt++) {
                int np = nt >> 1, hf = nt & 1;
                mma_f16(acc[mt][nt], af[mt], bf[np][hf], bf[np][hf + 2]);
            }
    }
    int off = br * CC + hh * CHD;
    #pragma unroll
    for (int mt = 0; mt < 3; mt++)
        #pragma unroll
        for (int nt = 0; nt < 4; nt++) {
            int r0 = off + mt * 16 + (lane >> 2);
            int pc = p0 + warpN + nt * 8 + (lane & 3) * 2;
            __half2 h0 = __floats2half2_rn(acc[mt][nt][0], acc[mt][nt][1]);
            __half2 h1 = __floats2half2_rn(acc[mt][nt][2], acc[mt][nt][3]);
            *(__half2*)(xt_ao + ((size_t)b * C2 + r0) * HWN + pc) = h0;
            *(__half2*)(xt_ao + ((size_t)b * C2 + r0 + 8) * HWN + pc) = h1;
        }
}

// ---------------- launch ----------------
extern "C" void kernel_launch(void* const* d_in, const int* in_sizes, int n_in,
                              void* d_out, int out_size) {
    const float* x       = (const float*)d_in[0];
    const float* kv1in   = (const float*)d_in[1];
    const float* kv2in   = (const float*)d_in[2];
    const float* n1w = (const float*)d_in[3];  const float* n1b = (const float*)d_in[4];
    const float* nk1w = (const float*)d_in[5]; const float* nk1b = (const float*)d_in[6];
    const float* nk2w = (const float*)d_in[7]; const float* nk2b = (const float*)d_in[8];
    const float* n2w = (const float*)d_in[9];  const float* n2b = (const float*)d_in[10];
    const float* q_w   = (const float*)d_in[11];
    const float* kv1_w = (const float*)d_in[12];
    const float* kv2_w = (const float*)d_in[13];
    const float* q_dw  = (const float*)d_in[14];
    const float* kv1_dw= (const float*)d_in[15];
    const float* kv2_dw= (const float*)d_in[16];
    const float* proj_w= (const float*)d_in[17];
    const float* temp1 = (const float*)d_in[18];
    const float* temp2 = (const float*)d_in[19];
    const float* pin_w = (const float*)d_in[20];
    const float* dw_w  = (const float*)d_in[21];
    const float* pout_w= (const float*)d_in[22];
    float* out = (float*)d_out;

    cudaFuncSetAttribute((const void*)gemm_mma<0, true>,  cudaFuncAttributeMaxDynamicSharedMemorySize, GEMM_SMEM_H);
    cudaFuncSetAttribute((const void*)gemm_mma<1, true>,  cudaFuncAttributeMaxDynamicSharedMemorySize, GEMM_SMEM_H);
    cudaFuncSetAttribute((const void*)gemm_mma<2, false>, cudaFuncAttributeMaxDynamicSharedMemorySize, GEMM_SMEM);
    cudaFuncSetAttribute((const void*)gemm3, cudaFuncAttributeMaxDynamicSharedMemorySize, GEMM_SMEM_H);

    __half *p_h, *wh, *pa, *pao, *pgg, *px2h;
    cudaGetSymbolAddress((void**)&p_h, g_h);
    cudaGetSymbolAddress((void**)&wh, g_wh);
    cudaGetSymbolAddress((void**)&pa, xt_a);
    cudaGetSymbolAddress((void**)&pao, xt_ao);
    cudaGetSymbolAddress((void**)&pgg, xt_gg);
    cudaGetSymbolAddress((void**)&px2h, g_x2h);

    // 1: weights + zero attn accumulators
    wconv_all<<<WCONV_BLKS + ZERO_BLKS, 64>>>(q_w, kv1_w, kv2_w, proj_w, pin_w, pout_w);
    // 2: merged LNs
    ln3<<<dim3(HWN / 64, BB, 3), 256>>>(x, kv1in, kv2in, n1w, n1b, nk1w, nk1b, nk2w, nk2b);
    // 3: merged q/kv1/kv2 GEMM
    gemm3<<<dim3(HWN / 128, 3, 12), 256, GEMM_SMEM_H>>>();
    // 4: merged dwconvs (+ fused attention norms), 8 px/thread
    dim3 dAll(HWN / 2048, 3 * C2, BB);
    dwconv_all<<<dAll, 256>>>(q_dw, kv1_dw, kv2_dw);
    // 5-7: attention on HMMA
    skernel<<<dim3(32, 8), 256>>>();
    softmax_kernel<<<32, 64>>>(temp1, temp2);
    av_mma<<<dim3(32, HWN / 256), 256>>>();
    // 8: proj + residual x -> g_x2h (fp16)
    dim3 gP(HWN / 128, 2, BB);
    gemm_mma<1, true><<<gP, 256, GEMM_SMEM_H>>>(wh + OFF_P, pao, x, px2h, 192, 384);
    // 9: FFN LN over fp16 x2
    dim3 lnG(HWN / 64, BB);
    ln_h<<<lnG, 256>>>(px2h, n2w, n2b, pa);
    // 10: pin GEMM -> g_h (fp16)
    dim3 gIn(HWN / 128, 8, BB);
    gemm_mma<0, true><<<gIn, 256, GEMM_SMEM_H>>>(wh + OFF_PIN, pa, nullptr, p_h, 1020, 192);
    // 11: fused dwconv+gelu, 8 px/thread
    dim3 dGG(HWN / 2048, GGPAD, BB);
    dwgelu<<<dGG, 256>>>(dw_w, pgg);
    // 12: pout GEMM + fp16 residual -> fp32 out
    gemm_mma<2, false><<<gP, 256, GEMM_SMEM>>>(wh + OFF_PO, pgg, px2h, out, 192, 512);
}

// round 15
// speedup vs baseline: 1.4439x; 1.0280x over previous
#include <cuda_runtime.h>
#include <cuda_fp16.h>
#include <math.h>

#define BB 4
#define CC 192
#define C2 384
#define HWN 16384
#define HIMG 128
#define CHD 48
#define HIDC 510
#define HID2 1020
#define GGPAD 512
#define EPSLN 1e-5f

__device__ __forceinline__ unsigned smem_u32(const void* p) {
    unsigned a;
    asm("{ .reg .u64 t; cvta.to.shared.u64 t, %1; cvt.u32.u64 %0, t; }"
        : "=r"(a) : "l"(p));
    return a;
}
#define CP_ASYNC16(dst, src) \
    asm volatile("cp.async.cg.shared.global [%0], [%1], 16;" :: "r"(dst), "l"(src))
#define CP_COMMIT() asm volatile("cp.async.commit_group;" ::: "memory")
#define CP_WAIT(n)  asm volatile("cp.async.wait_group %0;" :: "n"(n) : "memory")

__device__ __forceinline__ void ldm_x4(unsigned& r0, unsigned& r1, unsigned& r2, unsigned& r3,
                                       unsigned addr) {
    asm volatile("ldmatrix.sync.aligned.m8n8.x4.shared.b16 {%0,%1,%2,%3}, [%4];"
        : "=r"(r0), "=r"(r1), "=r"(r2), "=r"(r3) : "r"(addr));
}
__device__ __forceinline__ void ldm_x4_t(unsigned& r0, unsigned& r1, unsigned& r2, unsigned& r3,
                                         unsigned addr) {
    asm volatile("ldmatrix.sync.aligned.m8n8.x4.trans.shared.b16 {%0,%1,%2,%3}, [%4];"
        : "=r"(r0), "=r"(r1), "=r"(r2), "=r"(r3) : "r"(addr));
}
__device__ __forceinline__ void mma_f16(float* d, const unsigned* a, unsigned b0, unsigned b1) {
    asm volatile("mma.sync.aligned.m16n8k16.row.col.f32.f16.f16.f32 "
        "{%0,%1,%2,%3}, {%4,%5,%6,%7}, {%8,%9}, {%0,%1,%2,%3};"
        : "+f"(d[0]), "+f"(d[1]), "+f"(d[2]), "+f"(d[3])
        : "r"(a[0]), "r"(a[1]), "r"(a[2]), "r"(a[3]), "r"(b0), "r"(b1));
}

// ---------------- scratch ----------------
__device__ __align__(16) __half g_qpre [BB*C2*HWN];
__device__ __align__(16) __half g_kv1pre[BB*C2*HWN];
__device__ __align__(16) __half g_kv2pre[BB*C2*HWN];
__device__ __align__(16) __half g_q   [BB*C2*HWN];
__device__ __align__(16) __half g_kv1 [BB*C2*HWN];
__device__ __align__(16) __half g_kv2 [BB*C2*HWN];
__device__ __align__(16) __half g_h   [BB*HID2*HWN];
__device__ __align__(16) __half g_x2h [BB*CC*HWN];
__device__ float g_S   [32*CHD*CHD];
__device__ float g_nrm [32*2*CHD];

// fp16 activations, natural layout: [b][channel][pixel]
__device__ __align__(16) __half xt_a [BB*CC*HWN];
__device__ __align__(16) __half xt_k1[BB*CC*HWN];
__device__ __align__(16) __half xt_k2[BB*CC*HWN];
__device__ __align__(16) __half xt_ao[BB*C2*HWN];
__device__ __align__(16) __half xt_gg[BB*GGPAD*HWN];
// converted weights (row-major [O][Cpad]), fp16
#define OFF_Q   0
#define OFF_K1  (384*192)
#define OFF_K2  (2*384*192)
#define OFF_P   (3*384*192)
#define OFF_PIN (3*384*192 + 192*384)
#define OFF_PO  (3*384*192 + 192*384 + 1020*192)
#define WTOT    (3*384*192 + 192*384 + 1020*192 + 192*512)
#define WPAD    (64*512)
__device__ __align__(16) __half g_wh[WTOT + WPAD];

// ---------------- fp32 -> fp16 helpers ----------------
__device__ __forceinline__ void st_half8(__half* dst, const float* a) {
    __half2 h0 = __floats2half2_rn(a[0], a[1]);
    __half2 h1 = __floats2half2_rn(a[2], a[3]);
    __half2 h2 = __floats2half2_rn(a[4], a[5]);
    __half2 h3 = __floats2half2_rn(a[6], a[7]);
    uint4 u;
    u.x = *(unsigned*)&h0; u.y = *(unsigned*)&h1;
    u.z = *(unsigned*)&h2; u.w = *(unsigned*)&h3;
    *(uint4*)dst = u;
}

// ---------------- merged weight conversion + attn-accumulator zero ----------
#define WCONV_BLKS 2556
#define ZERO_BLKS 1152
__global__ void wconv_all(const float* __restrict__ q_w, const float* __restrict__ kv1_w,
                          const float* __restrict__ kv2_w, const float* __restrict__ proj_w,
                          const float* __restrict__ pin_w, const float* __restrict__ pout_w) {
    int r = blockIdx.x;
    if (r >= WCONV_BLKS) {
        int i = (r - WCONV_BLKS) * 64 + threadIdx.x;
        if (i < 32 * CHD * CHD) g_S[i] = 0.f;
        if (i < 32 * 96) g_nrm[i] = 0.f;
        return;
    }
    const float* W; int o, Cin, Cpad, off;
    if (r < 384)        { W = q_w;    o = r;        Cin = 192; Cpad = 192; off = OFF_Q; }
    else if (r < 768)   { W = kv1_w;  o = r - 384;  Cin = 192; Cpad = 192; off = OFF_K1; }
    else if (r < 1152)  { W = kv2_w;  o = r - 768;  Cin = 192; Cpad = 192; off = OFF_K2; }
    else if (r < 1344)  { W = proj_w; o = r - 1152; Cin = 384; Cpad = 384; off = OFF_P; }
    else if (r < 2364)  { W = pin_w;  o = r - 1344; Cin = 192; Cpad = 192; off = OFF_PIN; }
    else                { W = pout_w; o = r - 2364; Cin = 510; Cpad = 512; off = OFF_PO; }
    int c0 = threadIdx.x * 8;
    if (c0 >= Cpad) return;
    float v[8];
    #pragma unroll
    for (int j = 0; j < 8; j++) {
        int c = c0 + j;
        v[j] = (c < Cin) ? W[(size_t)o * Cin + c] : 0.f;
    }
    st_half8(g_wh + (size_t)off + (size_t)o * Cpad + c0, v);
}

// ======================= HMMA GEMM body (3-stage pipeline) ===================
// RMODE: 0 = no residual, 1 = fp32 residual, 2 = fp16 residual
#define BK 32
#define ASTRIDE 40
#define PSTR 136
#define A_BYTES (128 * ASTRIDE * 2)
#define B_BYTES (BK * PSTR * 2)
#define BUF_BYTES (A_BYTES + B_BYTES)
#define YSTRIDE 132
#define GEMM_SMEM (128 * YSTRIDE * 4)     // 67584 >= 3*BUF_BYTES
#define GEMM_SMEM_H (3 * BUF_BYTES)       // 56832

template<int RMODE, bool HALF_OUT>
__device__ __forceinline__
void gemm_body(const __half* __restrict__ W, const __half* __restrict__ XB,
               const void* __restrict__ Rv, void* __restrict__ Yv, int O, int Cpad,
               int b, int p0, int o0, char* dsm) {
    unsigned sbase = smem_u32(dsm);
    int t = threadIdx.x, lane = t & 31, wid = t >> 5;
    int warpM = (wid >> 1) * 32;
    int warpN = (wid & 1) * 64;
    const __half* WB = W + (size_t)o0 * Cpad;
    int nk = Cpad / BK;

    auto fill = [&](int kt) {
        int buf = kt % 3;
        unsigned bb = sbase + buf * BUF_BYTES;
        int k0 = kt * BK;
        #pragma unroll
        for (int j = 0; j < 4; j++) {
            int ci = j * 256 + t;
            if (ci < 512) {
                int row = ci >> 2, g = ci & 3;
                const __half* src = WB + (size_t)row * Cpad + k0 + g * 8;
                unsigned dst = bb + (unsigned)(row * ASTRIDE + g * 8) * 2;
                CP_ASYNC16(dst, src);
            } else {
                int m = ci - 512;
                int row = m >> 4, g = m & 15;
                const __half* src = XB + (size_t)(k0 + row) * HWN + g * 8;
                unsigned dst = bb + A_BYTES + (unsigned)(row * PSTR + g * 8) * 2;
                CP_ASYNC16(dst, src);
            }
        }
        CP_COMMIT();
    };

    float acc[2][8][4];
    #pragma unroll
    for (int i = 0; i < 2; i++)
        #pragma unroll
        for (int j = 0; j < 8; j++)
            #pragma unroll
            for (int k = 0; k < 4; k++) acc[i][j][k] = 0.f;

    fill(0);
    if (nk > 1) fill(1);
    int rsel = lane & 15, csel = (lane >> 4) * 8;
    int bkr = (lane & 7) + ((lane >> 4) & 1) * 8;
    int bpc = ((lane >> 3) & 1) * 8;

    for (int kt = 0; kt < nk; kt++) {
        if (kt + 1 < nk) { CP_WAIT(1); }
        else             { CP_WAIT(0); }
        __syncthreads();
        if (kt + 2 < nk) fill(kt + 2);
        unsigned bb = sbase + (kt % 3) * BUF_BYTES;
        unsigned Aa = bb, Ba = bb + A_BYTES;
        #pragma unroll
        for (int kk = 0; kk < 2; kk++) {
            int kc = csel + kk * 16;
            unsigned af[2][4], bf[4][4];
            #pragma unroll
            for (int mt = 0; mt < 2; mt++) {
                unsigned off = (unsigned)((warpM + mt * 16 + rsel) * ASTRIDE + kc) * 2;
                ldm_x4(af[mt][0], af[mt][1], af[mt][2], af[mt][3], Aa + off);
            }
            #pragma unroll
            for (int np = 0; np < 4; np++) {
                unsigned off = (unsigned)((kk * 16 + bkr) * PSTR + warpN + np * 16 + bpc) * 2;
                ldm_x4_t(bf[np][0], bf[np][1], bf[np][2], bf[np][3], Ba + off);
            }
            #pragma unroll
            for (int mt = 0; mt < 2; mt++)
                #pragma unroll
                for (int nt = 0; nt < 8; nt++) {
                    int np = nt >> 1, hf = nt & 1;
                    mma_f16(acc[mt][nt], af[mt], bf[np][hf], bf[np][hf + 2]);
                }
        }
    }
    __syncthreads();

    if (HALF_OUT) {
        __half* Y = (__half*)Yv;
        const float* Rf = (const float*)Rv;
        #pragma unroll
        for (int mt = 0; mt < 2; mt++)
            #pragma unroll
            for (int nt = 0; nt < 8; nt++) {
                int r0 = o0 + warpM + mt * 16 + (lane >> 2);
                int pc = p0 + warpN + nt * 8 + (lane & 3) * 2;
                float v0 = acc[mt][nt][0], v1 = acc[mt][nt][1];
                float v2 = acc[mt][nt][2], v3 = acc[mt][nt][3];
                if (RMODE == 1) {
                    if (r0 < O) {
                        float2 q = *(const float2*)(Rf + ((size_t)b * O + r0) * HWN + pc);
                        v0 += q.x; v1 += q.y;
                    }
                    if (r0 + 8 < O) {
                        float2 q = *(const float2*)(Rf + ((size_t)b * O + r0 + 8) * HWN + pc);
                        v2 += q.x; v3 += q.y;
                    }
                }
                __half2 h0 = __floats2half2_rn(v0, v1);
                __half2 h1 = __floats2half2_rn(v2, v3);
                if (r0 < O)     *(__half2*)(Y + ((size_t)b * O + r0) * HWN + pc) = h0;
                if (r0 + 8 < O) *(__half2*)(Y + ((size_t)b * O + r0 + 8) * HWN + pc) = h1;
            }
        return;
    }

    float* Ysm = (float*)dsm;
    #pragma unroll
    for (int mt = 0; mt < 2; mt++)
        #pragma unroll
        for (int nt = 0; nt < 8; nt++) {
            int r0 = warpM + mt * 16 + (lane >> 2);
            int cc = warpN + nt * 8 + (lane & 3) * 2;
            Ysm[r0 * YSTRIDE + cc]           = acc[mt][nt][0];
            Ysm[r0 * YSTRIDE + cc + 1]       = acc[mt][nt][1];
            Ysm[(r0 + 8) * YSTRIDE + cc]     = acc[mt][nt][2];
            Ysm[(r0 + 8) * YSTRIDE + cc + 1] = acc[mt][nt][3];
        }
    __syncthreads();
    #pragma unroll
    for (int i = 0; i < 16; i++) {
        int idx = i * 256 + t;
        int row = idx >> 5, c4 = (idx & 31) * 4;
        int o = o0 + row;
        if (o < O) {
            float4 v = *(float4*)(Ysm + row * YSTRIDE + c4);
            size_t goff = ((size_t)b * O + o) * HWN + p0 + c4;
            if (RMODE == 1) {
                float4 q = *(const float4*)((const float*)Rv + goff);
                v.x += q.x; v.y += q.y; v.z += q.z; v.w += q.w;
            } else if (RMODE == 2) {
                const __half* Rh = (const __half*)Rv;
                __half2 q0 = *(const __half2*)(Rh + goff);
                __half2 q1 = *(const __half2*)(Rh + goff + 2);
                v.x += __low2float(q0); v.y += __high2float(q0);
                v.z += __low2float(q1); v.w += __high2float(q1);
            }
            *(float4*)((float*)Yv + goff) = v;
        }
    }
}

template<int RMODE, bool HALF_OUT>
__global__ __launch_bounds__(256)
void gemm_mma(const __half* __restrict__ W, const __half* __restrict__ X,
              const void* __restrict__ R, void* __restrict__ Y, int O, int Cpad) {
    extern __shared__ char dsm[];
    int b = blockIdx.z;
    gemm_body<RMODE, HALF_OUT>(W,
                     X + (size_t)b * Cpad * HWN + blockIdx.x * 128,
                     R, Y, O, Cpad, b, blockIdx.x * 128, blockIdx.y * 128, dsm);
}

__global__ __launch_bounds__(256)
void gemm3(void) {
    extern __shared__ char dsm[];
    int z = blockIdx.z, which = z >> 2, b = z & 3;
    const __half *W, *X;
    __half* Y;
    if (which == 0)      { W = g_wh + OFF_Q;  X = xt_a;  Y = g_qpre; }
    else if (which == 1) { W = g_wh + OFF_K1; X = xt_k1; Y = g_kv1pre; }
    else                 { W = g_wh + OFF_K2; X = xt_k2; Y = g_kv2pre; }
    gemm_body<0, true>(W,
                     X + (size_t)b * CC * HWN + blockIdx.x * 128,
                     nullptr, Y, C2, CC, b, blockIdx.x * 128, blockIdx.y * 128, dsm);
}

// ---------------- LayerNorm -> fp16 [c][p] (fp32 input) ---------------------
__device__ __forceinline__
void ln_body(const float* __restrict__ X, const float* __restrict__ w,
             const float* __restrict__ bia, __half* __restrict__ Hx,
             int b, int pblk) {
    __shared__ float2 red[256];
    int px = threadIdx.x & 63, cg = threadIdx.x >> 6;
    int p = pblk * 64 + px;
    const float* xp = X + ((size_t)b * CC + (size_t)cg * 48) * HWN + p;
    float v[48];
    float s = 0.f, q = 0.f;
    #pragma unroll
    for (int i = 0; i < 48; i++) {
        float t = xp[(size_t)i * HWN];
        v[i] = t; s += t; q += t * t;
    }
    red[threadIdx.x] = make_float2(s, q);
    __syncthreads();
    float2 r0 = red[px], r1 = red[64 + px], r2 = red[128 + px], r3 = red[192 + px];
    float st = r0.x + r1.x + r2.x + r3.x;
    float qt = r0.y + r1.y + r2.y + r3.y;
    const float invc = 1.f / CC;
    float mu = st * invc;
    float iv = rsqrtf(fmaxf(qt * invc - mu * mu, 0.f) + EPSLN);
    size_t base = ((size_t)b * CC + (size_t)cg * 48) * HWN + p;
    #pragma unroll
    for (int i = 0; i < 48; i++) {
        int c = cg * 48 + i;
        float o = (v[i] - mu) * iv * w[c] + bia[c];
        Hx[base + (size_t)i * HWN] = __float2half_rn(o);
    }
}

__global__ __launch_bounds__(256)
void ln3(const float* __restrict__ X0, const float* __restrict__ X1, const float* __restrict__ X2,
         const float* __restrict__ w0, const float* __restrict__ b0,
         const float* __restrict__ w1, const float* __restrict__ b1,
         const float* __restrict__ w2, const float* __restrict__ b2) {
    int which = blockIdx.z;
    const float *X, *w, *bia;
    __half* Hx;
    if (which == 0)      { X = X0; w = w0; bia = b0; Hx = xt_a; }
    else if (which == 1) { X = X1; w = w1; bia = b1; Hx = xt_k1; }
    else                 { X = X2; w = w2; bia = b2; Hx = xt_k2; }
    ln_body(X, w, bia, Hx, blockIdx.y, blockIdx.x);
}

// fp16-input LN (for x2)
__global__ __launch_bounds__(256)
void ln_h(const __half* __restrict__ X, const float* __restrict__ w,
          const float* __restrict__ bia, __half* __restrict__ Hx) {
    __shared__ float2 red[256];
    int b = blockIdx.y, pblk = blockIdx.x;
    int px = threadIdx.x & 63, cg = threadIdx.x >> 6;
    int p = pblk * 64 + px;
    const __half* xp = X + ((size_t)b * CC + (size_t)cg * 48) * HWN + p;
    float v[48];
    float s = 0.f, q = 0.f;
    #pragma unroll
    for (int i = 0; i < 48; i++) {
        float t = __half2float(xp[(size_t)i * HWN]);
        v[i] = t; s += t; q += t * t;
    }
    red[threadIdx.x] = make_float2(s, q);
    __syncthreads();
    float2 r0 = red[px], r1 = red[64 + px], r2 = red[128 + px], r3 = red[192 + px];
    float st = r0.x + r1.x + r2.x + r3.x;
    float qt = r0.y + r1.y + r2.y + r3.y;
    const float invc = 1.f / CC;
    float mu = st * invc;
    float iv = rsqrtf(fmaxf(qt * invc - mu * mu, 0.f) + EPSLN);
    size_t base = ((size_t)b * CC + (size_t)cg * 48) * HWN + p;
    #pragma unroll
    for (int i = 0; i < 48; i++) {
        int c = cg * 48 + i;
        float o = (v[i] - mu) * iv * w[c] + bia[c];
        Hx[base + (size_t)i * HWN] = __float2half_rn(o);
    }
}

// ---------------- depthwise 3x3 core, 8 px/thread ----------------
__device__ __forceinline__ void dw_core_h8(const __half* __restrict__ xp, const float* kv,
                                           int h, int wcol, float* a) {
    #pragma unroll
    for (int dy = -1; dy <= 1; dy++) {
        int hh = h + dy;
        if (hh < 0 || hh >= HIMG) continue;
        const __half* r = xp + hh * HIMG + wcol;
        uint4 u = *(const uint4*)r;
        __half2 h0 = *(__half2*)&u.x, h1 = *(__half2*)&u.y;
        __half2 h2 = *(__half2*)&u.z, h3 = *(__half2*)&u.w;
        float m[8];
        m[0] = __low2float(h0); m[1] = __high2float(h0);
        m[2] = __low2float(h1); m[3] = __high2float(h1);
        m[4] = __low2float(h2); m[5] = __high2float(h2);
        m[6] = __low2float(h3); m[7] = __high2float(h3);
        float lf = (wcol > 0)   ? __half2float(r[-1]) : 0.f;
        float rt = (wcol < 120) ? __half2float(r[8])  : 0.f;
        const float* k = kv + (dy + 1) * 3;
        a[0] += k[0]*lf + k[1]*m[0] + k[2]*m[1];
        #pragma unroll
        for (int j = 1; j < 7; j++)
            a[j] += k[0]*m[j-1] + k[1]*m[j] + k[2]*m[j+1];
        a[7] += k[0]*m[6] + k[1]*m[7] + k[2]*rt;
    }
}

// merged q-grouped + kv1 + kv2 depthwise, fused norm sumsq (8 px/thread)
__global__ __launch_bounds__(256)
void dwconv_all(const float* __restrict__ Wq, const float* __restrict__ Wt1,
                const float* __restrict__ Wt2) {
    __shared__ float red[8];
    int b = blockIdx.z, cc = blockIdx.y;
    int t = threadIdx.x, lane = t & 31, wid = t >> 5;
    int p = (blockIdx.x * 256 + t) * 8;
    int h = p >> 7, wcol = p & 127;
    float a[8];
    #pragma unroll
    for (int i = 0; i < 8; i++) a[i] = 0.f;
    bool want = false; int nm = 0, slot = 0;
    if (cc < C2) {
        int o = cc;
        int i0 = (o >> 1) << 1;
        const __half* x0 = g_qpre + ((size_t)b * C2 + i0) * HWN;
        float kv[18];
        #pragma unroll
        for (int i = 0; i < 18; i++) kv[i] = Wq[(size_t)o * 18 + i];
        dw_core_h8(x0, kv, h, wcol, a);
        dw_core_h8(x0 + HWN, kv + 9, h, wcol, a);
        st_half8(g_q + ((size_t)b * C2 + o) * HWN + p, a);
        int br = o / CC, rem = o % CC;
        want = true; nm = b * 8 + br * 4 + rem / CHD; slot = rem % CHD;
    } else {
        const __half* X; const float* Wt; __half* Y; int c, br;
        if (cc < 2 * C2) { X = g_kv1pre; Wt = Wt1; Y = g_kv1; c = cc - C2;     br = 0; }
        else             { X = g_kv2pre; Wt = Wt2; Y = g_kv2; c = cc - 2 * C2; br = 1; }
        const __half* xp = X + ((size_t)b * C2 + c) * HWN;
        float kv[9];
        #pragma unroll
        for (int i = 0; i < 9; i++) kv[i] = Wt[(size_t)c * 9 + i];
        dw_core_h8(xp, kv, h, wcol, a);
        st_half8(Y + ((size_t)b * C2 + c) * HWN + p, a);
        if (c < CC) { want = true; nm = b * 8 + br * 4 + c / CHD; slot = CHD + c % CHD; }
    }
    if (want) {
        float ss = 0.f;
        #pragma unroll
        for (int i = 0; i < 8; i++) ss += a[i] * a[i];
        #pragma unroll
        for (int st = 16; st > 0; st >>= 1)
            ss += __shfl_xor_sync(0xffffffffu, ss, st);
        if (lane == 0) red[wid] = ss;
        __syncthreads();
        if (t == 0) {
            float tot = 0.f;
            #pragma unroll
            for (int i = 0; i < 8; i++) tot += red[i];
            atomicAdd(&g_nrm[nm * 96 + slot], tot);
        }
    }
}

// ---------------- fused FFN dwconv + gated gelu -> fp16, 8 px/thread --------
__global__ __launch_bounds__(256)
void dwgelu(const float* __restrict__ Wt, __half* __restrict__ Hx) {
    int b = blockIdx.z, c = blockIdx.y;
    int p = (blockIdx.x * 256 + threadIdx.x) * 8;
    size_t oidx = ((size_t)b * GGPAD + c) * HWN + p;
    if (c >= HIDC) {
        uint4 z = make_uint4(0, 0, 0, 0);
        *(uint4*)(Hx + oidx) = z;
        return;
    }
    int h = p >> 7, wcol = p & 127;
    float va[8], vg[8];
    #pragma unroll
    for (int i = 0; i < 8; i++) { va[i] = 0.f; vg[i] = 0.f; }
    {
        const __half* xp = g_h + ((size_t)b * HID2 + c) * HWN;
        float kv[9];
        #pragma unroll
        for (int i = 0; i < 9; i++) kv[i] = Wt[(size_t)c * 9 + i];
        dw_core_h8(xp, kv, h, wcol, va);
    }
    {
        int ch = c + HIDC;
        const __half* xp = g_h + ((size_t)b * HID2 + ch) * HWN;
        float kv[9];
        #pragma unroll
        for (int i = 0; i < 9; i++) kv[i] = Wt[(size_t)ch * 9 + i];
        dw_core_h8(xp, kv, h, wcol, vg);
    }
    float o[8];
    #pragma unroll
    for (int j = 0; j < 8; j++) {
        float aa = va[j];
        float ge = 0.5f * aa * (1.f + erff(aa * 0.70710678118654752f));
        o[j] = ge * vg[j];
    }
    st_half8(Hx + oidx, o);
}

// ---------------- attention ----------------
// QK^T double-buffered. Dynamic smem: 2 x (Q+K chunk) + Ssm
#define QKS 136
#define QKBUF (2 * CHD * QKS * 2)        // 26112 bytes per stage (Q+K)
#define SK_SMEM (2 * QKBUF + CHD * 49 * 4)  // 61632
__global__ __launch_bounds__(256)
void skernel() {
    extern __shared__ char sks[];
    float* Ssm = (float*)(sks + 2 * QKBUF);
    int m = blockIdx.x, ns = blockIdx.y;
    int b = m >> 3, br = (m >> 2) & 1, hh = m & 3;
    const __half* qb = g_q + ((size_t)b * C2 + br * CC + hh * CHD) * HWN;
    const __half* kb = (br ? g_kv2 : g_kv1) + ((size_t)b * C2 + hh * CHD) * HWN;
    int t = threadIdx.x, lane = t & 31, wid = t >> 5;
    for (int i = t; i < CHD * 49; i += 256) Ssm[i] = 0.f;
    unsigned sb = smem_u32(sks);

    float acc[3][6][4];
    #pragma unroll
    for (int i = 0; i < 3; i++)
        #pragma unroll
        for (int j = 0; j < 6; j++)
            #pragma unroll
            for (int k = 0; k < 4; k++) acc[i][j][k] = 0.f;

    int rsel = lane & 15, csel = (lane >> 4) * 8;
    int bnr = (lane & 7) + ((lane >> 4) & 1) * 8;
    int bkc = ((lane >> 3) & 1) * 8;
    int kc = wid * 16;
    int nbeg = ns * 2048;

    auto load = [&](int ch) {
        int n0 = nbeg + ch * 128;
        unsigned bb = sb + (ch & 1) * QKBUF;
        #pragma unroll
        for (int j = 0; j < 6; j++) {
            int ci = j * 256 + t;
            int mtx = (ci >= 768);
            int loc = ci - mtx * 768;
            int row = loc >> 4, g = loc & 15;
            const __half* src = (mtx ? kb : qb) + (size_t)row * HWN + n0 + g * 8;
            unsigned dst = bb + (unsigned)(mtx * (CHD * QKS) + row * QKS + g * 8) * 2;
            CP_ASYNC16(dst, src);
        }
        CP_COMMIT();
    };

    load(0);
    for (int ch = 0; ch < 16; ch++) {
        CP_WAIT(0);
        __syncthreads();
        if (ch + 1 < 16) load(ch + 1);
        unsigned qsb = sb + (ch & 1) * QKBUF;
        unsigned ksb = qsb + CHD * QKS * 2;
        unsigned af[3][4], bf[3][4];
        #pragma unroll
        for (int mt = 0; mt < 3; mt++) {
            unsigned off = (unsigned)((mt * 16 + rsel) * QKS + kc + csel) * 2;
            ldm_x4(af[mt][0], af[mt][1], af[mt][2], af[mt][3], qsb + off);
        }
        #pragma unroll
        for (int nf = 0; nf < 3; nf++) {
            unsigned off = (unsigned)((nf * 16 + bnr) * QKS + kc + bkc) * 2;
            ldm_x4(bf[nf][0], bf[nf][1], bf[nf][2], bf[nf][3], ksb + off);
        }
        #pragma unroll
        for (int mt = 0; mt < 3; mt++)
            #pragma unroll
            for (int nf = 0; nf < 3; nf++)
                #pragma unroll
                for (int hf = 0; hf < 2; hf++)
                    mma_f16(acc[mt][nf * 2 + hf], af[mt], bf[nf][2 * hf], bf[nf][2 * hf + 1]);
    }
    __syncthreads();
    #pragma unroll
    for (int mt = 0; mt < 3; mt++)
        #pragma unroll
        for (int nt = 0; nt < 6; nt++) {
            int r0 = mt * 16 + (lane >> 2);
            int cl = nt * 8 + (lane & 3) * 2;
            atomicAdd(&Ssm[r0 * 49 + cl],           acc[mt][nt][0]);
            atomicAdd(&Ssm[r0 * 49 + cl + 1],       acc[mt][nt][1]);
            atomicAdd(&Ssm[(r0 + 8) * 49 + cl],     acc[mt][nt][2]);
            atomicAdd(&Ssm[(r0 + 8) * 49 + cl + 1], acc[mt][nt][3]);
        }
    __syncthreads();
    for (int i = t; i < CHD * CHD; i += 256) {
        int r = i / CHD, c = i % CHD;
        atomicAdd(&g_S[(size_t)m * CHD * CHD + i], Ssm[r * 49 + c]);
    }
}

__global__ void softmax_kernel(const float* __restrict__ t1, const float* __restrict__ t2) {
    int m = blockIdx.x;
    int c = threadIdx.x;
    __shared__ float nk[CHD];
    if (c < CHD) nk[c] = fmaxf(sqrtf(g_nrm[m * 96 + CHD + c]), 1e-12f);
    __syncthreads();
    if (c >= CHD) return;
    int br = (m >> 2) & 1, hh = m & 3;
    float tmp = (br ? t2 : t1)[hh];
    float nq = fmaxf(sqrtf(g_nrm[m * 96 + c]), 1e-12f);
    float* row = g_S + (size_t)m * CHD * CHD + c * CHD;
    float vals[CHD];
    float mx = -1e30f;
    #pragma unroll
    for (int d = 0; d < CHD; d++) {
        float v = row[d] / (nq * nk[d]) * tmp;
        vals[d] = v;
        mx = fmaxf(mx, v);
    }
    float sum = 0.f;
    #pragma unroll
    for (int d = 0; d < CHD; d++) { vals[d] = __expf(vals[d] - mx); sum += vals[d]; }
    float inv = 1.f / sum;
    #pragma unroll
    for (int d = 0; d < CHD; d++) row[d] = vals[d] * inv;
}

#define AVS 56
#define VVS 264
__global__ __launch_bounds__(256)
void av_mma() {
    __shared__ __half As[CHD * AVS];
    __shared__ __half Vs[CHD * VVS];
    int m = blockIdx.x;
    int b = m >> 3, br = (m >> 2) & 1, hh = m & 3;
    int t = threadIdx.x, lane = t & 31, wid = t >> 5;
    for (int i = t; i < CHD * CHD; i += 256) {
        int r = i / CHD, c = i % CHD;
        As[r * AVS + c] = __float2half_rn(g_S[(size_t)m * CHD * CHD + i]);
    }
    const __half* vb = (br ? g_kv2 : g_kv1) + ((size_t)b * C2 + CC + hh * CHD) * HWN;
    int p0 = blockIdx.y * 256;
    unsigned asb = smem_u32(As), vsb = smem_u32(Vs);
    #pragma unroll
    for (int j = 0; j < 6; j++) {
        int ci = j * 256 + t;
        int row = ci >> 5, g = ci & 31;
        CP_ASYNC16(vsb + (unsigned)(row * VVS + g * 8) * 2,
                   vb + (size_t)row * HWN + p0 + g * 8);
    }
    CP_COMMIT(); CP_WAIT(0);
    __syncthreads();

    int rsel = lane & 15, csel = (lane >> 4) * 8;
    int bkr = (lane & 7) + ((lane >> 4) & 1) * 8;
    int bpc = ((lane >> 3) & 1) * 8;
    int warpN = wid * 32;

    float acc[3][4][4];
    #pragma unroll
    for (int i = 0; i < 3; i++)
        #pragma unroll
        for (int j = 0; j < 4; j++)
            #pragma unroll
            for (int k = 0; k < 4; k++) acc[i][j][k] = 0.f;

    #pragma unroll
    for (int kt = 0; kt < 3; kt++) {
        unsigned af[3][4], bf[2][4];
        #pragma unroll
        for (int mt = 0; mt < 3; mt++) {
            unsigned off = (unsigned)((mt * 16 + rsel) * AVS + kt * 16 + csel) * 2;
            ldm_x4(af[mt][0], af[mt][1], af[mt][2], af[mt][3], asb + off);
        }
        #pragma unroll
        for (int np = 0; np < 2; np++) {
            unsigned off = (unsigned)((kt * 16 + bkr) * VVS + warpN + np * 16 + bpc) * 2;
            ldm_x4_t(bf[np][0], bf[np][1], bf[np][2], bf[np][3], vsb + off);
        }
        #pragma unroll
        for (int mt = 0; mt < 3; mt++)
            #pragma unroll
            for (int nt = 0; nt < 4; nt++) {
                int np = nt >> 1, hf = nt & 1;
                mma_f16(acc[mt][nt], af[mt], bf[np][hf], bf[np][hf + 2]);
            }
    }
    int off = br * CC + hh * CHD;
    #pragma unroll
    for (int mt = 0; mt < 3; mt++)
        #pragma unroll
        for (int nt = 0; nt < 4; nt++) {
            int r0 = off + mt * 16 + (lane >> 2);
            int pc = p0 + warpN + nt * 8 + (lane & 3) * 2;
            __half2 h0 = __floats2half2_rn(acc[mt][nt][0], acc[mt][nt][1]);
            __half2 h1 = __floats2half2_rn(acc[mt][nt][2], acc[mt][nt][3]);
            *(__half2*)(xt_ao + ((size_t)b * C2 + r0) * HWN + pc) = h0;
            *(__half2*)(xt_ao + ((size_t)b * C2 + r0 + 8) * HWN + pc) = h1;
        }
}

// ---------------- launch ----------------
extern "C" void kernel_launch(void* const* d_in, const int* in_sizes, int n_in,
                              void* d_out, int out_size) {
    const float* x       = (const float*)d_in[0];
    const float* kv1in   = (const float*)d_in[1];
    const float* kv2in   = (const float*)d_in[2];
    const float* n1w = (const float*)d_in[3];  const float* n1b = (const float*)d_in[4];
    const float* nk1w = (const float*)d_in[5]; const float* nk1b = (const float*)d_in[6];
    const float* nk2w = (const float*)d_in[7]; const float* nk2b = (const float*)d_in[8];
    const float* n2w = (const float*)d_in[9];  const float* n2b = (const float*)d_in[10];
    const float* q_w   = (const float*)d_in[11];
    const float* kv1_w = (const float*)d_in[12];
    const float* kv2_w = (const float*)d_in[13];
    const float* q_dw  = (const float*)d_in[14];
    const float* kv1_dw= (const float*)d_in[15];
    const float* kv2_dw= (const float*)d_in[16];
    const float* proj_w= (const float*)d_in[17];
    const float* temp1 = (const float*)d_in[18];
    const float* temp2 = (const float*)d_in[19];
    const float* pin_w = (const float*)d_in[20];
    const float* dw_w  = (const float*)d_in[21];
    const float* pout_w= (const float*)d_in[22];
    float* out = (float*)d_out;

    cudaFuncSetAttribute((const void*)gemm_mma<0, true>,  cudaFuncAttributeMaxDynamicSharedMemorySize, GEMM_SMEM_H);
    cudaFuncSetAttribute((const void*)gemm_mma<1, true>,  cudaFuncAttributeMaxDynamicSharedMemorySize, GEMM_SMEM_H);
    cudaFuncSetAttribute((const void*)gemm_mma<2, false>, cudaFuncAttributeMaxDynamicSharedMemorySize, GEMM_SMEM);
    cudaFuncSetAttribute((const void*)gemm3, cudaFuncAttributeMaxDynamicSharedMemorySize, GEMM_SMEM_H);
    cudaFuncSetAttribute((const void*)skernel, cudaFuncAttributeMaxDynamicSharedMemorySize, SK_SMEM);

    __half *p_h, *wh, *pa, *pao, *pgg, *px2h;
    cudaGetSymbolAddress((void**)&p_h, g_h);
    cudaGetSymbolAddress((void**)&wh, g_wh);
    cudaGetSymbolAddress((void**)&pa, xt_a);
    cudaGetSymbolAddress((void**)&pao, xt_ao);
    cudaGetSymbolAddress((void**)&pgg, xt_gg);
    cudaGetSymbolAddress((void**)&px2h, g_x2h);

    // 1: weights + zero attn accumulators
    wconv_all<<<WCONV_BLKS + ZERO_BLKS, 64>>>(q_w, kv1_w, kv2_w, proj_w, pin_w, pout_w);
    // 2: merged LNs
    ln3<<<dim3(HWN / 64, BB, 3), 256>>>(x, kv1in, kv2in, n1w, n1b, nk1w, nk1b, nk2w, nk2b);
    // 3: merged q/kv1/kv2 GEMM
    gemm3<<<dim3(HWN / 128, 3, 12), 256, GEMM_SMEM_H>>>();
    // 4: merged dwconvs (+ fused attention norms), 8 px/thread
    dim3 dAll(HWN / 2048, 3 * C2, BB);
    dwconv_all<<<dAll, 256>>>(q_dw, kv1_dw, kv2_dw);
    // 5-7: attention on HMMA
    skernel<<<dim3(32, 8), 256, SK_SMEM>>>();
    softmax_kernel<<<32, 64>>>(temp1, temp2);
    av_mma<<<dim3(32, HWN / 256), 256>>>();
    // 8: proj + residual x -> g_x2h (fp16)
    dim3 gP(HWN / 128, 2, BB);
    gemm_mma<1, true><<<gP, 256, GEMM_SMEM_H>>>(wh + OFF_P, pao, x, px2h, 192, 384);
    // 9: FFN LN over fp16 x2
    dim3 lnG(HWN / 64, BB);
    ln_h<<<lnG, 256>>>(px2h, n2w, n2b, pa);
    // 10: pin GEMM -> g_h (fp16)
    dim3 gIn(HWN / 128, 8, BB);
    gemm_mma<0, true><<<gIn, 256, GEMM_SMEM_H>>>(wh + OFF_PIN, pa, nullptr, p_h, 1020, 192);
    // 11: fused dwconv+gelu, 8 px/thread
    dim3 dGG(HWN / 2048, GGPAD, BB);
    dwgelu<<<dGG, 256>>>(dw_w, pgg);
    // 12: pout GEMM + fp16 residual -> fp32 out
    gemm_mma<2, false><<<gP, 256, GEMM_SMEM>>>(wh + OFF_PO, pgg, px2h, out, 192, 512);
}

// round 16
// speedup vs baseline: 1.4995x; 1.0385x over previous
#include <cuda_runtime.h>
#include <cuda_fp16.h>
#include <math.h>

#define BB 4
#define CC 192
#define C2 384
#define HWN 16384
#define HIMG 128
#define CHD 48
#define HIDC 510
#define HID2 1020
#define GGPAD 512
#define EPSLN 1e-5f

__device__ __forceinline__ unsigned smem_u32(const void* p) {
    unsigned a;
    asm("{ .reg .u64 t; cvta.to.shared.u64 t, %1; cvt.u32.u64 %0, t; }"
        : "=r"(a) : "l"(p));
    return a;
}
#define CP_ASYNC16(dst, src) \
    asm volatile("cp.async.cg.shared.global [%0], [%1], 16;" :: "r"(dst), "l"(src))
#define CP_COMMIT() asm volatile("cp.async.commit_group;" ::: "memory")
#define CP_WAIT(n)  asm volatile("cp.async.wait_group %0;" :: "n"(n) : "memory")

__device__ __forceinline__ void ldm_x4(unsigned& r0, unsigned& r1, unsigned& r2, unsigned& r3,
                                       unsigned addr) {
    asm volatile("ldmatrix.sync.aligned.m8n8.x4.shared.b16 {%0,%1,%2,%3}, [%4];"
        : "=r"(r0), "=r"(r1), "=r"(r2), "=r"(r3) : "r"(addr));
}
__device__ __forceinline__ void ldm_x4_t(unsigned& r0, unsigned& r1, unsigned& r2, unsigned& r3,
                                         unsigned addr) {
    asm volatile("ldmatrix.sync.aligned.m8n8.x4.trans.shared.b16 {%0,%1,%2,%3}, [%4];"
        : "=r"(r0), "=r"(r1), "=r"(r2), "=r"(r3) : "r"(addr));
}
__device__ __forceinline__ void mma_f16(float* d, const unsigned* a, unsigned b0, unsigned b1) {
    asm volatile("mma.sync.aligned.m16n8k16.row.col.f32.f16.f16.f32 "
        "{%0,%1,%2,%3}, {%4,%5,%6,%7}, {%8,%9}, {%0,%1,%2,%3};"
        : "+f"(d[0]), "+f"(d[1]), "+f"(d[2]), "+f"(d[3])
        : "r"(a[0]), "r"(a[1]), "r"(a[2]), "r"(a[3]), "r"(b0), "r"(b1));
}

// ---------------- scratch ----------------
__device__ __align__(16) __half g_qpre [BB*C2*HWN];
__device__ __align__(16) __half g_kv1pre[BB*C2*HWN];
__device__ __align__(16) __half g_kv2pre[BB*C2*HWN];
__device__ __align__(16) __half g_q   [BB*C2*HWN];
__device__ __align__(16) __half g_kv1 [BB*C2*HWN];
__device__ __align__(16) __half g_kv2 [BB*C2*HWN];
__device__ __align__(16) __half g_h   [BB*HID2*HWN];
__device__ __align__(16) __half g_x2h [BB*CC*HWN];
__device__ float g_S   [32*CHD*CHD];
__device__ float g_nrm [32*2*CHD];

// fp16 activations, natural layout: [b][channel][pixel]
__device__ __align__(16) __half xt_a [BB*CC*HWN];
__device__ __align__(16) __half xt_k1[BB*CC*HWN];
__device__ __align__(16) __half xt_k2[BB*CC*HWN];
__device__ __align__(16) __half xt_ao[BB*C2*HWN];
__device__ __align__(16) __half xt_gg[BB*GGPAD*HWN];
// converted weights (row-major [O][Cpad]), fp16
#define OFF_Q   0
#define OFF_K1  (384*192)
#define OFF_K2  (2*384*192)
#define OFF_P   (3*384*192)
#define OFF_PIN (3*384*192 + 192*384)
#define OFF_PO  (3*384*192 + 192*384 + 1020*192)
#define WTOT    (3*384*192 + 192*384 + 1020*192 + 192*512)
#define WPAD    (64*512)
__device__ __align__(16) __half g_wh[WTOT + WPAD];

// ---------------- fp32 -> fp16 helpers ----------------
__device__ __forceinline__ void st_half8(__half* dst, const float* a) {
    __half2 h0 = __floats2half2_rn(a[0], a[1]);
    __half2 h1 = __floats2half2_rn(a[2], a[3]);
    __half2 h2 = __floats2half2_rn(a[4], a[5]);
    __half2 h3 = __floats2half2_rn(a[6], a[7]);
    uint4 u;
    u.x = *(unsigned*)&h0; u.y = *(unsigned*)&h1;
    u.z = *(unsigned*)&h2; u.w = *(unsigned*)&h3;
    *(uint4*)dst = u;
}

// ---------------- merged weight conversion + attn-accumulator zero ----------
#define WCONV_BLKS 2556
#define ZERO_BLKS 1152
__global__ void wconv_all(const float* __restrict__ q_w, const float* __restrict__ kv1_w,
                          const float* __restrict__ kv2_w, const float* __restrict__ proj_w,
                          const float* __restrict__ pin_w, const float* __restrict__ pout_w) {
    int r = blockIdx.x;
    if (r >= WCONV_BLKS) {
        int i = (r - WCONV_BLKS) * 64 + threadIdx.x;
        if (i < 32 * CHD * CHD) g_S[i] = 0.f;
        if (i < 32 * 96) g_nrm[i] = 0.f;
        return;
    }
    const float* W; int o, Cin, Cpad, off;
    if (r < 384)        { W = q_w;    o = r;        Cin = 192; Cpad = 192; off = OFF_Q; }
    else if (r < 768)   { W = kv1_w;  o = r - 384;  Cin = 192; Cpad = 192; off = OFF_K1; }
    else if (r < 1152)  { W = kv2_w;  o = r - 768;  Cin = 192; Cpad = 192; off = OFF_K2; }
    else if (r < 1344)  { W = proj_w; o = r - 1152; Cin = 384; Cpad = 384; off = OFF_P; }
    else if (r < 2364)  { W = pin_w;  o = r - 1344; Cin = 192; Cpad = 192; off = OFF_PIN; }
    else                { W = pout_w; o = r - 2364; Cin = 510; Cpad = 512; off = OFF_PO; }
    int c0 = threadIdx.x * 8;
    if (c0 >= Cpad) return;
    float v[8];
    #pragma unroll
    for (int j = 0; j < 8; j++) {
        int c = c0 + j;
        v[j] = (c < Cin) ? W[(size_t)o * Cin + c] : 0.f;
    }
    st_half8(g_wh + (size_t)off + (size_t)o * Cpad + c0, v);
}

// ======================= HMMA GEMM (generic, 3-stage) ========================
// RMODE: 0 = none, 1 = fp32 residual, 2 = fp16 residual
#define BK 32
#define ASTRIDE 40
#define PSTR 136
#define A_BYTES (128 * ASTRIDE * 2)
#define B_BYTES (BK * PSTR * 2)
#define BUF_BYTES (A_BYTES + B_BYTES)
#define YSTRIDE 132
#define GEMM_SMEM (128 * YSTRIDE * 4)
#define GEMM_SMEM_H (3 * BUF_BYTES)

template<int RMODE, bool HALF_OUT>
__device__ __forceinline__
void gemm_body(const __half* __restrict__ W, const __half* __restrict__ XB,
               const void* __restrict__ Rv, void* __restrict__ Yv, int O, int Cpad,
               int b, int p0, int o0, char* dsm) {
    unsigned sbase = smem_u32(dsm);
    int t = threadIdx.x, lane = t & 31, wid = t >> 5;
    int warpM = (wid >> 1) * 32;
    int warpN = (wid & 1) * 64;
    const __half* WB = W + (size_t)o0 * Cpad;
    int nk = Cpad / BK;

    auto fill = [&](int kt) {
        int buf = kt % 3;
        unsigned bb = sbase + buf * BUF_BYTES;
        int k0 = kt * BK;
        #pragma unroll
        for (int j = 0; j < 4; j++) {
            int ci = j * 256 + t;
            if (ci < 512) {
                int row = ci >> 2, g = ci & 3;
                const __half* src = WB + (size_t)row * Cpad + k0 + g * 8;
                unsigned dst = bb + (unsigned)(row * ASTRIDE + g * 8) * 2;
                CP_ASYNC16(dst, src);
            } else {
                int m = ci - 512;
                int row = m >> 4, g = m & 15;
                const __half* src = XB + (size_t)(k0 + row) * HWN + g * 8;
                unsigned dst = bb + A_BYTES + (unsigned)(row * PSTR + g * 8) * 2;
                CP_ASYNC16(dst, src);
            }
        }
        CP_COMMIT();
    };

    float acc[2][8][4];
    #pragma unroll
    for (int i = 0; i < 2; i++)
        #pragma unroll
        for (int j = 0; j < 8; j++)
            #pragma unroll
            for (int k = 0; k < 4; k++) acc[i][j][k] = 0.f;

    fill(0);
    if (nk > 1) fill(1);
    int rsel = lane & 15, csel = (lane >> 4) * 8;
    int bkr = (lane & 7) + ((lane >> 4) & 1) * 8;
    int bpc = ((lane >> 3) & 1) * 8;

    for (int kt = 0; kt < nk; kt++) {
        if (kt + 1 < nk) { CP_WAIT(1); }
        else             { CP_WAIT(0); }
        __syncthreads();
        if (kt + 2 < nk) fill(kt + 2);
        unsigned bb = sbase + (kt % 3) * BUF_BYTES;
        unsigned Aa = bb, Ba = bb + A_BYTES;
        #pragma unroll
        for (int kk = 0; kk < 2; kk++) {
            int kc = csel + kk * 16;
            unsigned af[2][4], bf[4][4];
            #pragma unroll
            for (int mt = 0; mt < 2; mt++) {
                unsigned off = (unsigned)((warpM + mt * 16 + rsel) * ASTRIDE + kc) * 2;
                ldm_x4(af[mt][0], af[mt][1], af[mt][2], af[mt][3], Aa + off);
            }
            #pragma unroll
            for (int np = 0; np < 4; np++) {
                unsigned off = (unsigned)((kk * 16 + bkr) * PSTR + warpN + np * 16 + bpc) * 2;
                ldm_x4_t(bf[np][0], bf[np][1], bf[np][2], bf[np][3], Ba + off);
            }
            #pragma unroll
            for (int mt = 0; mt < 2; mt++)
                #pragma unroll
                for (int nt = 0; nt < 8; nt++) {
                    int np = nt >> 1, hf = nt & 1;
                    mma_f16(acc[mt][nt], af[mt], bf[np][hf], bf[np][hf + 2]);
                }
        }
    }
    __syncthreads();

    if (HALF_OUT) {
        __half* Y = (__half*)Yv;
        const float* Rf = (const float*)Rv;
        #pragma unroll
        for (int mt = 0; mt < 2; mt++)
            #pragma unroll
            for (int nt = 0; nt < 8; nt++) {
                int r0 = o0 + warpM + mt * 16 + (lane >> 2);
                int pc = p0 + warpN + nt * 8 + (lane & 3) * 2;
                float v0 = acc[mt][nt][0], v1 = acc[mt][nt][1];
                float v2 = acc[mt][nt][2], v3 = acc[mt][nt][3];
                if (RMODE == 1) {
                    if (r0 < O) {
                        float2 q = *(const float2*)(Rf + ((size_t)b * O + r0) * HWN + pc);
                        v0 += q.x; v1 += q.y;
                    }
                    if (r0 + 8 < O) {
                        float2 q = *(const float2*)(Rf + ((size_t)b * O + r0 + 8) * HWN + pc);
                        v2 += q.x; v3 += q.y;
                    }
                }
                __half2 h0 = __floats2half2_rn(v0, v1);
                __half2 h1 = __floats2half2_rn(v2, v3);
                if (r0 < O)     *(__half2*)(Y + ((size_t)b * O + r0) * HWN + pc) = h0;
                if (r0 + 8 < O) *(__half2*)(Y + ((size_t)b * O + r0 + 8) * HWN + pc) = h1;
            }
        return;
    }

    float* Ysm = (float*)dsm;
    #pragma unroll
    for (int mt = 0; mt < 2; mt++)
        #pragma unroll
        for (int nt = 0; nt < 8; nt++) {
            int r0 = warpM + mt * 16 + (lane >> 2);
            int cc = warpN + nt * 8 + (lane & 3) * 2;
            Ysm[r0 * YSTRIDE + cc]           = acc[mt][nt][0];
            Ysm[r0 * YSTRIDE + cc + 1]       = acc[mt][nt][1];
            Ysm[(r0 + 8) * YSTRIDE + cc]     = acc[mt][nt][2];
            Ysm[(r0 + 8) * YSTRIDE + cc + 1] = acc[mt][nt][3];
        }
    __syncthreads();
    #pragma unroll
    for (int i = 0; i < 16; i++) {
        int idx = i * 256 + t;
        int row = idx >> 5, c4 = (idx & 31) * 4;
        int o = o0 + row;
        if (o < O) {
            float4 v = *(float4*)(Ysm + row * YSTRIDE + c4);
            size_t goff = ((size_t)b * O + o) * HWN + p0 + c4;
            if (RMODE == 1) {
                float4 q = *(const float4*)((const float*)Rv + goff);
                v.x += q.x; v.y += q.y; v.z += q.z; v.w += q.w;
            } else if (RMODE == 2) {
                const __half* Rh = (const __half*)Rv;
                __half2 q0 = *(const __half2*)(Rh + goff);
                __half2 q1 = *(const __half2*)(Rh + goff + 2);
                v.x += __low2float(q0); v.y += __high2float(q0);
                v.z += __low2float(q1); v.w += __high2float(q1);
            }
            *(float4*)((float*)Yv + goff) = v;
        }
    }
}

template<int RMODE, bool HALF_OUT>
__global__ __launch_bounds__(256)
void gemm_mma(const __half* __restrict__ W, const __half* __restrict__ X,
              const void* __restrict__ R, void* __restrict__ Y, int O, int Cpad) {
    extern __shared__ char dsm[];
    int b = blockIdx.z;
    gemm_body<RMODE, HALF_OUT>(W,
                     X + (size_t)b * Cpad * HWN + blockIdx.x * 128,
                     R, Y, O, Cpad, b, blockIdx.x * 128, blockIdx.y * 128, dsm);
}

// ======================= Persistent-weight GEMM (Cpad=192) ==================
// A loaded ONCE per block; 8 pixel-tiles per block with flat 3-stage B pipe.
#define PERS_NPT 8
#define ASTR2 200
#define PA_BYTES (128 * ASTR2 * 2)           // 51200
#define PERS_SMEM (PA_BYTES + 3 * B_BYTES)   // 77312

__device__ __forceinline__
void gemm_pers_body(const __half* __restrict__ W, const __half* __restrict__ XB,
                    __half* __restrict__ Y, int O, int b, int pbase, int o0) {
    extern __shared__ char dsm[];
    const int Cpad = 192, nk = 6;
    unsigned sbase = smem_u32(dsm);
    unsigned Bsm = sbase + PA_BYTES;
    int t = threadIdx.x, lane = t & 31, wid = t >> 5;
    int warpM = (wid >> 1) * 32;
    int warpN = (wid & 1) * 64;
    const __half* WB = W + (size_t)o0 * Cpad;

    // fill A once: 128 rows x 24 groups of 8 halves
    #pragma unroll
    for (int j = 0; j < 12; j++) {
        int ci = j * 256 + t;
        int row = ci / 24, g = ci % 24;
        CP_ASYNC16(sbase + (unsigned)(row * ASTR2 + g * 8) * 2,
                   WB + (size_t)row * Cpad + g * 8);
    }
    CP_COMMIT();

    auto fillB = [&](int s) {
        int ptl = s / nk, kt = s % nk;
        unsigned bb = Bsm + (s % 3) * B_BYTES;
        const __half* Xp = XB + ptl * 128 + (size_t)(kt * BK) * HWN;
        #pragma unroll
        for (int j = 0; j < 2; j++) {
            int ci = j * 256 + t;
            int row = ci >> 4, g = ci & 15;
            CP_ASYNC16(bb + (unsigned)(row * PSTR + g * 8) * 2,
                       Xp + (size_t)row * HWN + g * 8);
        }
        CP_COMMIT();
    };

    int total = PERS_NPT * nk;
    fillB(0); fillB(1);
    int rsel = lane & 15, csel = (lane >> 4) * 8;
    int bkr = (lane & 7) + ((lane >> 4) & 1) * 8;
    int bpc = ((lane >> 3) & 1) * 8;

    int s = 0;
    for (int pt = 0; pt < PERS_NPT; pt++) {
        float acc[2][8][4];
        #pragma unroll
        for (int i = 0; i < 2; i++)
            #pragma unroll
            for (int j = 0; j < 8; j++)
                #pragma unroll
                for (int k = 0; k < 4; k++) acc[i][j][k] = 0.f;

        for (int kt = 0; kt < nk; kt++) {
            if (s + 1 < total) { CP_WAIT(1); }
            else               { CP_WAIT(0); }
            __syncthreads();
            if (s + 2 < total) fillB(s + 2);
            unsigned Ba = Bsm + (s % 3) * B_BYTES;
            #pragma unroll
            for (int kk = 0; kk < 2; kk++) {
                int kc = kt * BK + csel + kk * 16;
                unsigned af[2][4], bf[4][4];
                #pragma unroll
                for (int mt = 0; mt < 2; mt++) {
                    unsigned off = (unsigned)((warpM + mt * 16 + rsel) * ASTR2 + kc) * 2;
                    ldm_x4(af[mt][0], af[mt][1], af[mt][2], af[mt][3], sbase + off);
                }
                #pragma unroll
                for (int np = 0; np < 4; np++) {
                    unsigned off = (unsigned)((kk * 16 + bkr) * PSTR + warpN + np * 16 + bpc) * 2;
                    ldm_x4_t(bf[np][0], bf[np][1], bf[np][2], bf[np][3], Ba + off);
                }
                #pragma unroll
                for (int mt = 0; mt < 2; mt++)
                    #pragma unroll
                    for (int nt = 0; nt < 8; nt++) {
                        int np = nt >> 1, hf = nt & 1;
                        mma_f16(acc[mt][nt], af[mt], bf[np][hf], bf[np][hf + 2]);
                    }
            }
            s++;
        }
        // direct half2 epilogue (no smem)
        int p0 = pbase + pt * 128;
        #pragma unroll
        for (int mt = 0; mt < 2; mt++)
            #pragma unroll
            for (int nt = 0; nt < 8; nt++) {
                int r0 = o0 + warpM + mt * 16 + (lane >> 2);
                int pc = p0 + warpN + nt * 8 + (lane & 3) * 2;
                __half2 h0 = __floats2half2_rn(acc[mt][nt][0], acc[mt][nt][1]);
                __half2 h1 = __floats2half2_rn(acc[mt][nt][2], acc[mt][nt][3]);
                if (r0 < O)     *(__half2*)(Y + ((size_t)b * O + r0) * HWN + pc) = h0;
                if (r0 + 8 < O) *(__half2*)(Y + ((size_t)b * O + r0 + 8) * HWN + pc) = h1;
            }
    }
}

// merged q/kv1/kv2 persistent GEMM: grid (16, 3, 12)
__global__ __launch_bounds__(256)
void gemm3p(void) {
    int z = blockIdx.z, which = z >> 2, b = z & 3;
    const __half *W, *X;
    __half* Y;
    if (which == 0)      { W = g_wh + OFF_Q;  X = xt_a;  Y = g_qpre; }
    else if (which == 1) { W = g_wh + OFF_K1; X = xt_k1; Y = g_kv1pre; }
    else                 { W = g_wh + OFF_K2; X = xt_k2; Y = g_kv2pre; }
    int pbase = blockIdx.x * (PERS_NPT * 128);
    gemm_pers_body(W, X + (size_t)b * CC * HWN + pbase, Y, C2, b, pbase, blockIdx.y * 128);
}

// pin persistent GEMM: grid (16, 8, 4)
__global__ __launch_bounds__(256)
void gemm_pin(void) {
    int b = blockIdx.z;
    int pbase = blockIdx.x * (PERS_NPT * 128);
    gemm_pers_body(g_wh + OFF_PIN, xt_a + (size_t)b * CC * HWN + pbase,
                   g_h, HID2, b, pbase, blockIdx.y * 128);
}

// ---------------- LayerNorm -> fp16 [c][p] (fp32 input) ---------------------
__device__ __forceinline__
void ln_body(const float* __restrict__ X, const float* __restrict__ w,
             const float* __restrict__ bia, __half* __restrict__ Hx,
             int b, int pblk) {
    __shared__ float2 red[256];
    int px = threadIdx.x & 63, cg = threadIdx.x >> 6;
    int p = pblk * 64 + px;
    const float* xp = X + ((size_t)b * CC + (size_t)cg * 48) * HWN + p;
    float v[48];
    float s = 0.f, q = 0.f;
    #pragma unroll
    for (int i = 0; i < 48; i++) {
        float t = xp[(size_t)i * HWN];
        v[i] = t; s += t; q += t * t;
    }
    red[threadIdx.x] = make_float2(s, q);
    __syncthreads();
    float2 r0 = red[px], r1 = red[64 + px], r2 = red[128 + px], r3 = red[192 + px];
    float st = r0.x + r1.x + r2.x + r3.x;
    float qt = r0.y + r1.y + r2.y + r3.y;
    const float invc = 1.f / CC;
    float mu = st * invc;
    float iv = rsqrtf(fmaxf(qt * invc - mu * mu, 0.f) + EPSLN);
    size_t base = ((size_t)b * CC + (size_t)cg * 48) * HWN + p;
    #pragma unroll
    for (int i = 0; i < 48; i++) {
        int c = cg * 48 + i;
        float o = (v[i] - mu) * iv * w[c] + bia[c];
        Hx[base + (size_t)i * HWN] = __float2half_rn(o);
    }
}

__global__ __launch_bounds__(256)
void ln3(const float* __restrict__ X0, const float* __restrict__ X1, const float* __restrict__ X2,
         const float* __restrict__ w0, const float* __restrict__ b0,
         const float* __restrict__ w1, const float* __restrict__ b1,
         const float* __restrict__ w2, const float* __restrict__ b2) {
    int which = blockIdx.z;
    const float *X, *w, *bia;
    __half* Hx;
    if (which == 0)      { X = X0; w = w0; bia = b0; Hx = xt_a; }
    else if (which == 1) { X = X1; w = w1; bia = b1; Hx = xt_k1; }
    else                 { X = X2; w = w2; bia = b2; Hx = xt_k2; }
    ln_body(X, w, bia, Hx, blockIdx.y, blockIdx.x);
}

// fp16-input LN (for x2)
__global__ __launch_bounds__(256)
void ln_h(const __half* __restrict__ X, const float* __restrict__ w,
          const float* __restrict__ bia, __half* __restrict__ Hx) {
    __shared__ float2 red[256];
    int b = blockIdx.y, pblk = blockIdx.x;
    int px = threadIdx.x & 63, cg = threadIdx.x >> 6;
    int p = pblk * 64 + px;
    const __half* xp = X + ((size_t)b * CC + (size_t)cg * 48) * HWN + p;
    float v[48];
    float s = 0.f, q = 0.f;
    #pragma unroll
    for (int i = 0; i < 48; i++) {
        float t = __half2float(xp[(size_t)i * HWN]);
        v[i] = t; s += t; q += t * t;
    }
    red[threadIdx.x] = make_float2(s, q);
    __syncthreads();
    float2 r0 = red[px], r1 = red[64 + px], r2 = red[128 + px], r3 = red[192 + px];
    float st = r0.x + r1.x + r2.x + r3.x;
    float qt = r0.y + r1.y + r2.y + r3.y;
    const float invc = 1.f / CC;
    float mu = st * invc;
    float iv = rsqrtf(fmaxf(qt * invc - mu * mu, 0.f) + EPSLN);
    size_t base = ((size_t)b * CC + (size_t)cg * 48) * HWN + p;
    #pragma unroll
    for (int i = 0; i < 48; i++) {
        int c = cg * 48 + i;
        float o = (v[i] - mu) * iv * w[c] + bia[c];
        Hx[base + (size_t)i * HWN] = __float2half_rn(o);
    }
}

// ---------------- depthwise 3x3 core, 16 px/thread ----------------
__device__ __forceinline__ void dw_core_h16(const __half* __restrict__ xp, const float* kv,
                                            int h, int wcol, float* a) {
    #pragma unroll
    for (int dy = -1; dy <= 1; dy++) {
        int hh = h + dy;
        if (hh < 0 || hh >= HIMG) continue;
        const __half* r = xp + hh * HIMG + wcol;
        uint4 u0 = *(const uint4*)r;
        uint4 u1 = *(const uint4*)(r + 8);
        float m[16];
        {
            __half2 hh0 = *(__half2*)&u0.x, hh1 = *(__half2*)&u0.y;
            __half2 hh2 = *(__half2*)&u0.z, hh3 = *(__half2*)&u0.w;
            m[0] = __low2float(hh0); m[1] = __high2float(hh0);
            m[2] = __low2float(hh1); m[3] = __high2float(hh1);
            m[4] = __low2float(hh2); m[5] = __high2float(hh2);
            m[6] = __low2float(hh3); m[7] = __high2float(hh3);
        }
        {
            __half2 hh0 = *(__half2*)&u1.x, hh1 = *(__half2*)&u1.y;
            __half2 hh2 = *(__half2*)&u1.z, hh3 = *(__half2*)&u1.w;
            m[8]  = __low2float(hh0); m[9]  = __high2float(hh0);
            m[10] = __low2float(hh1); m[11] = __high2float(hh1);
            m[12] = __low2float(hh2); m[13] = __high2float(hh2);
            m[14] = __low2float(hh3); m[15] = __high2float(hh3);
        }
        float lf = (wcol > 0)   ? __half2float(r[-1]) : 0.f;
        float rt = (wcol < 112) ? __half2float(r[16]) : 0.f;
        const float* k = kv + (dy + 1) * 3;
        a[0] += k[0]*lf + k[1]*m[0] + k[2]*m[1];
        #pragma unroll
        for (int j = 1; j < 15; j++)
            a[j] += k[0]*m[j-1] + k[1]*m[j] + k[2]*m[j+1];
        a[15] += k[0]*m[14] + k[1]*m[15] + k[2]*rt;
    }
}

// merged q-grouped + kv1 + kv2 depthwise, fused norm sumsq (16 px/thread)
__global__ __launch_bounds__(256)
void dwconv_all(const float* __restrict__ Wq, const float* __restrict__ Wt1,
                const float* __restrict__ Wt2) {
    __shared__ float red[8];
    int b = blockIdx.z, cc = blockIdx.y;
    int t = threadIdx.x, lane = t & 31, wid = t >> 5;
    int p = (blockIdx.x * 256 + t) * 16;
    int h = p >> 7, wcol = p & 127;
    float a[16];
    #pragma unroll
    for (int i = 0; i < 16; i++) a[i] = 0.f;
    bool want = false; int nm = 0, slot = 0;
    if (cc < C2) {
        int o = cc;
        int i0 = (o >> 1) << 1;
        const __half* x0 = g_qpre + ((size_t)b * C2 + i0) * HWN;
        float kv[18];
        #pragma unroll
        for (int i = 0; i < 18; i++) kv[i] = Wq[(size_t)o * 18 + i];
        dw_core_h16(x0, kv, h, wcol, a);
        dw_core_h16(x0 + HWN, kv + 9, h, wcol, a);
        __half* dst = g_q + ((size_t)b * C2 + o) * HWN + p;
        st_half8(dst, a);
        st_half8(dst + 8, a + 8);
        int br = o / CC, rem = o % CC;
        want = true; nm = b * 8 + br * 4 + rem / CHD; slot = rem % CHD;
    } else {
        const __half* X; const float* Wt; __half* Y; int c, br;
        if (cc < 2 * C2) { X = g_kv1pre; Wt = Wt1; Y = g_kv1; c = cc - C2;     br = 0; }
        else             { X = g_kv2pre; Wt = Wt2; Y = g_kv2; c = cc - 2 * C2; br = 1; }
        const __half* xp = X + ((size_t)b * C2 + c) * HWN;
        float kv[9];
        #pragma unroll
        for (int i = 0; i < 9; i++) kv[i] = Wt[(size_t)c * 9 + i];
        dw_core_h16(xp, kv, h, wcol, a);
        __half* dst = Y + ((size_t)b * C2 + c) * HWN + p;
        st_half8(dst, a);
        st_half8(dst + 8, a + 8);
        if (c < CC) { want = true; nm = b * 8 + br * 4 + c / CHD; slot = CHD + c % CHD; }
    }
    if (want) {
        float ss = 0.f;
        #pragma unroll
        for (int i = 0; i < 16; i++) ss += a[i] * a[i];
        #pragma unroll
        for (int st = 16; st > 0; st >>= 1)
            ss += __shfl_xor_sync(0xffffffffu, ss, st);
        if (lane == 0) red[wid] = ss;
        __syncthreads();
        if (t == 0) {
            float tot = 0.f;
            #pragma unroll
            for (int i = 0; i < 8; i++) tot += red[i];
            atomicAdd(&g_nrm[nm * 96 + slot], tot);
        }
    }
}

// ---------------- fused FFN dwconv + gated gelu -> fp16, 16 px/thread -------
__global__ __launch_bounds__(256)
void dwgelu(const float* __restrict__ Wt, __half* __restrict__ Hx) {
    int b = blockIdx.z, c = blockIdx.y;
    int p = (blockIdx.x * 256 + threadIdx.x) * 16;
    size_t oidx = ((size_t)b * GGPAD + c) * HWN + p;
    if (c >= HIDC) {
        uint4 z = make_uint4(0, 0, 0, 0);
        *(uint4*)(Hx + oidx) = z;
        *(uint4*)(Hx + oidx + 8) = z;
        return;
    }
    int h = p >> 7, wcol = p & 127;
    float va[16], vg[16];
    #pragma unroll
    for (int i = 0; i < 16; i++) { va[i] = 0.f; vg[i] = 0.f; }
    {
        const __half* xp = g_h + ((size_t)b * HID2 + c) * HWN;
        float kv[9];
        #pragma unroll
        for (int i = 0; i < 9; i++) kv[i] = Wt[(size_t)c * 9 + i];
        dw_core_h16(xp, kv, h, wcol, va);
    }
    {
        int ch = c + HIDC;
        const __half* xp = g_h + ((size_t)b * HID2 + ch) * HWN;
        float kv[9];
        #pragma unroll
        for (int i = 0; i < 9; i++) kv[i] = Wt[(size_t)ch * 9 + i];
        dw_core_h16(xp, kv, h, wcol, vg);
    }
    float o[16];
    #pragma unroll
    for (int j = 0; j < 16; j++) {
        float aa = va[j];
        float ge = 0.5f * aa * (1.f + erff(aa * 0.70710678118654752f));
        o[j] = ge * vg[j];
    }
    st_half8(Hx + oidx, o);
    st_half8(Hx + oidx + 8, o + 8);
}

// ---------------- attention ----------------
#define QKS 136
#define QKBUF (2 * CHD * QKS * 2)
#define SK_SMEM (2 * QKBUF + CHD * 49 * 4)
__global__ __launch_bounds__(256)
void skernel() {
    extern __shared__ char sks[];
    float* Ssm = (float*)(sks + 2 * QKBUF);
    int m = blockIdx.x, ns = blockIdx.y;
    int b = m >> 3, br = (m >> 2) & 1, hh = m & 3;
    const __half* qb = g_q + ((size_t)b * C2 + br * CC + hh * CHD) * HWN;
    const __half* kb = (br ? g_kv2 : g_kv1) + ((size_t)b * C2 + hh * CHD) * HWN;
    int t = threadIdx.x, lane = t & 31, wid = t >> 5;
    for (int i = t; i < CHD * 49; i += 256) Ssm[i] = 0.f;
    unsigned sb = smem_u32(sks);

    float acc[3][6][4];
    #pragma unroll
    for (int i = 0; i < 3; i++)
        #pragma unroll
        for (int j = 0; j < 6; j++)
            #pragma unroll
            for (int k = 0; k < 4; k++) acc[i][j][k] = 0.f;

    int rsel = lane & 15, csel = (lane >> 4) * 8;
    int bnr = (lane & 7) + ((lane >> 4) & 1) * 8;
    int bkc = ((lane >> 3) & 1) * 8;
    int kc = wid * 16;
    int nbeg = ns * 2048;

    auto load = [&](int ch) {
        int n0 = nbeg + ch * 128;
        unsigned bb = sb + (ch & 1) * QKBUF;
        #pragma unroll
        for (int j = 0; j < 6; j++) {
            int ci = j * 256 + t;
            int mtx = (ci >= 768);
            int loc = ci - mtx * 768;
            int row = loc >> 4, g = loc & 15;
            const __half* src = (mtx ? kb : qb) + (size_t)row * HWN + n0 + g * 8;
            unsigned dst = bb + (unsigned)(mtx * (CHD * QKS) + row * QKS + g * 8) * 2;
            CP_ASYNC16(dst, src);
        }
        CP_COMMIT();
    };

    load(0);
    for (int ch = 0; ch < 16; ch++) {
        CP_WAIT(0);
        __syncthreads();
        if (ch + 1 < 16) load(ch + 1);
        unsigned qsb = sb + (ch & 1) * QKBUF;
        unsigned ksb = qsb + CHD * QKS * 2;
        unsigned af[3][4], bf[3][4];
        #pragma unroll
        for (int mt = 0; mt < 3; mt++) {
            unsigned off = (unsigned)((mt * 16 + rsel) * QKS + kc + csel) * 2;
            ldm_x4(af[mt][0], af[mt][1], af[mt][2], af[mt][3], qsb + off);
        }
        #pragma unroll
        for (int nf = 0; nf < 3; nf++) {
            unsigned off = (unsigned)((nf * 16 + bnr) * QKS + kc + bkc) * 2;
            ldm_x4(bf[nf][0], bf[nf][1], bf[nf][2], bf[nf][3], ksb + off);
        }
        #pragma unroll
        for (int mt = 0; mt < 3; mt++)
            #pragma unroll
            for (int nf = 0; nf < 3; nf++)
                #pragma unroll
                for (int hf = 0; hf < 2; hf++)
                    mma_f16(acc[mt][nf * 2 + hf], af[mt], bf[nf][2 * hf], bf[nf][2 * hf + 1]);
    }
    __syncthreads();
    #pragma unroll
    for (int mt = 0; mt < 3; mt++)
        #pragma unroll
        for (int nt = 0; nt < 6; nt++) {
            int r0 = mt * 16 + (lane >> 2);
            int cl = nt * 8 + (lane & 3) * 2;
            atomicAdd(&Ssm[r0 * 49 + cl],           acc[mt][nt][0]);
            atomicAdd(&Ssm[r0 * 49 + cl + 1],       acc[mt][nt][1]);
            atomicAdd(&Ssm[(r0 + 8) * 49 + cl],     acc[mt][nt][2]);
            atomicAdd(&Ssm[(r0 + 8) * 49 + cl + 1], acc[mt][nt][3]);
        }
    __syncthreads();
    for (int i = t; i < CHD * CHD; i += 256) {
        int r = i / CHD, c = i % CHD;
        atomicAdd(&g_S[(size_t)m * CHD * CHD + i], Ssm[r * 49 + c]);
    }
}

__global__ void softmax_kernel(const float* __restrict__ t1, const float* __restrict__ t2) {
    int m = blockIdx.x;
    int c = threadIdx.x;
    __shared__ float nk[CHD];
    if (c < CHD) nk[c] = fmaxf(sqrtf(g_nrm[m * 96 + CHD + c]), 1e-12f);
    __syncthreads();
    if (c >= CHD) return;
    int br = (m >> 2) & 1, hh = m & 3;
    float tmp = (br ? t2 : t1)[hh];
    float nq = fmaxf(sqrtf(g_nrm[m * 96 + c]), 1e-12f);
    float* row = g_S + (size_t)m * CHD * CHD + c * CHD;
    float vals[CHD];
    float mx = -1e30f;
    #pragma unroll
    for (int d = 0; d < CHD; d++) {
        float v = row[d] / (nq * nk[d]) * tmp;
        vals[d] = v;
        mx = fmaxf(mx, v);
    }
    float sum = 0.f;
    #pragma unroll
    for (int d = 0; d < CHD; d++) { vals[d] = __expf(vals[d] - mx); sum += vals[d]; }
    float inv = 1.f / sum;
    #pragma unroll
    for (int d = 0; d < CHD; d++) row[d] = vals[d] * inv;
}

#define AVS 56
#define VVS 264
__global__ __launch_bounds__(256)
void av_mma() {
    __shared__ __half As[CHD * AVS];
    __shared__ __half Vs[CHD * VVS];
    int m = blockIdx.x;
    int b = m >> 3, br = (m >> 2) & 1, hh = m & 3;
    int t = threadIdx.x, lane = t & 31, wid = t >> 5;
    for (int i = t; i < CHD * CHD; i += 256) {
        int r = i / CHD, c = i % CHD;
        As[r * AVS + c] = __float2half_rn(g_S[(size_t)m * CHD * CHD + i]);
    }
    const __half* vb = (br ? g_kv2 : g_kv1) + ((size_t)b * C2 + CC + hh * CHD) * HWN;
    int p0 = blockIdx.y * 256;
    unsigned asb = smem_u32(As), vsb = smem_u32(Vs);
    #pragma unroll
    for (int j = 0; j < 6; j++) {
        int ci = j * 256 + t;
        int row = ci >> 5, g = ci & 31;
        CP_ASYNC16(vsb + (unsigned)(row * VVS + g * 8) * 2,
                   vb + (size_t)row * HWN + p0 + g * 8);
    }
    CP_COMMIT(); CP_WAIT(0);
    __syncthreads();

    int rsel = lane & 15, csel = (lane >> 4) * 8;
    int bkr = (lane & 7) + ((lane >> 4) & 1) * 8;
    int bpc = ((lane >> 3) & 1) * 8;
    int warpN = wid * 32;

    float acc[3][4][4];
    #pragma unroll
    for (int i = 0; i < 3; i++)
        #pragma unroll
        for (int j = 0; j < 4; j++)
            #pragma unroll
            for (int k = 0; k < 4; k++) acc[i][j][k] = 0.f;

    #pragma unroll
    for (int kt = 0; kt < 3; kt++) {
        unsigned af[3][4], bf[2][4];
        #pragma unroll
        for (int mt = 0; mt < 3; mt++) {
            unsigned off = (unsigned)((mt * 16 + rsel) * AVS + kt * 16 + csel) * 2;
            ldm_x4(af[mt][0], af[mt][1], af[mt][2], af[mt][3], asb + off);
        }
        #pragma unroll
        for (int np = 0; np < 2; np++) {
            unsigned off = (unsigned)((kt * 16 + bkr) * VVS + warpN + np * 16 + bpc) * 2;
            ldm_x4_t(bf[np][0], bf[np][1], bf[np][2], bf[np][3], vsb + off);
        }
        #pragma unroll
        for (int mt = 0; mt < 3; mt++)
            #pragma unroll
            for (int nt = 0; nt < 4; nt++) {
                int np = nt >> 1, hf = nt & 1;
                mma_f16(acc[mt][nt], af[mt], bf[np][hf], bf[np][hf + 2]);
            }
    }
    int off = br * CC + hh * CHD;
    #pragma unroll
    for (int mt = 0; mt < 3; mt++)
        #pragma unroll
        for (int nt = 0; nt < 4; nt++) {
            int r0 = off + mt * 16 + (lane >> 2);
            int pc = p0 + warpN + nt * 8 + (lane & 3) * 2;
            __half2 h0 = __floats2half2_rn(acc[mt][nt][0], acc[mt][nt][1]);
            __half2 h1 = __floats2half2_rn(acc[mt][nt][2], acc[mt][nt][3]);
            *(__half2*)(xt_ao + ((size_t)b * C2 + r0) * HWN + pc) = h0;
            *(__half2*)(xt_ao + ((size_t)b * C2 + r0 + 8) * HWN + pc) = h1;
        }
}

// ---------------- launch ----------------
extern "C" void kernel_launch(void* const* d_in, const int* in_sizes, int n_in,
                              void* d_out, int out_size) {
    const float* x       = (const float*)d_in[0];
    const float* kv1in   = (const float*)d_in[1];
    const float* kv2in   = (const float*)d_in[2];
    const float* n1w = (const float*)d_in[3];  const float* n1b = (const float*)d_in[4];
    const float* nk1w = (const float*)d_in[5]; const float* nk1b = (const float*)d_in[6];
    const float* nk2w = (const float*)d_in[7]; const float* nk2b = (const float*)d_in[8];
    const float* n2w = (const float*)d_in[9];  const float* n2b = (const float*)d_in[10];
    const float* q_w   = (const float*)d_in[11];
    const float* kv1_w = (const float*)d_in[12];
    const float* kv2_w = (const float*)d_in[13];
    const float* q_dw  = (const float*)d_in[14];
    const float* kv1_dw= (const float*)d_in[15];
    const float* kv2_dw= (const float*)d_in[16];
    const float* proj_w= (const float*)d_in[17];
    const float* temp1 = (const float*)d_in[18];
    const float* temp2 = (const float*)d_in[19];
    const float* pin_w = (const float*)d_in[20];
    const float* dw_w  = (const float*)d_in[21];
    const float* pout_w= (const float*)d_in[22];
    float* out = (float*)d_out;

    cudaFuncSetAttribute((const void*)gemm_mma<1, true>,  cudaFuncAttributeMaxDynamicSharedMemorySize, GEMM_SMEM_H);
    cudaFuncSetAttribute((const void*)gemm_mma<2, false>, cudaFuncAttributeMaxDynamicSharedMemorySize, GEMM_SMEM);
    cudaFuncSetAttribute((const void*)gemm3p,  cudaFuncAttributeMaxDynamicSharedMemorySize, PERS_SMEM);
    cudaFuncSetAttribute((const void*)gemm_pin, cudaFuncAttributeMaxDynamicSharedMemorySize, PERS_SMEM);
    cudaFuncSetAttribute((const void*)skernel, cudaFuncAttributeMaxDynamicSharedMemorySize, SK_SMEM);

    __half *wh, *pa, *pao, *pgg, *px2h;
    cudaGetSymbolAddress((void**)&wh, g_wh);
    cudaGetSymbolAddress((void**)&pa, xt_a);
    cudaGetSymbolAddress((void**)&pao, xt_ao);
    cudaGetSymbolAddress((void**)&pgg, xt_gg);
    cudaGetSymbolAddress((void**)&px2h, g_x2h);

    // 1: weights + zero attn accumulators
    wconv_all<<<WCONV_BLKS + ZERO_BLKS, 64>>>(q_w, kv1_w, kv2_w, proj_w, pin_w, pout_w);
    // 2: merged LNs
    ln3<<<dim3(HWN / 64, BB, 3), 256>>>(x, kv1in, kv2in, n1w, n1b, nk1w, nk1b, nk2w, nk2b);
    // 3: merged q/kv1/kv2 persistent GEMM
    gemm3p<<<dim3(16, 3, 12), 256, PERS_SMEM>>>();
    // 4: merged dwconvs (+ fused attention norms), 16 px/thread
    dim3 dAll(HWN / 4096, 3 * C2, BB);
    dwconv_all<<<dAll, 256>>>(q_dw, kv1_dw, kv2_dw);
    // 5-7: attention on HMMA
    skernel<<<dim3(32, 8), 256, SK_SMEM>>>();
    softmax_kernel<<<32, 64>>>(temp1, temp2);
    av_mma<<<dim3(32, HWN / 256), 256>>>();
    // 8: proj + residual x -> g_x2h (fp16)
    dim3 gP(HWN / 128, 2, BB);
    gemm_mma<1, true><<<gP, 256, GEMM_SMEM_H>>>(wh + OFF_P, pao, x, px2h, 192, 384);
    // 9: FFN LN over fp16 x2
    dim3 lnG(HWN / 64, BB);
    ln_h<<<lnG, 256>>>(px2h, n2w, n2b, pa);
    // 10: pin persistent GEMM -> g_h (fp16)
    gemm_pin<<<dim3(16, 8, 4), 256, PERS_SMEM>>>();
    // 11: fused dwconv+gelu, 16 px/thread
    dim3 dGG(HWN / 4096, GGPAD, BB);
    dwgelu<<<dGG, 256>>>(dw_w, pgg);
    // 12: pout GEMM + fp16 residual -> fp32 out
    gemm_mma<2, false><<<gP, 256, GEMM_SMEM>>>(wh + OFF_PO, pgg, px2h, out, 192, 512);
}